// round 4
// baseline (speedup 1.0000x reference)
#include <cuda_runtime.h>
#include <cuda_bf16.h>
#include <cstdint>
#include <math.h>

#define Bb 64
#define Nn 512
#define Dd 256
#define Ll 4

// ======================= helpers =======================
__device__ __forceinline__ uint32_t smem_u32(const void* p) {
    uint32_t a;
    asm("{ .reg .u64 t; cvta.to.shared.u64 t, %1; cvt.u32.u64 %0, t; }" : "=r"(a) : "l"(p));
    return a;
}
__device__ __forceinline__ void cp16(uint32_t s, const void* g) {
    asm volatile("cp.async.cg.shared.global [%0], [%1], 16;" :: "r"(s), "l"(g));
}
__device__ __forceinline__ void ldsm4(uint32_t* r, uint32_t addr) {
    asm volatile("ldmatrix.sync.aligned.m8n8.x4.shared.b16 {%0,%1,%2,%3}, [%4];"
        : "=r"(r[0]), "=r"(r[1]), "=r"(r[2]), "=r"(r[3]) : "r"(addr));
}
__device__ __forceinline__ void mma16816(float* d, const uint32_t* a, const uint32_t* b) {
    asm volatile("mma.sync.aligned.m16n8k16.row.col.f32.bf16.bf16.f32 "
        "{%0,%1,%2,%3}, {%4,%5,%6,%7}, {%8,%9}, {%0,%1,%2,%3};"
        : "+f"(d[0]), "+f"(d[1]), "+f"(d[2]), "+f"(d[3])
        : "r"(a[0]), "r"(a[1]), "r"(a[2]), "r"(a[3]), "r"(b[0]), "r"(b[1]));
}

// ======================= device globals (scratch) =======================
#define XSZ (Bb * Nn * Dd)
#define ASZ (Bb * Nn * Nn)
__device__ __align__(128) __nv_bfloat16 g_xh[XSZ], g_xl[XSZ];
__device__ __align__(128) __nv_bfloat16 g_th[XSZ], g_tl[XSZ];   // xT, then lin0 output
__device__ __align__(128) __nv_bfloat16 g_qh[XSZ], g_ql[XSZ];   // q, then t1
__device__ __align__(128) __nv_bfloat16 g_ah[ASZ], g_al[ASZ];   // attn hi/lo
__device__ __align__(128) __nv_bfloat16 g_wh[13 * Dd * Dd], g_wl[13 * Dd * Dd];
__device__ __align__(128) float g_x[XSZ];

// ======================= MMA GEMM (NT, K-major both operands) =======================
// C[M, Ncols] = (Ah+Al)[M,K] @ ((Bh+Bl)[Ncols,K])^T ; fp32 accum via 3 HMMA products.
// EPI: 1=bias->hl | 2=sigmoid*adj fp32 | 3=plain->hl | 4=relu(bias)->hl
//      5=relu(bias)+res -> fp32+hl | 6=bias->fp32
#define TM 128
#define TN 128
#define BKK 64                          // k per stage (bf16 elems) = 128B row
#define RS 144                          // padded smem row stride (bytes)
#define MAT_BYTES (128 * RS)            // 18432
#define STAGE_BYTES (4 * MAT_BYTES)     // Ah, Al, Bh, Bl = 73728
#define GEMM_SMEM (2 * STAGE_BYTES)     // 147456

template<int EPI>
__global__ void __launch_bounds__(256, 1)
mma_gemm(const __nv_bfloat16* __restrict__ Ah, const __nv_bfloat16* __restrict__ Al,
         const __nv_bfloat16* __restrict__ Bh, const __nv_bfloat16* __restrict__ Bl,
         int K, long long sAz, long long sBz,
         float* __restrict__ Cf, __nv_bfloat16* __restrict__ Ch, __nv_bfloat16* __restrict__ Cl,
         long long sCz, int ldc,
         const float* __restrict__ bias, const float* __restrict__ res,
         const float* __restrict__ adj)
{
    extern __shared__ char smch[];
    const uint32_t sb = smem_u32(smch);
    const int tid = threadIdx.x;
    const int wid = tid >> 5;
    const int lane = tid & 31;
    const int z = blockIdx.z;
    const int bm = blockIdx.x * TM;
    const int bn = blockIdx.y * TN;

    Ah += (size_t)z * sAz + (size_t)bm * K;
    Al += (size_t)z * sAz + (size_t)bm * K;
    Bh += (size_t)z * sBz + (size_t)bn * K;
    Bl += (size_t)z * sBz + (size_t)bn * K;

    // loader geometry: each thread owns a 64B half of one row per matrix
    const int lr = tid >> 1;            // row 0..127
    const int lh = tid & 1;             // which 64B half
    const uint32_t s_off = (uint32_t)lr * RS + (uint32_t)lh * 64;

    auto issue = [&](int kb, int buf) {
        const size_t go = (size_t)lr * K + (size_t)kb * BKK + (size_t)lh * 32;
        const uint32_t s0 = sb + buf * STAGE_BYTES + s_off;
        #pragma unroll
        for (int i = 0; i < 4; i++) {
            cp16(s0 + i * 16,                 Ah + go + i * 8);
            cp16(s0 + MAT_BYTES + i * 16,     Al + go + i * 8);
            cp16(s0 + 2 * MAT_BYTES + i * 16, Bh + go + i * 8);
            cp16(s0 + 3 * MAT_BYTES + i * 16, Bl + go + i * 8);
        }
    };

    const int KB = K / BKK;
    issue(0, 0);
    asm volatile("cp.async.commit_group;" ::: "memory");
    issue(1, 1);
    asm volatile("cp.async.commit_group;" ::: "memory");

    const int wm = (wid & 1) * 64;      // warp row offset in tile
    const int wn = (wid >> 1) * 32;     // warp col offset in tile

    float acc[4][4][4];
    #pragma unroll
    for (int i = 0; i < 4; i++)
        #pragma unroll
        for (int j = 0; j < 4; j++)
            #pragma unroll
            for (int k = 0; k < 4; k++) acc[i][j][k] = 0.0f;

    const int rr = lane & 15;
    const int csel = lane >> 4;         // 0/1 -> second 16B chunk of the k16

    for (int kb = 0; kb < KB; kb++) {
        asm volatile("cp.async.wait_group 1;" ::: "memory");
        __syncthreads();
        const uint32_t bufb = sb + (kb & 1) * STAGE_BYTES;
        const uint32_t abase0 = bufb + (uint32_t)(wm + rr) * RS + (uint32_t)csel * 16;
        const uint32_t bbase0 = bufb + 2 * MAT_BYTES + (uint32_t)(wn + rr) * RS + (uint32_t)csel * 16;

        #pragma unroll
        for (int ks = 0; ks < 4; ks++) {
            const uint32_t coff = (uint32_t)ks * 32;
            uint32_t ah[4][4], al[4][4], bh[4][2], bl[4][2];
            #pragma unroll
            for (int mt = 0; mt < 4; mt++) {
                ldsm4(ah[mt], abase0 + coff + mt * (16 * RS));
                ldsm4(al[mt], abase0 + coff + mt * (16 * RS) + MAT_BYTES);
            }
            #pragma unroll
            for (int ntt = 0; ntt < 2; ntt++) {
                uint32_t t4[4];
                ldsm4(t4, bbase0 + coff + ntt * (16 * RS));
                bh[2 * ntt][0] = t4[0]; bh[2 * ntt][1] = t4[2];
                bh[2 * ntt + 1][0] = t4[1]; bh[2 * ntt + 1][1] = t4[3];
                ldsm4(t4, bbase0 + coff + ntt * (16 * RS) + MAT_BYTES);
                bl[2 * ntt][0] = t4[0]; bl[2 * ntt][1] = t4[2];
                bl[2 * ntt + 1][0] = t4[1]; bl[2 * ntt + 1][1] = t4[3];
            }
            #pragma unroll
            for (int mt = 0; mt < 4; mt++)
                #pragma unroll
                for (int nt = 0; nt < 4; nt++) {
                    mma16816(acc[mt][nt], ah[mt], bh[nt]);
                    mma16816(acc[mt][nt], ah[mt], bl[nt]);
                    mma16816(acc[mt][nt], al[mt], bh[nt]);
                }
        }
        __syncthreads();
        if (kb + 2 < KB) issue(kb + 2, kb & 1);
        asm volatile("cp.async.commit_group;" ::: "memory");
    }

    // ======================= epilogue =======================
    const int qrow = lane >> 2;         // 0..7
    const int qcol = (lane & 3) * 2;    // 0,2,4,6

    #pragma unroll
    for (int mt = 0; mt < 4; mt++) {
        const int r0 = bm + wm + mt * 16 + qrow;
        const int r1 = r0 + 8;
        #pragma unroll
        for (int nt = 0; nt < 4; nt++) {
            const int col = bn + wn + nt * 8 + qcol;
            float v00 = acc[mt][nt][0], v01 = acc[mt][nt][1];
            float v10 = acc[mt][nt][2], v11 = acc[mt][nt][3];

            if (EPI == 2) {
                float* cf0 = Cf + (size_t)z * sCz + (size_t)r0 * ldc;
                float* cf1 = Cf + (size_t)z * sCz + (size_t)r1 * ldc;
                const float* a0 = adj + ((size_t)z * Nn + r0) * Nn;
                const float* a1 = adj + ((size_t)z * Nn + r1) * Nn;
                float s00 = 1.0f / (1.0f + __expf(-v00));
                float s01 = 1.0f / (1.0f + __expf(-v01));
                float s10 = 1.0f / (1.0f + __expf(-v10));
                float s11 = 1.0f / (1.0f + __expf(-v11));
                cf0[col]     = (col == r0)     ? (s00 + 1e-5f) : s00 * __ldg(a0 + col);
                cf0[col + 1] = (col + 1 == r0) ? (s01 + 1e-5f) : s01 * __ldg(a0 + col + 1);
                cf1[col]     = (col == r1)     ? (s10 + 1e-5f) : s10 * __ldg(a1 + col);
                cf1[col + 1] = (col + 1 == r1) ? (s11 + 1e-5f) : s11 * __ldg(a1 + col + 1);
            } else if (EPI == 6) {
                const float b0v = __ldg(bias + col), b1v = __ldg(bias + col + 1);
                float* cf0 = Cf + (size_t)z * sCz + (size_t)r0 * ldc;
                float* cf1 = Cf + (size_t)z * sCz + (size_t)r1 * ldc;
                float2 p0; p0.x = v00 + b0v; p0.y = v01 + b1v;
                float2 p1; p1.x = v10 + b0v; p1.y = v11 + b1v;
                *(float2*)(cf0 + col) = p0;
                *(float2*)(cf1 + col) = p1;
            } else {
                if (EPI == 1) {
                    const float b0v = __ldg(bias + col), b1v = __ldg(bias + col + 1);
                    v00 += b0v; v01 += b1v; v10 += b0v; v11 += b1v;
                }
                if (EPI == 4 || EPI == 5) {
                    const float b0v = __ldg(bias + col), b1v = __ldg(bias + col + 1);
                    v00 = fmaxf(v00 + b0v, 0.0f); v01 = fmaxf(v01 + b1v, 0.0f);
                    v10 = fmaxf(v10 + b0v, 0.0f); v11 = fmaxf(v11 + b1v, 0.0f);
                }
                if (EPI == 5) {
                    const float* rp0 = res + (size_t)r0 * ldc;
                    const float* rp1 = res + (size_t)r1 * ldc;
                    v00 += rp0[col]; v01 += rp0[col + 1];
                    v10 += rp1[col]; v11 += rp1[col + 1];
                    float* cf0 = Cf + (size_t)r0 * ldc;
                    float* cf1 = Cf + (size_t)r1 * ldc;
                    float2 p0; p0.x = v00; p0.y = v01;
                    float2 p1; p1.x = v10; p1.y = v11;
                    *(float2*)(cf0 + col) = p0;
                    *(float2*)(cf1 + col) = p1;
                }
                __nv_bfloat16* ch0 = Ch + (size_t)z * sCz + (size_t)r0 * ldc;
                __nv_bfloat16* ch1 = Ch + (size_t)z * sCz + (size_t)r1 * ldc;
                __nv_bfloat16* cl0 = Cl + (size_t)z * sCz + (size_t)r0 * ldc;
                __nv_bfloat16* cl1 = Cl + (size_t)z * sCz + (size_t)r1 * ldc;
                __nv_bfloat16 h00 = __float2bfloat16_rn(v00), h01 = __float2bfloat16_rn(v01);
                __nv_bfloat16 h10 = __float2bfloat16_rn(v10), h11 = __float2bfloat16_rn(v11);
                __nv_bfloat162 hp0; hp0.x = h00; hp0.y = h01;
                __nv_bfloat162 hp1; hp1.x = h10; hp1.y = h11;
                *(__nv_bfloat162*)(ch0 + col) = hp0;
                *(__nv_bfloat162*)(ch1 + col) = hp1;
                __nv_bfloat162 lp0, lp1;
                lp0.x = __float2bfloat16_rn(v00 - __bfloat162float(h00));
                lp0.y = __float2bfloat16_rn(v01 - __bfloat162float(h01));
                lp1.x = __float2bfloat16_rn(v10 - __bfloat162float(h10));
                lp1.y = __float2bfloat16_rn(v11 - __bfloat162float(h11));
                *(__nv_bfloat162*)(cl0 + col) = lp0;
                *(__nv_bfloat162*)(cl1 + col) = lp1;
            }
        }
    }
}

// ======================= small kernels =======================
__global__ void __launch_bounds__(256)
split_copy(const float4* __restrict__ src, float4* __restrict__ dst,
           __nv_bfloat16* __restrict__ h, __nv_bfloat16* __restrict__ l, int n4)
{
    const int i = blockIdx.x * blockDim.x + threadIdx.x;
    if (i >= n4) return;
    const float4 v = src[i];
    dst[i] = v;
    const float vv[4] = {v.x, v.y, v.z, v.w};
    __nv_bfloat16 hh[4], ll[4];
    #pragma unroll
    for (int k = 0; k < 4; k++) {
        hh[k] = __float2bfloat16_rn(vv[k]);
        ll[k] = __float2bfloat16_rn(vv[k] - __bfloat162float(hh[k]));
    }
    __nv_bfloat162 a, b;
    a.x = hh[0]; a.y = hh[1]; b.x = hh[2]; b.y = hh[3];
    *(__nv_bfloat162*)(h + 4 * (size_t)i) = a;
    *(__nv_bfloat162*)(h + 4 * (size_t)i + 2) = b;
    a.x = ll[0]; a.y = ll[1]; b.x = ll[2]; b.y = ll[3];
    *(__nv_bfloat162*)(l + 4 * (size_t)i) = a;
    *(__nv_bfloat162*)(l + 4 * (size_t)i + 2) = b;
}

__global__ void __launch_bounds__(256)
wsplit(const float* __restrict__ src, __nv_bfloat16* __restrict__ h,
       __nv_bfloat16* __restrict__ l, int n)
{
    const int i = blockIdx.x * blockDim.x + threadIdx.x;
    if (i >= n) return;
    const float v = src[i];
    const __nv_bfloat16 hv = __float2bfloat16_rn(v);
    h[i] = hv;
    l[i] = __float2bfloat16_rn(v - __bfloat162float(hv));
}

// x [B,N,D] fp32 -> xT hi/lo [B,D,N] bf16
__global__ void __launch_bounds__(256)
transpose_split(const float* __restrict__ src,
                __nv_bfloat16* __restrict__ th, __nv_bfloat16* __restrict__ tl)
{
    __shared__ float ts[32][33];
    const int z = blockIdx.z;
    const int d0 = blockIdx.x * 32, n0 = blockIdx.y * 32;
    const int tx = threadIdx.x & 31, ty = threadIdx.x >> 5;   // ty 0..7
    const float* s = src + ((size_t)z * Nn + n0) * Dd + d0;
    #pragma unroll
    for (int r = 0; r < 4; r++)
        ts[ty + r * 8][tx] = s[(size_t)(ty + r * 8) * Dd + tx];
    __syncthreads();
    __nv_bfloat16* ph = th + ((size_t)z * Dd + d0) * Nn + n0;
    __nv_bfloat16* pl = tl + ((size_t)z * Dd + d0) * Nn + n0;
    #pragma unroll
    for (int r = 0; r < 4; r++) {
        const float v = ts[tx][ty + r * 8];
        const __nv_bfloat16 h = __float2bfloat16_rn(v);
        ph[(size_t)(ty + r * 8) * Nn + tx] = h;
        pl[(size_t)(ty + r * 8) * Nn + tx] = __float2bfloat16_rn(v - __bfloat162float(h));
    }
}

// normalize one attn row (512) in place; also emit bf16 hi/lo
__global__ void __launch_bounds__(256)
rownorm_split(float* __restrict__ a, __nv_bfloat16* __restrict__ h,
              __nv_bfloat16* __restrict__ l)
{
    const size_t row = blockIdx.x;
    float* p = a + row * Nn;
    const int t = threadIdx.x;
    const float v0 = p[t];
    const float v1 = p[t + 256];
    float s = v0 + v1;
    #pragma unroll
    for (int o = 16; o; o >>= 1) s += __shfl_xor_sync(0xffffffffu, s, o);
    __shared__ float ws[8];
    if ((t & 31) == 0) ws[t >> 5] = s;
    __syncthreads();
    if (t < 8) {
        float x = ws[t];
        #pragma unroll
        for (int o = 4; o; o >>= 1) x += __shfl_xor_sync(0xffu, x, o);
        if (t == 0) ws[0] = x;
    }
    __syncthreads();
    const float inv = 1.0f / ws[0];
    const float n0 = v0 * inv, n1 = v1 * inv;
    p[t] = n0;
    p[t + 256] = n1;
    const __nv_bfloat16 h0 = __float2bfloat16_rn(n0);
    const __nv_bfloat16 h1 = __float2bfloat16_rn(n1);
    h[row * Nn + t] = h0;
    h[row * Nn + t + 256] = h1;
    l[row * Nn + t] = __float2bfloat16_rn(n0 - __bfloat162float(h0));
    l[row * Nn + t + 256] = __float2bfloat16_rn(n1 - __bfloat162float(h1));
}

// ======================= launch =======================
extern "C" void kernel_launch(void* const* d_in, const int* in_sizes, int n_in,
                              void* d_out, int out_size)
{
    const float* x_in  = (const float*)d_in[0];
    const float* adj   = (const float*)d_in[1];
    const float* wA_w  = (const float*)d_in[2];
    const float* wA_b  = (const float*)d_in[3];
    const float* l0_w  = (const float*)d_in[4];
    const float* l0_b  = (const float*)d_in[5];
    const float* l1_w  = (const float*)d_in[6];
    const float* l1_b  = (const float*)d_in[7];
    const float* fin_w = (const float*)d_in[8];
    const float* fin_b = (const float*)d_in[9];

    float* out_x = (float*)d_out;
    float* attls = out_x + (size_t)Bb * Nn * Dd;

    __nv_bfloat16 *xh, *xl, *th, *tl, *qh, *ql, *ah, *al, *wh, *wl;
    float* gx;
    cudaGetSymbolAddress((void**)&xh, g_xh); cudaGetSymbolAddress((void**)&xl, g_xl);
    cudaGetSymbolAddress((void**)&th, g_th); cudaGetSymbolAddress((void**)&tl, g_tl);
    cudaGetSymbolAddress((void**)&qh, g_qh); cudaGetSymbolAddress((void**)&ql, g_ql);
    cudaGetSymbolAddress((void**)&ah, g_ah); cudaGetSymbolAddress((void**)&al, g_al);
    cudaGetSymbolAddress((void**)&wh, g_wh); cudaGetSymbolAddress((void**)&wl, g_wl);
    cudaGetSymbolAddress((void**)&gx, g_x);

    cudaFuncSetAttribute(mma_gemm<1>, cudaFuncAttributeMaxDynamicSharedMemorySize, GEMM_SMEM);
    cudaFuncSetAttribute(mma_gemm<2>, cudaFuncAttributeMaxDynamicSharedMemorySize, GEMM_SMEM);
    cudaFuncSetAttribute(mma_gemm<3>, cudaFuncAttributeMaxDynamicSharedMemorySize, GEMM_SMEM);
    cudaFuncSetAttribute(mma_gemm<4>, cudaFuncAttributeMaxDynamicSharedMemorySize, GEMM_SMEM);
    cudaFuncSetAttribute(mma_gemm<5>, cudaFuncAttributeMaxDynamicSharedMemorySize, GEMM_SMEM);
    cudaFuncSetAttribute(mma_gemm<6>, cudaFuncAttributeMaxDynamicSharedMemorySize, GEMM_SMEM);

    const int WSZ = Dd * Dd;                 // 65536
    const long long sX = (long long)Nn * Dd; // per batch
    const long long sA = (long long)Nn * Nn; // per batch

    // split weights: [0..3]=wA, [4..7]=lin0, [8..11]=lin1, [12]=final
    wsplit<<<(4 * WSZ + 255) / 256, 256>>>(wA_w,  wh,            wl,            4 * WSZ);
    wsplit<<<(4 * WSZ + 255) / 256, 256>>>(l0_w,  wh + 4 * WSZ,  wl + 4 * WSZ,  4 * WSZ);
    wsplit<<<(4 * WSZ + 255) / 256, 256>>>(l1_w,  wh + 8 * WSZ,  wl + 8 * WSZ,  4 * WSZ);
    wsplit<<<(WSZ + 255) / 256, 256>>>(fin_w, wh + 12 * WSZ, wl + 12 * WSZ, WSZ);

    // x -> g_x (fp32) + xh/xl (bf16 split)
    {
        const int n4 = XSZ / 4;
        split_copy<<<(n4 + 255) / 256, 256>>>((const float4*)x_in, (float4*)gx, xh, xl, n4);
    }

    const int BIGM = Bb * Nn; // 32768
    for (int l = 0; l < Ll; l++) {
        const float* ba = wA_b + (size_t)l * Dd;
        const float* b0 = l0_b + (size_t)l * Dd;
        const float* b1 = l1_b + (size_t)l * Dd;
        const __nv_bfloat16* Wah = wh + (size_t)l * WSZ;
        const __nv_bfloat16* Wal = wl + (size_t)l * WSZ;
        const __nv_bfloat16* W0h = wh + (size_t)(4 + l) * WSZ;
        const __nv_bfloat16* W0l = wl + (size_t)(4 + l) * WSZ;
        const __nv_bfloat16* W1h = wh + (size_t)(8 + l) * WSZ;
        const __nv_bfloat16* W1l = wl + (size_t)(8 + l) * WSZ;
        float* attl = attls + (size_t)l * Bb * Nn * Nn;

        // xT hi/lo from g_x
        transpose_split<<<dim3(Dd / 32, Nn / 32, Bb), 256>>>(gx, th, tl);

        // q = x @ Wa^T + ba  ->  qh/ql
        mma_gemm<1><<<dim3(BIGM / TM, Dd / TN, 1), 256, GEMM_SMEM>>>(
            xh, xl, Wah, Wal, Dd, 0, 0,
            nullptr, qh, ql, 0, Dd, ba, nullptr, nullptr);

        // attn_unnorm = sig(q @ x^T)*adj (+diag)  -> attl (fp32)
        mma_gemm<2><<<dim3(Nn / TM, Nn / TN, Bb), 256, GEMM_SMEM>>>(
            qh, ql, xh, xl, Dd, sX, sX,
            attl, nullptr, nullptr, sA, Nn, nullptr, nullptr, adj);

        // normalize rows + split to ah/al
        rownorm_split<<<Bb * Nn, 256>>>(attl, ah, al);

        // t1 = attn @ x  (as NT with xT)  -> qh/ql
        mma_gemm<3><<<dim3(Nn / TM, Dd / TN, Bb), 256, GEMM_SMEM>>>(
            ah, al, th, tl, Nn, sA, sX,
            nullptr, qh, ql, sX, Dd, nullptr, nullptr, nullptr);

        // h = relu(t1 @ W0^T + b0) -> th/tl
        mma_gemm<4><<<dim3(BIGM / TM, Dd / TN, 1), 256, GEMM_SMEM>>>(
            qh, ql, W0h, W0l, Dd, 0, 0,
            nullptr, th, tl, 0, Dd, b0, nullptr, nullptr);

        // x = relu(h @ W1^T + b1) + x0 -> g_x (fp32) + xh/xl
        mma_gemm<5><<<dim3(BIGM / TM, Dd / TN, 1), 256, GEMM_SMEM>>>(
            th, tl, W1h, W1l, Dd, 0, 0,
            gx, xh, xl, 0, Dd, b1, gx, nullptr);
    }

    // out = x @ final^T + b
    mma_gemm<6><<<dim3(BIGM / TM, Dd / TN, 1), 256, GEMM_SMEM>>>(
        xh, xl, wh + 12 * WSZ, wl + 12 * WSZ, Dd, 0, 0,
        out_x, nullptr, nullptr, 0, Dd, fin_b, nullptr, nullptr);
}

// round 5
// speedup vs baseline: 1.0163x; 1.0163x over previous
#include <cuda_runtime.h>
#include <cuda_bf16.h>
#include <cstdint>
#include <math.h>

#define Bb 64
#define Nn 512
#define Dd 256
#define Ll 4

// ======================= helpers =======================
__device__ __forceinline__ uint32_t smem_u32(const void* p) {
    uint32_t a;
    asm("{ .reg .u64 t; cvta.to.shared.u64 t, %1; cvt.u32.u64 %0, t; }" : "=r"(a) : "l"(p));
    return a;
}
__device__ __forceinline__ void cp16(uint32_t s, const void* g) {
    asm volatile("cp.async.cg.shared.global [%0], [%1], 16;" :: "r"(s), "l"(g));
}
__device__ __forceinline__ void ldsm4(uint32_t* r, uint32_t addr) {
    asm volatile("ldmatrix.sync.aligned.m8n8.x4.shared.b16 {%0,%1,%2,%3}, [%4];"
        : "=r"(r[0]), "=r"(r[1]), "=r"(r[2]), "=r"(r[3]) : "r"(addr));
}
__device__ __forceinline__ void mma16816(float* d, const uint32_t* a, const uint32_t* b) {
    asm volatile("mma.sync.aligned.m16n8k16.row.col.f32.bf16.bf16.f32 "
        "{%0,%1,%2,%3}, {%4,%5,%6,%7}, {%8,%9}, {%0,%1,%2,%3};"
        : "+f"(d[0]), "+f"(d[1]), "+f"(d[2]), "+f"(d[3])
        : "r"(a[0]), "r"(a[1]), "r"(a[2]), "r"(a[3]), "r"(b[0]), "r"(b[1]));
}

// ======================= device globals (scratch) =======================
#define XSZ (Bb * Nn * Dd)
#define ASZ (Bb * Nn * Nn)
__device__ __align__(128) __nv_bfloat16 g_xh[XSZ], g_xl[XSZ];
__device__ __align__(128) __nv_bfloat16 g_th[XSZ], g_tl[XSZ];   // xT, then lin0 output
__device__ __align__(128) __nv_bfloat16 g_qh[XSZ], g_ql[XSZ];   // q, then t1
__device__ __align__(128) __nv_bfloat16 g_ah[ASZ], g_al[ASZ];   // attn hi/lo (UNNORMALIZED)
__device__ __align__(128) __nv_bfloat16 g_wh[13 * Dd * Dd], g_wl[13 * Dd * Dd];
__device__ __align__(128) float g_x[XSZ];
__device__ __align__(128) float g_part[Bb * Nn * 4];            // row-sum partials (4 ctaY)

// ======================= MMA GEMM (NT, K-major both operands) =======================
// C[M, Ncols] = (Ah+Al)[M,K] @ ((Bh+Bl)[Ncols,K])^T ; fp32 accum via 3 HMMA products.
// EPI: 1=bias->hl | 2=sigmoid*adj->hl + rowsum partials | 4=relu(bias)->hl
//      5=relu(bias)+res->fp32+hl | 6=bias->fp32 | 7=rowscale(1/sum part)->hl
#define TM 128
#define TN 128
#define RS 80                           // padded smem row stride (bytes) for 64B rows
#define MAT_BYTES (128 * RS)            // 10240
#define STAGE_BYTES (4 * MAT_BYTES)     // Ah, Al, Bh, Bl = 40960
#define NSTAGE 3
#define GEMM_SMEM (NSTAGE * STAGE_BYTES) // 122880

template<int EPI>
__global__ void __launch_bounds__(256, 1)
mma_gemm(const __nv_bfloat16* __restrict__ Ah, const __nv_bfloat16* __restrict__ Al,
         const __nv_bfloat16* __restrict__ Bh, const __nv_bfloat16* __restrict__ Bl,
         int K, long long sAz, long long sBz,
         float* __restrict__ Cf, __nv_bfloat16* __restrict__ Ch, __nv_bfloat16* __restrict__ Cl,
         long long sCz, int ldc,
         const float* __restrict__ bias, const float* __restrict__ res,
         const float* __restrict__ adj, float* __restrict__ part)
{
    extern __shared__ char smch[];
    const uint32_t sb = smem_u32(smch);
    const int tid = threadIdx.x;
    const int wid = tid >> 5;
    const int lane = tid & 31;
    const int z = blockIdx.z;
    const int bm = blockIdx.x * TM;
    const int bn = blockIdx.y * TN;

    Ah += (size_t)z * sAz + (size_t)bm * K;
    Al += (size_t)z * sAz + (size_t)bm * K;
    Bh += (size_t)z * sBz + (size_t)bn * K;
    Bl += (size_t)z * sBz + (size_t)bn * K;

    // loader geometry: each thread owns one 32B segment of one row, per matrix
    const int lr = tid >> 1;            // row 0..127
    const int lc = (tid & 1) * 2;       // chunk pair 0 or 2
    const uint32_t s_off = (uint32_t)lr * RS + (uint32_t)lc * 16;

    auto issue = [&](int kb, int buf) {
        const size_t go = (size_t)lr * K + (size_t)kb * 32 + (size_t)lc * 8;
        const uint32_t s0 = sb + buf * STAGE_BYTES + s_off;
        cp16(s0,                      Ah + go);
        cp16(s0 + 16,                 Ah + go + 8);
        cp16(s0 + MAT_BYTES,          Al + go);
        cp16(s0 + MAT_BYTES + 16,     Al + go + 8);
        cp16(s0 + 2 * MAT_BYTES,      Bh + go);
        cp16(s0 + 2 * MAT_BYTES + 16, Bh + go + 8);
        cp16(s0 + 3 * MAT_BYTES,      Bl + go);
        cp16(s0 + 3 * MAT_BYTES + 16, Bl + go + 8);
    };

    const int KB = K / 32;
    issue(0, 0);
    asm volatile("cp.async.commit_group;" ::: "memory");
    issue(1, 1);
    asm volatile("cp.async.commit_group;" ::: "memory");
    issue(2, 2);
    asm volatile("cp.async.commit_group;" ::: "memory");

    const int wm = (wid & 1) * 64;      // warp row offset in tile
    const int wn = (wid >> 1) * 32;     // warp col offset in tile

    float acc[4][4][4];
    #pragma unroll
    for (int i = 0; i < 4; i++)
        #pragma unroll
        for (int j = 0; j < 4; j++)
            #pragma unroll
            for (int k = 0; k < 4; k++) acc[i][j][k] = 0.0f;

    const int rr = lane & 15;
    const int csel = lane >> 4;         // 0/1 -> second 16B chunk of the k16

    int buf = 0;
    for (int kb = 0; kb < KB; kb++) {
        asm volatile("cp.async.wait_group 2;" ::: "memory");
        __syncthreads();
        const uint32_t bufb = sb + buf * STAGE_BYTES;

        #pragma unroll
        for (int ks = 0; ks < 2; ks++) {
            const uint32_t coff = (uint32_t)(ks * 2 + csel) * 16;
            uint32_t ah[4][4], al[4][4], bh[4][2], bl[4][2];
            const uint32_t abase = bufb + (uint32_t)(wm + rr) * RS + coff;
            #pragma unroll
            for (int mt = 0; mt < 4; mt++) {
                ldsm4(ah[mt], abase + mt * (16 * RS));
                ldsm4(al[mt], abase + mt * (16 * RS) + MAT_BYTES);
            }
            const uint32_t bbase = bufb + 2 * MAT_BYTES + (uint32_t)(wn + rr) * RS + coff;
            #pragma unroll
            for (int ntt = 0; ntt < 2; ntt++) {
                uint32_t t4[4];
                ldsm4(t4, bbase + ntt * (16 * RS));
                bh[2 * ntt][0] = t4[0]; bh[2 * ntt][1] = t4[2];
                bh[2 * ntt + 1][0] = t4[1]; bh[2 * ntt + 1][1] = t4[3];
                ldsm4(t4, bbase + ntt * (16 * RS) + MAT_BYTES);
                bl[2 * ntt][0] = t4[0]; bl[2 * ntt][1] = t4[2];
                bl[2 * ntt + 1][0] = t4[1]; bl[2 * ntt + 1][1] = t4[3];
            }
            #pragma unroll
            for (int mt = 0; mt < 4; mt++)
                #pragma unroll
                for (int nt = 0; nt < 4; nt++) {
                    mma16816(acc[mt][nt], ah[mt], bh[nt]);
                    mma16816(acc[mt][nt], ah[mt], bl[nt]);
                    mma16816(acc[mt][nt], al[mt], bh[nt]);
                }
        }
        __syncthreads();
        if (kb + NSTAGE < KB) issue(kb + NSTAGE, buf);
        asm volatile("cp.async.commit_group;" ::: "memory");
        buf = (buf == NSTAGE - 1) ? 0 : buf + 1;
    }

    // ======================= epilogue =======================
    const int qrow = lane >> 2;         // 0..7
    const int qcol = (lane & 3) * 2;    // 0,2,4,6
    float* redsm = (float*)smch;        // [128 rows][4 nwarps] overlay (mainloop done)

    float rsum0[4], rsum1[4];           // per-thread row partial sums (EPI==2)

    #pragma unroll
    for (int mt = 0; mt < 4; mt++) {
        const int r0 = bm + wm + mt * 16 + qrow;
        const int r1 = r0 + 8;
        if (EPI == 2) { rsum0[mt] = 0.0f; rsum1[mt] = 0.0f; }
        #pragma unroll
        for (int nt = 0; nt < 4; nt++) {
            const int col = bn + wn + nt * 8 + qcol;
            float v00 = acc[mt][nt][0], v01 = acc[mt][nt][1];
            float v10 = acc[mt][nt][2], v11 = acc[mt][nt][3];

            if (EPI == 2) {
                const float* a0 = adj + ((size_t)z * Nn + r0) * Nn;
                const float* a1 = adj + ((size_t)z * Nn + r1) * Nn;
                float s00 = 1.0f / (1.0f + __expf(-v00));
                float s01 = 1.0f / (1.0f + __expf(-v01));
                float s10 = 1.0f / (1.0f + __expf(-v10));
                float s11 = 1.0f / (1.0f + __expf(-v11));
                v00 = (col == r0)     ? (s00 + 1e-5f) : s00 * __ldg(a0 + col);
                v01 = (col + 1 == r0) ? (s01 + 1e-5f) : s01 * __ldg(a0 + col + 1);
                v10 = (col == r1)     ? (s10 + 1e-5f) : s10 * __ldg(a1 + col);
                v11 = (col + 1 == r1) ? (s11 + 1e-5f) : s11 * __ldg(a1 + col + 1);
                rsum0[mt] += v00 + v01;
                rsum1[mt] += v10 + v11;
            } else if (EPI == 7) {
                const float4 p0 = *(const float4*)(part + ((size_t)z * Nn + r0) * 4);
                const float4 p1 = *(const float4*)(part + ((size_t)z * Nn + r1) * 4);
                const float inv0 = 1.0f / (p0.x + p0.y + p0.z + p0.w);
                const float inv1 = 1.0f / (p1.x + p1.y + p1.z + p1.w);
                v00 *= inv0; v01 *= inv0; v10 *= inv1; v11 *= inv1;
            } else if (EPI == 1) {
                const float b0v = __ldg(bias + col), b1v = __ldg(bias + col + 1);
                v00 += b0v; v01 += b1v; v10 += b0v; v11 += b1v;
            } else if (EPI == 4 || EPI == 5) {
                const float b0v = __ldg(bias + col), b1v = __ldg(bias + col + 1);
                v00 = fmaxf(v00 + b0v, 0.0f); v01 = fmaxf(v01 + b1v, 0.0f);
                v10 = fmaxf(v10 + b0v, 0.0f); v11 = fmaxf(v11 + b1v, 0.0f);
            }

            if (EPI == 6) {
                const float b0v = __ldg(bias + col), b1v = __ldg(bias + col + 1);
                float* cf0 = Cf + (size_t)z * sCz + (size_t)r0 * ldc;
                float* cf1 = Cf + (size_t)z * sCz + (size_t)r1 * ldc;
                float2 p0; p0.x = v00 + b0v; p0.y = v01 + b1v;
                float2 p1; p1.x = v10 + b0v; p1.y = v11 + b1v;
                *(float2*)(cf0 + col) = p0;
                *(float2*)(cf1 + col) = p1;
            } else {
                if (EPI == 5) {
                    const float* rp0 = res + (size_t)r0 * ldc;
                    const float* rp1 = res + (size_t)r1 * ldc;
                    v00 += rp0[col]; v01 += rp0[col + 1];
                    v10 += rp1[col]; v11 += rp1[col + 1];
                    float* cf0 = Cf + (size_t)r0 * ldc;
                    float* cf1 = Cf + (size_t)r1 * ldc;
                    float2 p0; p0.x = v00; p0.y = v01;
                    float2 p1; p1.x = v10; p1.y = v11;
                    *(float2*)(cf0 + col) = p0;
                    *(float2*)(cf1 + col) = p1;
                }
                __nv_bfloat16* ch0 = Ch + (size_t)z * sCz + (size_t)r0 * ldc;
                __nv_bfloat16* ch1 = Ch + (size_t)z * sCz + (size_t)r1 * ldc;
                __nv_bfloat16* cl0 = Cl + (size_t)z * sCz + (size_t)r0 * ldc;
                __nv_bfloat16* cl1 = Cl + (size_t)z * sCz + (size_t)r1 * ldc;
                __nv_bfloat16 h00 = __float2bfloat16_rn(v00), h01 = __float2bfloat16_rn(v01);
                __nv_bfloat16 h10 = __float2bfloat16_rn(v10), h11 = __float2bfloat16_rn(v11);
                __nv_bfloat162 hp0; hp0.x = h00; hp0.y = h01;
                __nv_bfloat162 hp1; hp1.x = h10; hp1.y = h11;
                *(__nv_bfloat162*)(ch0 + col) = hp0;
                *(__nv_bfloat162*)(ch1 + col) = hp1;
                __nv_bfloat162 lp0, lp1;
                lp0.x = __float2bfloat16_rn(v00 - __bfloat162float(h00));
                lp0.y = __float2bfloat16_rn(v01 - __bfloat162float(h01));
                lp1.x = __float2bfloat16_rn(v10 - __bfloat162float(h10));
                lp1.y = __float2bfloat16_rn(v11 - __bfloat162float(h11));
                *(__nv_bfloat162*)(cl0 + col) = lp0;
                *(__nv_bfloat162*)(cl1 + col) = lp1;
            }
        }
    }

    if (EPI == 2) {
        // reduce row partial sums: across (lane&3), then across the 4 n-warps via smem
        const int nw = wid >> 1;
        #pragma unroll
        for (int mt = 0; mt < 4; mt++) {
            float s0 = rsum0[mt], s1 = rsum1[mt];
            s0 += __shfl_xor_sync(0xffffffffu, s0, 1);
            s0 += __shfl_xor_sync(0xffffffffu, s0, 2);
            s1 += __shfl_xor_sync(0xffffffffu, s1, 1);
            s1 += __shfl_xor_sync(0xffffffffu, s1, 2);
            if ((lane & 3) == 0) {
                const int rc = wm + mt * 16 + qrow;
                redsm[rc * 4 + nw]       = s0;
                redsm[(rc + 8) * 4 + nw] = s1;
            }
        }
        __syncthreads();
        if (tid < 128) {
            const float s = redsm[tid * 4] + redsm[tid * 4 + 1]
                          + redsm[tid * 4 + 2] + redsm[tid * 4 + 3];
            part[((size_t)z * Nn + bm + tid) * 4 + blockIdx.y] = s;
        }
    }
}

// ======================= small kernels =======================
__global__ void __launch_bounds__(256)
split_copy(const float4* __restrict__ src, float4* __restrict__ dst,
           __nv_bfloat16* __restrict__ h, __nv_bfloat16* __restrict__ l, int n4)
{
    const int i = blockIdx.x * blockDim.x + threadIdx.x;
    if (i >= n4) return;
    const float4 v = src[i];
    dst[i] = v;
    const float vv[4] = {v.x, v.y, v.z, v.w};
    __nv_bfloat16 hh[4], ll[4];
    #pragma unroll
    for (int k = 0; k < 4; k++) {
        hh[k] = __float2bfloat16_rn(vv[k]);
        ll[k] = __float2bfloat16_rn(vv[k] - __bfloat162float(hh[k]));
    }
    __nv_bfloat162 a, b;
    a.x = hh[0]; a.y = hh[1]; b.x = hh[2]; b.y = hh[3];
    *(__nv_bfloat162*)(h + 4 * (size_t)i) = a;
    *(__nv_bfloat162*)(h + 4 * (size_t)i + 2) = b;
    a.x = ll[0]; a.y = ll[1]; b.x = ll[2]; b.y = ll[3];
    *(__nv_bfloat162*)(l + 4 * (size_t)i) = a;
    *(__nv_bfloat162*)(l + 4 * (size_t)i + 2) = b;
}

__global__ void __launch_bounds__(256)
wsplit(const float* __restrict__ src, __nv_bfloat16* __restrict__ h,
       __nv_bfloat16* __restrict__ l, int n)
{
    const int i = blockIdx.x * blockDim.x + threadIdx.x;
    if (i >= n) return;
    const float v = src[i];
    const __nv_bfloat16 hv = __float2bfloat16_rn(v);
    h[i] = hv;
    l[i] = __float2bfloat16_rn(v - __bfloat162float(hv));
}

// x [B,N,D] fp32 -> xT hi/lo [B,D,N] bf16
__global__ void __launch_bounds__(256)
transpose_split(const float* __restrict__ src,
                __nv_bfloat16* __restrict__ th, __nv_bfloat16* __restrict__ tl)
{
    __shared__ float ts[32][33];
    const int z = blockIdx.z;
    const int d0 = blockIdx.x * 32, n0 = blockIdx.y * 32;
    const int tx = threadIdx.x & 31, ty = threadIdx.x >> 5;   // ty 0..7
    const float* s = src + ((size_t)z * Nn + n0) * Dd + d0;
    #pragma unroll
    for (int r = 0; r < 4; r++)
        ts[ty + r * 8][tx] = s[(size_t)(ty + r * 8) * Dd + tx];
    __syncthreads();
    __nv_bfloat16* ph = th + ((size_t)z * Dd + d0) * Nn + n0;
    __nv_bfloat16* pl = tl + ((size_t)z * Dd + d0) * Nn + n0;
    #pragma unroll
    for (int r = 0; r < 4; r++) {
        const float v = ts[tx][ty + r * 8];
        const __nv_bfloat16 h = __float2bfloat16_rn(v);
        ph[(size_t)(ty + r * 8) * Nn + tx] = h;
        pl[(size_t)(ty + r * 8) * Nn + tx] = __float2bfloat16_rn(v - __bfloat162float(h));
    }
}

// write normalized fp32 attn from unnormalized hi/lo + rowsum partials
__global__ void __launch_bounds__(256)
normout(const __nv_bfloat16* __restrict__ h, const __nv_bfloat16* __restrict__ l,
        const float* __restrict__ part, float* __restrict__ out)
{
    const size_t row = blockIdx.x;
    const float4 p = *(const float4*)(part + row * 4);
    const float inv = 1.0f / (p.x + p.y + p.z + p.w);
    const int t = threadIdx.x;
    const __nv_bfloat162 hv = *(const __nv_bfloat162*)(h + row * Nn + t * 2);
    const __nv_bfloat162 lv = *(const __nv_bfloat162*)(l + row * Nn + t * 2);
    float2 o;
    o.x = (__bfloat162float(hv.x) + __bfloat162float(lv.x)) * inv;
    o.y = (__bfloat162float(hv.y) + __bfloat162float(lv.y)) * inv;
    *(float2*)(out + row * Nn + t * 2) = o;
}

// ======================= launch =======================
extern "C" void kernel_launch(void* const* d_in, const int* in_sizes, int n_in,
                              void* d_out, int out_size)
{
    const float* x_in  = (const float*)d_in[0];
    const float* adj   = (const float*)d_in[1];
    const float* wA_w  = (const float*)d_in[2];
    const float* wA_b  = (const float*)d_in[3];
    const float* l0_w  = (const float*)d_in[4];
    const float* l0_b  = (const float*)d_in[5];
    const float* l1_w  = (const float*)d_in[6];
    const float* l1_b  = (const float*)d_in[7];
    const float* fin_w = (const float*)d_in[8];
    const float* fin_b = (const float*)d_in[9];

    float* out_x = (float*)d_out;
    float* attls = out_x + (size_t)Bb * Nn * Dd;

    __nv_bfloat16 *xh, *xl, *th, *tl, *qh, *ql, *ah, *al, *wh, *wl;
    float *gx, *gp;
    cudaGetSymbolAddress((void**)&xh, g_xh); cudaGetSymbolAddress((void**)&xl, g_xl);
    cudaGetSymbolAddress((void**)&th, g_th); cudaGetSymbolAddress((void**)&tl, g_tl);
    cudaGetSymbolAddress((void**)&qh, g_qh); cudaGetSymbolAddress((void**)&ql, g_ql);
    cudaGetSymbolAddress((void**)&ah, g_ah); cudaGetSymbolAddress((void**)&al, g_al);
    cudaGetSymbolAddress((void**)&wh, g_wh); cudaGetSymbolAddress((void**)&wl, g_wl);
    cudaGetSymbolAddress((void**)&gx, g_x);  cudaGetSymbolAddress((void**)&gp, g_part);

    cudaFuncSetAttribute(mma_gemm<1>, cudaFuncAttributeMaxDynamicSharedMemorySize, GEMM_SMEM);
    cudaFuncSetAttribute(mma_gemm<2>, cudaFuncAttributeMaxDynamicSharedMemorySize, GEMM_SMEM);
    cudaFuncSetAttribute(mma_gemm<4>, cudaFuncAttributeMaxDynamicSharedMemorySize, GEMM_SMEM);
    cudaFuncSetAttribute(mma_gemm<5>, cudaFuncAttributeMaxDynamicSharedMemorySize, GEMM_SMEM);
    cudaFuncSetAttribute(mma_gemm<6>, cudaFuncAttributeMaxDynamicSharedMemorySize, GEMM_SMEM);
    cudaFuncSetAttribute(mma_gemm<7>, cudaFuncAttributeMaxDynamicSharedMemorySize, GEMM_SMEM);

    const int WSZ = Dd * Dd;                 // 65536
    const long long sX = (long long)Nn * Dd; // per batch
    const long long sA = (long long)Nn * Nn; // per batch

    // split weights: [0..3]=wA, [4..7]=lin0, [8..11]=lin1, [12]=final
    wsplit<<<(4 * WSZ + 255) / 256, 256>>>(wA_w,  wh,            wl,            4 * WSZ);
    wsplit<<<(4 * WSZ + 255) / 256, 256>>>(l0_w,  wh + 4 * WSZ,  wl + 4 * WSZ,  4 * WSZ);
    wsplit<<<(4 * WSZ + 255) / 256, 256>>>(l1_w,  wh + 8 * WSZ,  wl + 8 * WSZ,  4 * WSZ);
    wsplit<<<(WSZ + 255) / 256, 256>>>(fin_w, wh + 12 * WSZ, wl + 12 * WSZ, WSZ);

    // x -> g_x (fp32) + xh/xl (bf16 split)
    {
        const int n4 = XSZ / 4;
        split_copy<<<(n4 + 255) / 256, 256>>>((const float4*)x_in, (float4*)gx, xh, xl, n4);
    }

    const int BIGM = Bb * Nn; // 32768
    for (int l = 0; l < Ll; l++) {
        const float* ba = wA_b + (size_t)l * Dd;
        const float* b0 = l0_b + (size_t)l * Dd;
        const float* b1 = l1_b + (size_t)l * Dd;
        const __nv_bfloat16* Wah = wh + (size_t)l * WSZ;
        const __nv_bfloat16* Wal = wl + (size_t)l * WSZ;
        const __nv_bfloat16* W0h = wh + (size_t)(4 + l) * WSZ;
        const __nv_bfloat16* W0l = wl + (size_t)(4 + l) * WSZ;
        const __nv_bfloat16* W1h = wh + (size_t)(8 + l) * WSZ;
        const __nv_bfloat16* W1l = wl + (size_t)(8 + l) * WSZ;
        float* attl = attls + (size_t)l * Bb * Nn * Nn;

        // xT hi/lo from g_x
        transpose_split<<<dim3(Dd / 32, Nn / 32, Bb), 256>>>(gx, th, tl);

        // q = x @ Wa^T + ba  ->  qh/ql
        mma_gemm<1><<<dim3(BIGM / TM, Dd / TN, 1), 256, GEMM_SMEM>>>(
            xh, xl, Wah, Wal, Dd, 0, 0,
            nullptr, qh, ql, 0, Dd, ba, nullptr, nullptr, nullptr);

        // attn_unnorm = sig(q @ x^T)*adj (+diag) -> ah/al bf16 + rowsum partials
        mma_gemm<2><<<dim3(Nn / TM, Nn / TN, Bb), 256, GEMM_SMEM>>>(
            qh, ql, xh, xl, Dd, sX, sX,
            nullptr, ah, al, sA, Nn, nullptr, nullptr, adj, gp);

        // normalized fp32 attn to output
        normout<<<Bb * Nn, 256>>>(ah, al, gp, attl);

        // t1 = rowscale(attn_unnorm @ x)  (NT with xT)  -> qh/ql
        mma_gemm<7><<<dim3(Nn / TM, Dd / TN, Bb), 256, GEMM_SMEM>>>(
            ah, al, th, tl, Nn, sA, sX,
            nullptr, qh, ql, sX, Dd, nullptr, nullptr, nullptr, gp);

        // h = relu(t1 @ W0^T + b0) -> th/tl
        mma_gemm<4><<<dim3(BIGM / TM, Dd / TN, 1), 256, GEMM_SMEM>>>(
            qh, ql, W0h, W0l, Dd, 0, 0,
            nullptr, th, tl, 0, Dd, b0, nullptr, nullptr, nullptr);

        // x = relu(h @ W1^T + b1) + x0 -> g_x (fp32) + xh/xl
        mma_gemm<5><<<dim3(BIGM / TM, Dd / TN, 1), 256, GEMM_SMEM>>>(
            th, tl, W1h, W1l, Dd, 0, 0,
            gx, xh, xl, 0, Dd, b1, gx, nullptr, nullptr);
    }

    // out = x @ final^T + b
    mma_gemm<6><<<dim3(BIGM / TM, Dd / TN, 1), 256, GEMM_SMEM>>>(
        xh, xl, wh + 12 * WSZ, wl + 12 * WSZ, Dd, 0, 0,
        out_x, nullptr, nullptr, 0, Dd, fin_b, nullptr, nullptr, nullptr);
}

// round 6
// speedup vs baseline: 1.1821x; 1.1631x over previous
#include <cuda_runtime.h>
#include <cuda_bf16.h>
#include <cstdint>
#include <math.h>

#define Bb 64
#define Nn 512
#define Dd 256
#define Ll 4

// ======================= helpers =======================
__device__ __forceinline__ uint32_t smem_u32(const void* p) {
    uint32_t a;
    asm("{ .reg .u64 t; cvta.to.shared.u64 t, %1; cvt.u32.u64 %0, t; }" : "=r"(a) : "l"(p));
    return a;
}
__device__ __forceinline__ void cp16(uint32_t s, const void* g) {
    asm volatile("cp.async.cg.shared.global [%0], [%1], 16;" :: "r"(s), "l"(g));
}
__device__ __forceinline__ void ldsm4(uint32_t* r, uint32_t addr) {
    asm volatile("ldmatrix.sync.aligned.m8n8.x4.shared.b16 {%0,%1,%2,%3}, [%4];"
        : "=r"(r[0]), "=r"(r[1]), "=r"(r[2]), "=r"(r[3]) : "r"(addr));
}
__device__ __forceinline__ void mma16816(float* d, const uint32_t* a, const uint32_t* b) {
    asm volatile("mma.sync.aligned.m16n8k16.row.col.f32.bf16.bf16.f32 "
        "{%0,%1,%2,%3}, {%4,%5,%6,%7}, {%8,%9}, {%0,%1,%2,%3};"
        : "+f"(d[0]), "+f"(d[1]), "+f"(d[2]), "+f"(d[3])
        : "r"(a[0]), "r"(a[1]), "r"(a[2]), "r"(a[3]), "r"(b[0]), "r"(b[1]));
}

// ======================= device globals (scratch) =======================
#define XSZ (Bb * Nn * Dd)
#define ASZ (Bb * Nn * Nn)
__device__ __align__(128) __nv_bfloat16 g_xh[XSZ], g_xl[XSZ];
__device__ __align__(128) __nv_bfloat16 g_th[XSZ], g_tl[XSZ];   // xT, then lin0 output
__device__ __align__(128) __nv_bfloat16 g_qh[XSZ], g_ql[XSZ];   // q, then t1
__device__ __align__(128) __nv_bfloat16 g_ah[ASZ], g_al[ASZ];   // attn hi/lo (UNNORMALIZED)
__device__ __align__(128) __nv_bfloat16 g_wh[13 * Dd * Dd], g_wl[13 * Dd * Dd];
__device__ __align__(128) float g_x[XSZ];
__device__ __align__(128) float g_part[Bb * Nn * 4];            // row-sum partials (4 ctaY)

// ======================= MMA GEMM (NT, K-major both operands) =======================
// C[M, Ncols] = (Ah+Al)[M,K] @ ((Bh+Bl)[Ncols,K])^T ; fp32 accum via 3 HMMA products.
// EPI: 1=bias->hl | 2=sigmoid*adj->hl + rowsum partials | 4=relu(bias)->hl
//      5=relu(bias)+res->fp32+hl | 6=bias->fp32 | 7=rowscale(1/sum part)->hl
#define TM 128
#define TN 128
#define RS 80                           // padded smem row stride (bytes) for 64B rows
#define MAT_BYTES (128 * RS)            // 10240
#define STAGE_BYTES (4 * MAT_BYTES)     // Ah, Al, Bh, Bl = 40960
#define GEMM_SMEM (2 * STAGE_BYTES)     // 81920 -> 2 CTAs/SM

template<int EPI>
__global__ void __launch_bounds__(256, 1)
mma_gemm(const __nv_bfloat16* __restrict__ Ah, const __nv_bfloat16* __restrict__ Al,
         const __nv_bfloat16* __restrict__ Bh, const __nv_bfloat16* __restrict__ Bl,
         int K, long long sAz, long long sBz,
         float* __restrict__ Cf, __nv_bfloat16* __restrict__ Ch, __nv_bfloat16* __restrict__ Cl,
         long long sCz, int ldc,
         const float* __restrict__ bias, const float* __restrict__ res,
         const float* __restrict__ adj, float* __restrict__ part)
{
    extern __shared__ char smch[];
    const uint32_t sb = smem_u32(smch);
    const int tid = threadIdx.x;
    const int wid = tid >> 5;
    const int lane = tid & 31;
    const int z = blockIdx.z;
    const int bm = blockIdx.x * TM;
    const int bn = blockIdx.y * TN;

    Ah += (size_t)z * sAz + (size_t)bm * K;
    Al += (size_t)z * sAz + (size_t)bm * K;
    Bh += (size_t)z * sBz + (size_t)bn * K;
    Bl += (size_t)z * sBz + (size_t)bn * K;

    // loader geometry: each thread owns one 32B segment of one row, per matrix
    const int lr = tid >> 1;            // row 0..127
    const int lc = (tid & 1) * 2;       // chunk pair 0 or 2
    const uint32_t s_off = (uint32_t)lr * RS + (uint32_t)lc * 16;

    auto issue = [&](int kb, int buf) {
        const size_t go = (size_t)lr * K + (size_t)kb * 32 + (size_t)lc * 8;
        const uint32_t s0 = sb + buf * STAGE_BYTES + s_off;
        cp16(s0,                      Ah + go);
        cp16(s0 + 16,                 Ah + go + 8);
        cp16(s0 + MAT_BYTES,          Al + go);
        cp16(s0 + MAT_BYTES + 16,     Al + go + 8);
        cp16(s0 + 2 * MAT_BYTES,      Bh + go);
        cp16(s0 + 2 * MAT_BYTES + 16, Bh + go + 8);
        cp16(s0 + 3 * MAT_BYTES,      Bl + go);
        cp16(s0 + 3 * MAT_BYTES + 16, Bl + go + 8);
    };

    const int KB = K / 32;
    issue(0, 0);
    asm volatile("cp.async.commit_group;" ::: "memory");
    issue(1, 1);
    asm volatile("cp.async.commit_group;" ::: "memory");

    const int wm = (wid & 1) * 64;      // warp row offset in tile
    const int wn = (wid >> 1) * 32;     // warp col offset in tile

    float acc[4][4][4];
    #pragma unroll
    for (int i = 0; i < 4; i++)
        #pragma unroll
        for (int j = 0; j < 4; j++)
            #pragma unroll
            for (int k = 0; k < 4; k++) acc[i][j][k] = 0.0f;

    const int rr = lane & 15;
    const int csel = lane >> 4;         // 0/1 -> second 16B chunk of the k16

    for (int kb = 0; kb < KB; kb++) {
        asm volatile("cp.async.wait_group 1;" ::: "memory");
        __syncthreads();
        const uint32_t bufb = sb + (kb & 1) * STAGE_BYTES;

        #pragma unroll
        for (int ks = 0; ks < 2; ks++) {
            const uint32_t coff = (uint32_t)(ks * 2 + csel) * 16;
            uint32_t ah[4][4], al[4][4], bh[4][2], bl[4][2];
            const uint32_t abase = bufb + (uint32_t)(wm + rr) * RS + coff;
            #pragma unroll
            for (int mt = 0; mt < 4; mt++) {
                ldsm4(ah[mt], abase + mt * (16 * RS));
                ldsm4(al[mt], abase + mt * (16 * RS) + MAT_BYTES);
            }
            const uint32_t bbase = bufb + 2 * MAT_BYTES + (uint32_t)(wn + rr) * RS + coff;
            #pragma unroll
            for (int ntt = 0; ntt < 2; ntt++) {
                uint32_t t4[4];
                ldsm4(t4, bbase + ntt * (16 * RS));
                bh[2 * ntt][0] = t4[0]; bh[2 * ntt][1] = t4[2];
                bh[2 * ntt + 1][0] = t4[1]; bh[2 * ntt + 1][1] = t4[3];
                ldsm4(t4, bbase + ntt * (16 * RS) + MAT_BYTES);
                bl[2 * ntt][0] = t4[0]; bl[2 * ntt][1] = t4[2];
                bl[2 * ntt + 1][0] = t4[1]; bl[2 * ntt + 1][1] = t4[3];
            }
            #pragma unroll
            for (int mt = 0; mt < 4; mt++)
                #pragma unroll
                for (int nt = 0; nt < 4; nt++) {
                    mma16816(acc[mt][nt], ah[mt], bh[nt]);
                    mma16816(acc[mt][nt], ah[mt], bl[nt]);
                    mma16816(acc[mt][nt], al[mt], bh[nt]);
                }
        }
        __syncthreads();
        if (kb + 2 < KB) issue(kb + 2, kb & 1);
        asm volatile("cp.async.commit_group;" ::: "memory");
    }

    // ======================= epilogue =======================
    const int qrow = lane >> 2;         // 0..7
    const int qcol = (lane & 3) * 2;    // 0,2,4,6
    float* redsm = (float*)smch;        // [128 rows][4 nwarps] overlay (mainloop done)

    float rsum0[4], rsum1[4];           // per-thread row partial sums (EPI==2)

    #pragma unroll
    for (int mt = 0; mt < 4; mt++) {
        const int r0 = bm + wm + mt * 16 + qrow;
        const int r1 = r0 + 8;
        if (EPI == 2) { rsum0[mt] = 0.0f; rsum1[mt] = 0.0f; }
        #pragma unroll
        for (int nt = 0; nt < 4; nt++) {
            const int col = bn + wn + nt * 8 + qcol;
            float v00 = acc[mt][nt][0], v01 = acc[mt][nt][1];
            float v10 = acc[mt][nt][2], v11 = acc[mt][nt][3];

            if (EPI == 2) {
                const float* a0 = adj + ((size_t)z * Nn + r0) * Nn;
                const float* a1 = adj + ((size_t)z * Nn + r1) * Nn;
                float s00 = 1.0f / (1.0f + __expf(-v00));
                float s01 = 1.0f / (1.0f + __expf(-v01));
                float s10 = 1.0f / (1.0f + __expf(-v10));
                float s11 = 1.0f / (1.0f + __expf(-v11));
                v00 = (col == r0)     ? (s00 + 1e-5f) : s00 * __ldg(a0 + col);
                v01 = (col + 1 == r0) ? (s01 + 1e-5f) : s01 * __ldg(a0 + col + 1);
                v10 = (col == r1)     ? (s10 + 1e-5f) : s10 * __ldg(a1 + col);
                v11 = (col + 1 == r1) ? (s11 + 1e-5f) : s11 * __ldg(a1 + col + 1);
                rsum0[mt] += v00 + v01;
                rsum1[mt] += v10 + v11;
            } else if (EPI == 7) {
                const float4 p0 = *(const float4*)(part + ((size_t)z * Nn + r0) * 4);
                const float4 p1 = *(const float4*)(part + ((size_t)z * Nn + r1) * 4);
                const float inv0 = 1.0f / (p0.x + p0.y + p0.z + p0.w);
                const float inv1 = 1.0f / (p1.x + p1.y + p1.z + p1.w);
                v00 *= inv0; v01 *= inv0; v10 *= inv1; v11 *= inv1;
            } else if (EPI == 1) {
                const float b0v = __ldg(bias + col), b1v = __ldg(bias + col + 1);
                v00 += b0v; v01 += b1v; v10 += b0v; v11 += b1v;
            } else if (EPI == 4 || EPI == 5) {
                const float b0v = __ldg(bias + col), b1v = __ldg(bias + col + 1);
                v00 = fmaxf(v00 + b0v, 0.0f); v01 = fmaxf(v01 + b1v, 0.0f);
                v10 = fmaxf(v10 + b0v, 0.0f); v11 = fmaxf(v11 + b1v, 0.0f);
            }

            if (EPI == 6) {
                const float b0v = __ldg(bias + col), b1v = __ldg(bias + col + 1);
                float* cf0 = Cf + (size_t)z * sCz + (size_t)r0 * ldc;
                float* cf1 = Cf + (size_t)z * sCz + (size_t)r1 * ldc;
                float2 p0; p0.x = v00 + b0v; p0.y = v01 + b1v;
                float2 p1; p1.x = v10 + b0v; p1.y = v11 + b1v;
                *(float2*)(cf0 + col) = p0;
                *(float2*)(cf1 + col) = p1;
            } else {
                if (EPI == 5) {
                    const float* rp0 = res + (size_t)r0 * ldc;
                    const float* rp1 = res + (size_t)r1 * ldc;
                    v00 += rp0[col]; v01 += rp0[col + 1];
                    v10 += rp1[col]; v11 += rp1[col + 1];
                    float* cf0 = Cf + (size_t)r0 * ldc;
                    float* cf1 = Cf + (size_t)r1 * ldc;
                    float2 p0; p0.x = v00; p0.y = v01;
                    float2 p1; p1.x = v10; p1.y = v11;
                    *(float2*)(cf0 + col) = p0;
                    *(float2*)(cf1 + col) = p1;
                }
                __nv_bfloat16* ch0 = Ch + (size_t)z * sCz + (size_t)r0 * ldc;
                __nv_bfloat16* ch1 = Ch + (size_t)z * sCz + (size_t)r1 * ldc;
                __nv_bfloat16* cl0 = Cl + (size_t)z * sCz + (size_t)r0 * ldc;
                __nv_bfloat16* cl1 = Cl + (size_t)z * sCz + (size_t)r1 * ldc;
                __nv_bfloat16 h00 = __float2bfloat16_rn(v00), h01 = __float2bfloat16_rn(v01);
                __nv_bfloat16 h10 = __float2bfloat16_rn(v10), h11 = __float2bfloat16_rn(v11);
                __nv_bfloat162 hp0; hp0.x = h00; hp0.y = h01;
                __nv_bfloat162 hp1; hp1.x = h10; hp1.y = h11;
                *(__nv_bfloat162*)(ch0 + col) = hp0;
                *(__nv_bfloat162*)(ch1 + col) = hp1;
                __nv_bfloat162 lp0, lp1;
                lp0.x = __float2bfloat16_rn(v00 - __bfloat162float(h00));
                lp0.y = __float2bfloat16_rn(v01 - __bfloat162float(h01));
                lp1.x = __float2bfloat16_rn(v10 - __bfloat162float(h10));
                lp1.y = __float2bfloat16_rn(v11 - __bfloat162float(h11));
                *(__nv_bfloat162*)(cl0 + col) = lp0;
                *(__nv_bfloat162*)(cl1 + col) = lp1;
            }
        }
    }

    if (EPI == 2) {
        // reduce row partial sums: across (lane&3), then across the 4 n-warps via smem
        __syncthreads();                // mainloop smem dead; safe to overlay
        const int nw = wid >> 1;
        #pragma unroll
        for (int mt = 0; mt < 4; mt++) {
            float s0 = rsum0[mt], s1 = rsum1[mt];
            s0 += __shfl_xor_sync(0xffffffffu, s0, 1);
            s0 += __shfl_xor_sync(0xffffffffu, s0, 2);
            s1 += __shfl_xor_sync(0xffffffffu, s1, 1);
            s1 += __shfl_xor_sync(0xffffffffu, s1, 2);
            if ((lane & 3) == 0) {
                const int rc = wm + mt * 16 + qrow;
                redsm[rc * 4 + nw]       = s0;
                redsm[(rc + 8) * 4 + nw] = s1;
            }
        }
        __syncthreads();
        if (tid < 128) {
            const float s = redsm[tid * 4] + redsm[tid * 4 + 1]
                          + redsm[tid * 4 + 2] + redsm[tid * 4 + 3];
            part[((size_t)z * Nn + bm + tid) * 4 + blockIdx.y] = s;
        }
    }
}

// ======================= small kernels =======================
__global__ void __launch_bounds__(256)
split_copy(const float4* __restrict__ src, float4* __restrict__ dst,
           __nv_bfloat16* __restrict__ h, __nv_bfloat16* __restrict__ l, int n4)
{
    const int i = blockIdx.x * blockDim.x + threadIdx.x;
    if (i >= n4) return;
    const float4 v = src[i];
    dst[i] = v;
    const float vv[4] = {v.x, v.y, v.z, v.w};
    __nv_bfloat16 hh[4], ll[4];
    #pragma unroll
    for (int k = 0; k < 4; k++) {
        hh[k] = __float2bfloat16_rn(vv[k]);
        ll[k] = __float2bfloat16_rn(vv[k] - __bfloat162float(hh[k]));
    }
    __nv_bfloat162 a, b;
    a.x = hh[0]; a.y = hh[1]; b.x = hh[2]; b.y = hh[3];
    *(__nv_bfloat162*)(h + 4 * (size_t)i) = a;
    *(__nv_bfloat162*)(h + 4 * (size_t)i + 2) = b;
    a.x = ll[0]; a.y = ll[1]; b.x = ll[2]; b.y = ll[3];
    *(__nv_bfloat162*)(l + 4 * (size_t)i) = a;
    *(__nv_bfloat162*)(l + 4 * (size_t)i + 2) = b;
}

__global__ void __launch_bounds__(256)
wsplit(const float* __restrict__ src, __nv_bfloat16* __restrict__ h,
       __nv_bfloat16* __restrict__ l, int n)
{
    const int i = blockIdx.x * blockDim.x + threadIdx.x;
    if (i >= n) return;
    const float v = src[i];
    const __nv_bfloat16 hv = __float2bfloat16_rn(v);
    h[i] = hv;
    l[i] = __float2bfloat16_rn(v - __bfloat162float(hv));
}

// x [B,N,D] fp32 -> xT hi/lo [B,D,N] bf16
__global__ void __launch_bounds__(256)
transpose_split(const float* __restrict__ src,
                __nv_bfloat16* __restrict__ th, __nv_bfloat16* __restrict__ tl)
{
    __shared__ float ts[32][33];
    const int z = blockIdx.z;
    const int d0 = blockIdx.x * 32, n0 = blockIdx.y * 32;
    const int tx = threadIdx.x & 31, ty = threadIdx.x >> 5;   // ty 0..7
    const float* s = src + ((size_t)z * Nn + n0) * Dd + d0;
    #pragma unroll
    for (int r = 0; r < 4; r++)
        ts[ty + r * 8][tx] = s[(size_t)(ty + r * 8) * Dd + tx];
    __syncthreads();
    __nv_bfloat16* ph = th + ((size_t)z * Dd + d0) * Nn + n0;
    __nv_bfloat16* pl = tl + ((size_t)z * Dd + d0) * Nn + n0;
    #pragma unroll
    for (int r = 0; r < 4; r++) {
        const float v = ts[tx][ty + r * 8];
        const __nv_bfloat16 h = __float2bfloat16_rn(v);
        ph[(size_t)(ty + r * 8) * Nn + tx] = h;
        pl[(size_t)(ty + r * 8) * Nn + tx] = __float2bfloat16_rn(v - __bfloat162float(h));
    }
}

// write normalized fp32 attn from unnormalized hi/lo + rowsum partials
__global__ void __launch_bounds__(256)
normout(const __nv_bfloat16* __restrict__ h, const __nv_bfloat16* __restrict__ l,
        const float* __restrict__ part, float* __restrict__ out)
{
    const size_t row = blockIdx.x;
    const float4 p = *(const float4*)(part + row * 4);
    const float inv = 1.0f / (p.x + p.y + p.z + p.w);
    const int t = threadIdx.x;
    const __nv_bfloat162 hv = *(const __nv_bfloat162*)(h + row * Nn + t * 2);
    const __nv_bfloat162 lv = *(const __nv_bfloat162*)(l + row * Nn + t * 2);
    float2 o;
    o.x = (__bfloat162float(hv.x) + __bfloat162float(lv.x)) * inv;
    o.y = (__bfloat162float(hv.y) + __bfloat162float(lv.y)) * inv;
    *(float2*)(out + row * Nn + t * 2) = o;
}

// ======================= launch =======================
extern "C" void kernel_launch(void* const* d_in, const int* in_sizes, int n_in,
                              void* d_out, int out_size)
{
    const float* x_in  = (const float*)d_in[0];
    const float* adj   = (const float*)d_in[1];
    const float* wA_w  = (const float*)d_in[2];
    const float* wA_b  = (const float*)d_in[3];
    const float* l0_w  = (const float*)d_in[4];
    const float* l0_b  = (const float*)d_in[5];
    const float* l1_w  = (const float*)d_in[6];
    const float* l1_b  = (const float*)d_in[7];
    const float* fin_w = (const float*)d_in[8];
    const float* fin_b = (const float*)d_in[9];

    float* out_x = (float*)d_out;
    float* attls = out_x + (size_t)Bb * Nn * Dd;

    __nv_bfloat16 *xh, *xl, *th, *tl, *qh, *ql, *ah, *al, *wh, *wl;
    float *gx, *gp;
    cudaGetSymbolAddress((void**)&xh, g_xh); cudaGetSymbolAddress((void**)&xl, g_xl);
    cudaGetSymbolAddress((void**)&th, g_th); cudaGetSymbolAddress((void**)&tl, g_tl);
    cudaGetSymbolAddress((void**)&qh, g_qh); cudaGetSymbolAddress((void**)&ql, g_ql);
    cudaGetSymbolAddress((void**)&ah, g_ah); cudaGetSymbolAddress((void**)&al, g_al);
    cudaGetSymbolAddress((void**)&wh, g_wh); cudaGetSymbolAddress((void**)&wl, g_wl);
    cudaGetSymbolAddress((void**)&gx, g_x);  cudaGetSymbolAddress((void**)&gp, g_part);

    cudaFuncSetAttribute(mma_gemm<1>, cudaFuncAttributeMaxDynamicSharedMemorySize, GEMM_SMEM);
    cudaFuncSetAttribute(mma_gemm<2>, cudaFuncAttributeMaxDynamicSharedMemorySize, GEMM_SMEM);
    cudaFuncSetAttribute(mma_gemm<4>, cudaFuncAttributeMaxDynamicSharedMemorySize, GEMM_SMEM);
    cudaFuncSetAttribute(mma_gemm<5>, cudaFuncAttributeMaxDynamicSharedMemorySize, GEMM_SMEM);
    cudaFuncSetAttribute(mma_gemm<6>, cudaFuncAttributeMaxDynamicSharedMemorySize, GEMM_SMEM);
    cudaFuncSetAttribute(mma_gemm<7>, cudaFuncAttributeMaxDynamicSharedMemorySize, GEMM_SMEM);

    const int WSZ = Dd * Dd;                 // 65536
    const long long sX = (long long)Nn * Dd; // per batch
    const long long sA = (long long)Nn * Nn; // per batch

    // split weights: [0..3]=wA, [4..7]=lin0, [8..11]=lin1, [12]=final
    wsplit<<<(4 * WSZ + 255) / 256, 256>>>(wA_w,  wh,            wl,            4 * WSZ);
    wsplit<<<(4 * WSZ + 255) / 256, 256>>>(l0_w,  wh + 4 * WSZ,  wl + 4 * WSZ,  4 * WSZ);
    wsplit<<<(4 * WSZ + 255) / 256, 256>>>(l1_w,  wh + 8 * WSZ,  wl + 8 * WSZ,  4 * WSZ);
    wsplit<<<(WSZ + 255) / 256, 256>>>(fin_w, wh + 12 * WSZ, wl + 12 * WSZ, WSZ);

    // x -> g_x (fp32) + xh/xl (bf16 split)
    {
        const int n4 = XSZ / 4;
        split_copy<<<(n4 + 255) / 256, 256>>>((const float4*)x_in, (float4*)gx, xh, xl, n4);
    }

    const int BIGM = Bb * Nn; // 32768
    for (int l = 0; l < Ll; l++) {
        const float* ba = wA_b + (size_t)l * Dd;
        const float* b0 = l0_b + (size_t)l * Dd;
        const float* b1 = l1_b + (size_t)l * Dd;
        const __nv_bfloat16* Wah = wh + (size_t)l * WSZ;
        const __nv_bfloat16* Wal = wl + (size_t)l * WSZ;
        const __nv_bfloat16* W0h = wh + (size_t)(4 + l) * WSZ;
        const __nv_bfloat16* W0l = wl + (size_t)(4 + l) * WSZ;
        const __nv_bfloat16* W1h = wh + (size_t)(8 + l) * WSZ;
        const __nv_bfloat16* W1l = wl + (size_t)(8 + l) * WSZ;
        float* attl = attls + (size_t)l * Bb * Nn * Nn;

        // xT hi/lo from g_x
        transpose_split<<<dim3(Dd / 32, Nn / 32, Bb), 256>>>(gx, th, tl);

        // q = x @ Wa^T + ba  ->  qh/ql
        mma_gemm<1><<<dim3(BIGM / TM, Dd / TN, 1), 256, GEMM_SMEM>>>(
            xh, xl, Wah, Wal, Dd, 0, 0,
            nullptr, qh, ql, 0, Dd, ba, nullptr, nullptr, nullptr);

        // attn_unnorm = sig(q @ x^T)*adj (+diag) -> ah/al bf16 + rowsum partials
        mma_gemm<2><<<dim3(Nn / TM, Nn / TN, Bb), 256, GEMM_SMEM>>>(
            qh, ql, xh, xl, Dd, sX, sX,
            nullptr, ah, al, sA, Nn, nullptr, nullptr, adj, gp);

        // normalized fp32 attn to output
        normout<<<Bb * Nn, 256>>>(ah, al, gp, attl);

        // t1 = rowscale(attn_unnorm @ x)  (NT with xT)  -> qh/ql
        mma_gemm<7><<<dim3(Nn / TM, Dd / TN, Bb), 256, GEMM_SMEM>>>(
            ah, al, th, tl, Nn, sA, sX,
            nullptr, qh, ql, sX, Dd, nullptr, nullptr, nullptr, gp);

        // h = relu(t1 @ W0^T + b0) -> th/tl
        mma_gemm<4><<<dim3(BIGM / TM, Dd / TN, 1), 256, GEMM_SMEM>>>(
            qh, ql, W0h, W0l, Dd, 0, 0,
            nullptr, th, tl, 0, Dd, b0, nullptr, nullptr, nullptr);

        // x = relu(h @ W1^T + b1) + x0 -> g_x (fp32) + xh/xl
        mma_gemm<5><<<dim3(BIGM / TM, Dd / TN, 1), 256, GEMM_SMEM>>>(
            th, tl, W1h, W1l, Dd, 0, 0,
            gx, xh, xl, 0, Dd, b1, gx, nullptr, nullptr);
    }

    // out = x @ final^T + b
    mma_gemm<6><<<dim3(BIGM / TM, Dd / TN, 1), 256, GEMM_SMEM>>>(
        xh, xl, wh + 12 * WSZ, wl + 12 * WSZ, Dd, 0, 0,
        out_x, nullptr, nullptr, 0, Dd, fin_b, nullptr, nullptr, nullptr);
}

// round 7
// speedup vs baseline: 1.5196x; 1.2856x over previous
#include <cuda_runtime.h>
#include <cuda_fp16.h>
#include <cstdint>
#include <math.h>

#define Bb 64
#define Nn 512
#define Dd 256
#define Ll 4

// ======================= helpers =======================
__device__ __forceinline__ uint32_t smem_u32(const void* p) {
    uint32_t a;
    asm("{ .reg .u64 t; cvta.to.shared.u64 t, %1; cvt.u32.u64 %0, t; }" : "=r"(a) : "l"(p));
    return a;
}
__device__ __forceinline__ void cp16(uint32_t s, const void* g) {
    asm volatile("cp.async.cg.shared.global [%0], [%1], 16;" :: "r"(s), "l"(g));
}
__device__ __forceinline__ void ldsm4(uint32_t* r, uint32_t addr) {
    asm volatile("ldmatrix.sync.aligned.m8n8.x4.shared.b16 {%0,%1,%2,%3}, [%4];"
        : "=r"(r[0]), "=r"(r[1]), "=r"(r[2]), "=r"(r[3]) : "r"(addr));
}
__device__ __forceinline__ void mma16816(float* d, const uint32_t* a, const uint32_t* b) {
    asm volatile("mma.sync.aligned.m16n8k16.row.col.f32.f16.f16.f32 "
        "{%0,%1,%2,%3}, {%4,%5,%6,%7}, {%8,%9}, {%0,%1,%2,%3};"
        : "+f"(d[0]), "+f"(d[1]), "+f"(d[2]), "+f"(d[3])
        : "r"(a[0]), "r"(a[1]), "r"(a[2]), "r"(a[3]), "r"(b[0]), "r"(b[1]));
}

// ======================= device globals (scratch) =======================
#define XSZ (Bb * Nn * Dd)
#define ASZ (Bb * Nn * Nn)
__device__ __align__(128) __half g_xh[XSZ], g_xl[XSZ];
__device__ __align__(128) __half g_th[XSZ], g_tl[XSZ];   // xT, then lin0 output
__device__ __align__(128) __half g_qh[XSZ], g_ql[XSZ];   // q, then t1
__device__ __align__(128) __half g_ah[ASZ], g_al[ASZ];   // attn hi/lo (UNNORMALIZED)
__device__ __align__(128) __half g_wh[13 * Dd * Dd], g_wl[13 * Dd * Dd];
__device__ __align__(128) float g_x[XSZ];
__device__ __align__(128) float g_part[Bb * Nn * 4];     // row-sum partials (4 ctaY)

// ======================= MMA GEMM (NT, K-major both operands) =======================
// C[M, Ncols] = (Ah+Al)[M,K] @ (Bh[Ncols,K])^T ; fp32 accum via 2 HMMA products.
// EPI: 1=bias->hl | 2=sigmoid*adj->hl + rowsum partials | 4=relu(bias)->hl
//      5=relu(bias)+res->fp32+hl | 6=bias->fp32 | 7=rowscale(1/sum part)->hl
#define TM 128
#define TN 128
#define RS 80                           // padded smem row stride (bytes) for 64B rows
#define MAT_BYTES (128 * RS)            // 10240
#define STAGE_BYTES (3 * MAT_BYTES)     // Ah, Al, Bh = 30720
#define GEMM_SMEM (2 * STAGE_BYTES)     // 61440 -> 2 CTAs/SM

template<int EPI>
__global__ void __launch_bounds__(256, 2)
mma_gemm(const __half* __restrict__ Ah, const __half* __restrict__ Al,
         const __half* __restrict__ Bh,
         int K, long long sAz, long long sBz,
         float* __restrict__ Cf, __half* __restrict__ Ch, __half* __restrict__ Cl,
         long long sCz, int ldc,
         const float* __restrict__ bias, const float* __restrict__ res,
         const float* __restrict__ adj, float* __restrict__ part)
{
    extern __shared__ char smch[];
    const uint32_t sb = smem_u32(smch);
    const int tid = threadIdx.x;
    const int wid = tid >> 5;
    const int lane = tid & 31;
    const int z = blockIdx.z;
    const int bm = blockIdx.x * TM;
    const int bn = blockIdx.y * TN;

    Ah += (size_t)z * sAz + (size_t)bm * K;
    Al += (size_t)z * sAz + (size_t)bm * K;
    Bh += (size_t)z * sBz + (size_t)bn * K;

    // loader geometry: each thread owns one 32B segment of one row, per matrix
    const int lr = tid >> 1;            // row 0..127
    const int lc = (tid & 1) * 2;       // chunk pair 0 or 2
    const uint32_t s_off = (uint32_t)lr * RS + (uint32_t)lc * 16;

    auto issue = [&](int kb, int buf) {
        const size_t go = (size_t)lr * K + (size_t)kb * 32 + (size_t)lc * 8;
        const uint32_t s0 = sb + buf * STAGE_BYTES + s_off;
        cp16(s0,                      Ah + go);
        cp16(s0 + 16,                 Ah + go + 8);
        cp16(s0 + MAT_BYTES,          Al + go);
        cp16(s0 + MAT_BYTES + 16,     Al + go + 8);
        cp16(s0 + 2 * MAT_BYTES,      Bh + go);
        cp16(s0 + 2 * MAT_BYTES + 16, Bh + go + 8);
    };

    const int KB = K / 32;
    issue(0, 0);
    asm volatile("cp.async.commit_group;" ::: "memory");
    issue(1, 1);
    asm volatile("cp.async.commit_group;" ::: "memory");

    const int wm = (wid & 1) * 64;      // warp row offset in tile
    const int wn = (wid >> 1) * 32;     // warp col offset in tile

    float acc[4][4][4];
    #pragma unroll
    for (int i = 0; i < 4; i++)
        #pragma unroll
        for (int j = 0; j < 4; j++)
            #pragma unroll
            for (int k = 0; k < 4; k++) acc[i][j][k] = 0.0f;

    const int rr = lane & 15;
    const int csel = lane >> 4;         // 0/1 -> second 16B chunk of the k16

    for (int kb = 0; kb < KB; kb++) {
        asm volatile("cp.async.wait_group 1;" ::: "memory");
        __syncthreads();
        const uint32_t bufb = sb + (kb & 1) * STAGE_BYTES;

        #pragma unroll
        for (int ks = 0; ks < 2; ks++) {
            const uint32_t coff = (uint32_t)(ks * 2 + csel) * 16;
            uint32_t ah[4][4], al[4][4], bh[4][2];
            const uint32_t abase = bufb + (uint32_t)(wm + rr) * RS + coff;
            #pragma unroll
            for (int mt = 0; mt < 4; mt++) {
                ldsm4(ah[mt], abase + mt * (16 * RS));
                ldsm4(al[mt], abase + mt * (16 * RS) + MAT_BYTES);
            }
            const uint32_t bbase = bufb + 2 * MAT_BYTES + (uint32_t)(wn + rr) * RS + coff;
            #pragma unroll
            for (int ntt = 0; ntt < 2; ntt++) {
                uint32_t t4[4];
                ldsm4(t4, bbase + ntt * (16 * RS));
                bh[2 * ntt][0] = t4[0]; bh[2 * ntt][1] = t4[2];
                bh[2 * ntt + 1][0] = t4[1]; bh[2 * ntt + 1][1] = t4[3];
            }
            #pragma unroll
            for (int mt = 0; mt < 4; mt++)
                #pragma unroll
                for (int nt = 0; nt < 4; nt++) {
                    mma16816(acc[mt][nt], ah[mt], bh[nt]);
                    mma16816(acc[mt][nt], al[mt], bh[nt]);
                }
        }
        __syncthreads();
        if (kb + 2 < KB) issue(kb + 2, kb & 1);
        asm volatile("cp.async.commit_group;" ::: "memory");
    }

    // ======================= epilogue =======================
    const int qrow = lane >> 2;         // 0..7
    const int qcol = (lane & 3) * 2;    // 0,2,4,6
    float* redsm = (float*)smch;        // [128 rows][4 nwarps] overlay (mainloop done)

    float rsum0[4], rsum1[4];           // per-thread row partial sums (EPI==2)

    #pragma unroll
    for (int mt = 0; mt < 4; mt++) {
        const int r0 = bm + wm + mt * 16 + qrow;
        const int r1 = r0 + 8;
        if (EPI == 2) { rsum0[mt] = 0.0f; rsum1[mt] = 0.0f; }
        #pragma unroll
        for (int nt = 0; nt < 4; nt++) {
            const int col = bn + wn + nt * 8 + qcol;
            float v00 = acc[mt][nt][0], v01 = acc[mt][nt][1];
            float v10 = acc[mt][nt][2], v11 = acc[mt][nt][3];

            if (EPI == 2) {
                const float* a0 = adj + ((size_t)z * Nn + r0) * Nn;
                const float* a1 = adj + ((size_t)z * Nn + r1) * Nn;
                float s00 = 1.0f / (1.0f + __expf(-v00));
                float s01 = 1.0f / (1.0f + __expf(-v01));
                float s10 = 1.0f / (1.0f + __expf(-v10));
                float s11 = 1.0f / (1.0f + __expf(-v11));
                v00 = (col == r0)     ? (s00 + 1e-5f) : s00 * __ldg(a0 + col);
                v01 = (col + 1 == r0) ? (s01 + 1e-5f) : s01 * __ldg(a0 + col + 1);
                v10 = (col == r1)     ? (s10 + 1e-5f) : s10 * __ldg(a1 + col);
                v11 = (col + 1 == r1) ? (s11 + 1e-5f) : s11 * __ldg(a1 + col + 1);
                rsum0[mt] += v00 + v01;
                rsum1[mt] += v10 + v11;
            } else if (EPI == 7) {
                const float4 p0 = *(const float4*)(part + ((size_t)z * Nn + r0) * 4);
                const float4 p1 = *(const float4*)(part + ((size_t)z * Nn + r1) * 4);
                const float inv0 = 1.0f / (p0.x + p0.y + p0.z + p0.w);
                const float inv1 = 1.0f / (p1.x + p1.y + p1.z + p1.w);
                v00 *= inv0; v01 *= inv0; v10 *= inv1; v11 *= inv1;
            } else if (EPI == 1) {
                const float b0v = __ldg(bias + col), b1v = __ldg(bias + col + 1);
                v00 += b0v; v01 += b1v; v10 += b0v; v11 += b1v;
            } else if (EPI == 4 || EPI == 5) {
                const float b0v = __ldg(bias + col), b1v = __ldg(bias + col + 1);
                v00 = fmaxf(v00 + b0v, 0.0f); v01 = fmaxf(v01 + b1v, 0.0f);
                v10 = fmaxf(v10 + b0v, 0.0f); v11 = fmaxf(v11 + b1v, 0.0f);
            }

            if (EPI == 6) {
                const float b0v = __ldg(bias + col), b1v = __ldg(bias + col + 1);
                float* cf0 = Cf + (size_t)z * sCz + (size_t)r0 * ldc;
                float* cf1 = Cf + (size_t)z * sCz + (size_t)r1 * ldc;
                float2 p0; p0.x = v00 + b0v; p0.y = v01 + b1v;
                float2 p1; p1.x = v10 + b0v; p1.y = v11 + b1v;
                *(float2*)(cf0 + col) = p0;
                *(float2*)(cf1 + col) = p1;
            } else {
                if (EPI == 5) {
                    const float* rp0 = res + (size_t)r0 * ldc;
                    const float* rp1 = res + (size_t)r1 * ldc;
                    v00 += rp0[col]; v01 += rp0[col + 1];
                    v10 += rp1[col]; v11 += rp1[col + 1];
                    float* cf0 = Cf + (size_t)r0 * ldc;
                    float* cf1 = Cf + (size_t)r1 * ldc;
                    float2 p0; p0.x = v00; p0.y = v01;
                    float2 p1; p1.x = v10; p1.y = v11;
                    *(float2*)(cf0 + col) = p0;
                    *(float2*)(cf1 + col) = p1;
                }
                __half* ch0 = Ch + (size_t)z * sCz + (size_t)r0 * ldc;
                __half* ch1 = Ch + (size_t)z * sCz + (size_t)r1 * ldc;
                __half* cl0 = Cl + (size_t)z * sCz + (size_t)r0 * ldc;
                __half* cl1 = Cl + (size_t)z * sCz + (size_t)r1 * ldc;
                const __half h00 = __float2half_rn(v00), h01 = __float2half_rn(v01);
                const __half h10 = __float2half_rn(v10), h11 = __float2half_rn(v11);
                __half2 hp0; hp0.x = h00; hp0.y = h01;
                __half2 hp1; hp1.x = h10; hp1.y = h11;
                *(__half2*)(ch0 + col) = hp0;
                *(__half2*)(ch1 + col) = hp1;
                __half2 lp0, lp1;
                lp0.x = __float2half_rn(v00 - __half2float(h00));
                lp0.y = __float2half_rn(v01 - __half2float(h01));
                lp1.x = __float2half_rn(v10 - __half2float(h10));
                lp1.y = __float2half_rn(v11 - __half2float(h11));
                *(__half2*)(cl0 + col) = lp0;
                *(__half2*)(cl1 + col) = lp1;
            }
        }
    }

    if (EPI == 2) {
        // reduce row partial sums: across (lane&3), then across the 4 n-warps via smem
        __syncthreads();                // mainloop smem dead; safe to overlay
        const int nw = wid >> 1;
        #pragma unroll
        for (int mt = 0; mt < 4; mt++) {
            float s0 = rsum0[mt], s1 = rsum1[mt];
            s0 += __shfl_xor_sync(0xffffffffu, s0, 1);
            s0 += __shfl_xor_sync(0xffffffffu, s0, 2);
            s1 += __shfl_xor_sync(0xffffffffu, s1, 1);
            s1 += __shfl_xor_sync(0xffffffffu, s1, 2);
            if ((lane & 3) == 0) {
                const int rc = wm + mt * 16 + qrow;
                redsm[rc * 4 + nw]       = s0;
                redsm[(rc + 8) * 4 + nw] = s1;
            }
        }
        __syncthreads();
        if (tid < 128) {
            const float s = redsm[tid * 4] + redsm[tid * 4 + 1]
                          + redsm[tid * 4 + 2] + redsm[tid * 4 + 3];
            part[((size_t)z * Nn + bm + tid) * 4 + blockIdx.y] = s;
        }
    }
}

// ======================= small kernels =======================
__global__ void __launch_bounds__(256)
split_copy(const float4* __restrict__ src, float4* __restrict__ dst,
           __half* __restrict__ h, __half* __restrict__ l, int n4)
{
    const int i = blockIdx.x * blockDim.x + threadIdx.x;
    if (i >= n4) return;
    const float4 v = src[i];
    dst[i] = v;
    const float vv[4] = {v.x, v.y, v.z, v.w};
    __half hh[4], ll[4];
    #pragma unroll
    for (int k = 0; k < 4; k++) {
        hh[k] = __float2half_rn(vv[k]);
        ll[k] = __float2half_rn(vv[k] - __half2float(hh[k]));
    }
    __half2 a, b;
    a.x = hh[0]; a.y = hh[1]; b.x = hh[2]; b.y = hh[3];
    *(__half2*)(h + 4 * (size_t)i) = a;
    *(__half2*)(h + 4 * (size_t)i + 2) = b;
    a.x = ll[0]; a.y = ll[1]; b.x = ll[2]; b.y = ll[3];
    *(__half2*)(l + 4 * (size_t)i) = a;
    *(__half2*)(l + 4 * (size_t)i + 2) = b;
}

__global__ void __launch_bounds__(256)
wsplit(const float* __restrict__ src, __half* __restrict__ h,
       __half* __restrict__ l, int n)
{
    const int i = blockIdx.x * blockDim.x + threadIdx.x;
    if (i >= n) return;
    const float v = src[i];
    const __half hv = __float2half_rn(v);
    h[i] = hv;
    l[i] = __float2half_rn(v - __half2float(hv));
}

// x [B,N,D] fp32 -> xT hi/lo [B,D,N] fp16
__global__ void __launch_bounds__(256)
transpose_split(const float* __restrict__ src,
                __half* __restrict__ th, __half* __restrict__ tl)
{
    __shared__ float ts[32][33];
    const int z = blockIdx.z;
    const int d0 = blockIdx.x * 32, n0 = blockIdx.y * 32;
    const int tx = threadIdx.x & 31, ty = threadIdx.x >> 5;   // ty 0..7
    const float* s = src + ((size_t)z * Nn + n0) * Dd + d0;
    #pragma unroll
    for (int r = 0; r < 4; r++)
        ts[ty + r * 8][tx] = s[(size_t)(ty + r * 8) * Dd + tx];
    __syncthreads();
    __half* ph = th + ((size_t)z * Dd + d0) * Nn + n0;
    __half* pl = tl + ((size_t)z * Dd + d0) * Nn + n0;
    #pragma unroll
    for (int r = 0; r < 4; r++) {
        const float v = ts[tx][ty + r * 8];
        const __half h = __float2half_rn(v);
        ph[(size_t)(ty + r * 8) * Nn + tx] = h;
        pl[(size_t)(ty + r * 8) * Nn + tx] = __float2half_rn(v - __half2float(h));
    }
}

// write normalized fp32 attn from unnormalized hi/lo + rowsum partials
__global__ void __launch_bounds__(256)
normout(const __half* __restrict__ h, const __half* __restrict__ l,
        const float* __restrict__ part, float* __restrict__ out)
{
    const size_t row = blockIdx.x;
    const float4 p = *(const float4*)(part + row * 4);
    const float inv = 1.0f / (p.x + p.y + p.z + p.w);
    const int t = threadIdx.x;
    const __half2 hv = *(const __half2*)(h + row * Nn + t * 2);
    const __half2 lv = *(const __half2*)(l + row * Nn + t * 2);
    float2 o;
    o.x = (__half2float(hv.x) + __half2float(lv.x)) * inv;
    o.y = (__half2float(hv.y) + __half2float(lv.y)) * inv;
    *(float2*)(out + row * Nn + t * 2) = o;
}

// ======================= launch =======================
extern "C" void kernel_launch(void* const* d_in, const int* in_sizes, int n_in,
                              void* d_out, int out_size)
{
    const float* x_in  = (const float*)d_in[0];
    const float* adj   = (const float*)d_in[1];
    const float* wA_w  = (const float*)d_in[2];
    const float* wA_b  = (const float*)d_in[3];
    const float* l0_w  = (const float*)d_in[4];
    const float* l0_b  = (const float*)d_in[5];
    const float* l1_w  = (const float*)d_in[6];
    const float* l1_b  = (const float*)d_in[7];
    const float* fin_w = (const float*)d_in[8];
    const float* fin_b = (const float*)d_in[9];

    float* out_x = (float*)d_out;
    float* attls = out_x + (size_t)Bb * Nn * Dd;

    __half *xh, *xl, *th, *tl, *qh, *ql, *ah, *al, *wh, *wl;
    float *gx, *gp;
    cudaGetSymbolAddress((void**)&xh, g_xh); cudaGetSymbolAddress((void**)&xl, g_xl);
    cudaGetSymbolAddress((void**)&th, g_th); cudaGetSymbolAddress((void**)&tl, g_tl);
    cudaGetSymbolAddress((void**)&qh, g_qh); cudaGetSymbolAddress((void**)&ql, g_ql);
    cudaGetSymbolAddress((void**)&ah, g_ah); cudaGetSymbolAddress((void**)&al, g_al);
    cudaGetSymbolAddress((void**)&wh, g_wh); cudaGetSymbolAddress((void**)&wl, g_wl);
    cudaGetSymbolAddress((void**)&gx, g_x);  cudaGetSymbolAddress((void**)&gp, g_part);

    cudaFuncSetAttribute(mma_gemm<1>, cudaFuncAttributeMaxDynamicSharedMemorySize, GEMM_SMEM);
    cudaFuncSetAttribute(mma_gemm<2>, cudaFuncAttributeMaxDynamicSharedMemorySize, GEMM_SMEM);
    cudaFuncSetAttribute(mma_gemm<4>, cudaFuncAttributeMaxDynamicSharedMemorySize, GEMM_SMEM);
    cudaFuncSetAttribute(mma_gemm<5>, cudaFuncAttributeMaxDynamicSharedMemorySize, GEMM_SMEM);
    cudaFuncSetAttribute(mma_gemm<6>, cudaFuncAttributeMaxDynamicSharedMemorySize, GEMM_SMEM);
    cudaFuncSetAttribute(mma_gemm<7>, cudaFuncAttributeMaxDynamicSharedMemorySize, GEMM_SMEM);

    const int WSZ = Dd * Dd;                 // 65536
    const long long sX = (long long)Nn * Dd; // per batch
    const long long sA = (long long)Nn * Nn; // per batch

    // split weights: [0..3]=wA, [4..7]=lin0, [8..11]=lin1, [12]=final
    wsplit<<<(4 * WSZ + 255) / 256, 256>>>(wA_w,  wh,            wl,            4 * WSZ);
    wsplit<<<(4 * WSZ + 255) / 256, 256>>>(l0_w,  wh + 4 * WSZ,  wl + 4 * WSZ,  4 * WSZ);
    wsplit<<<(4 * WSZ + 255) / 256, 256>>>(l1_w,  wh + 8 * WSZ,  wl + 8 * WSZ,  4 * WSZ);
    wsplit<<<(WSZ + 255) / 256, 256>>>(fin_w, wh + 12 * WSZ, wl + 12 * WSZ, WSZ);

    // x -> g_x (fp32) + xh/xl (fp16 split)
    {
        const int n4 = XSZ / 4;
        split_copy<<<(n4 + 255) / 256, 256>>>((const float4*)x_in, (float4*)gx, xh, xl, n4);
    }

    const int BIGM = Bb * Nn; // 32768
    for (int l = 0; l < Ll; l++) {
        const float* ba = wA_b + (size_t)l * Dd;
        const float* b0 = l0_b + (size_t)l * Dd;
        const float* b1 = l1_b + (size_t)l * Dd;
        const __half* Wah = wh + (size_t)l * WSZ;
        const __half* Wal = wl + (size_t)l * WSZ;
        const __half* W0h = wh + (size_t)(4 + l) * WSZ;
        const __half* W0l = wl + (size_t)(4 + l) * WSZ;
        const __half* W1h = wh + (size_t)(8 + l) * WSZ;
        const __half* W1l = wl + (size_t)(8 + l) * WSZ;
        float* attl = attls + (size_t)l * Bb * Nn * Nn;

        // xT hi/lo from g_x
        transpose_split<<<dim3(Dd / 32, Nn / 32, Bb), 256>>>(gx, th, tl);

        // q = x @ Wa^T + ba  ->  qh/ql   (A = x split; B = Wa_h)
        mma_gemm<1><<<dim3(BIGM / TM, Dd / TN, 1), 256, GEMM_SMEM>>>(
            xh, xl, Wah, Dd, 0, 0,
            nullptr, qh, ql, 0, Dd, ba, nullptr, nullptr, nullptr);

        // attn_unnorm = sig(q @ x^T)*adj (+diag) -> ah/al fp16 + rowsum partials
        mma_gemm<2><<<dim3(Nn / TM, Nn / TN, Bb), 256, GEMM_SMEM>>>(
            qh, ql, xh, Dd, sX, sX,
            nullptr, ah, al, sA, Nn, nullptr, nullptr, adj, gp);

        // normalized fp32 attn to output
        normout<<<Bb * Nn, 256>>>(ah, al, gp, attl);

        // t1 = rowscale(attn_unnorm @ x)  (NT with xT)  -> qh/ql
        mma_gemm<7><<<dim3(Nn / TM, Dd / TN, Bb), 256, GEMM_SMEM>>>(
            ah, al, th, Nn, sA, sX,
            nullptr, qh, ql, sX, Dd, nullptr, nullptr, nullptr, gp);

        // h = relu(t1 @ W0^T + b0) -> th/tl
        mma_gemm<4><<<dim3(BIGM / TM, Dd / TN, 1), 256, GEMM_SMEM>>>(
            qh, ql, W0h, Dd, 0, 0,
            nullptr, th, tl, 0, Dd, b0, nullptr, nullptr, nullptr);

        // x = relu(h @ W1^T + b1) + x0 -> g_x (fp32) + xh/xl
        mma_gemm<5><<<dim3(BIGM / TM, Dd / TN, 1), 256, GEMM_SMEM>>>(
            th, tl, W1h, Dd, 0, 0,
            gx, xh, xl, 0, Dd, b1, gx, nullptr, nullptr);
    }

    // out = x @ final^T + b
    mma_gemm<6><<<dim3(BIGM / TM, Dd / TN, 1), 256, GEMM_SMEM>>>(
        xh, xl, wh + 12 * WSZ, Dd, 0, 0,
        out_x, nullptr, nullptr, 0, Dd, fin_b, nullptr, nullptr, nullptr);
}

// round 8
// speedup vs baseline: 1.6324x; 1.0742x over previous
#include <cuda_runtime.h>
#include <cuda_fp16.h>
#include <cstdint>
#include <math.h>

#define Bb 64
#define Nn 512
#define Dd 256
#define Ll 4

// ======================= helpers =======================
__device__ __forceinline__ uint32_t smem_u32(const void* p) {
    uint32_t a;
    asm("{ .reg .u64 t; cvta.to.shared.u64 t, %1; cvt.u32.u64 %0, t; }" : "=r"(a) : "l"(p));
    return a;
}
__device__ __forceinline__ void cp16(uint32_t s, const void* g) {
    asm volatile("cp.async.cg.shared.global [%0], [%1], 16;" :: "r"(s), "l"(g));
}
__device__ __forceinline__ void ldsm4(uint32_t* r, uint32_t addr) {
    asm volatile("ldmatrix.sync.aligned.m8n8.x4.shared.b16 {%0,%1,%2,%3}, [%4];"
        : "=r"(r[0]), "=r"(r[1]), "=r"(r[2]), "=r"(r[3]) : "r"(addr));
}
__device__ __forceinline__ void ldsm4t(uint32_t* r, uint32_t addr) {
    asm volatile("ldmatrix.sync.aligned.m8n8.x4.trans.shared.b16 {%0,%1,%2,%3}, [%4];"
        : "=r"(r[0]), "=r"(r[1]), "=r"(r[2]), "=r"(r[3]) : "r"(addr));
}
__device__ __forceinline__ void mma16816(float* d, const uint32_t* a, const uint32_t* b) {
    asm volatile("mma.sync.aligned.m16n8k16.row.col.f32.f16.f16.f32 "
        "{%0,%1,%2,%3}, {%4,%5,%6,%7}, {%8,%9}, {%0,%1,%2,%3};"
        : "+f"(d[0]), "+f"(d[1]), "+f"(d[2]), "+f"(d[3])
        : "r"(a[0]), "r"(a[1]), "r"(a[2]), "r"(a[3]), "r"(b[0]), "r"(b[1]));
}

// ======================= device globals (scratch) =======================
#define XSZ (Bb * Nn * Dd)
#define ASZ (Bb * Nn * Nn)
__device__ __align__(128) __half g_xh[XSZ], g_xl[XSZ];
__device__ __align__(128) __half g_th[XSZ], g_tl[XSZ];   // lin0 output
__device__ __align__(128) __half g_qh[XSZ], g_ql[XSZ];   // q, then t1
__device__ __align__(128) __half g_ah[ASZ], g_al[ASZ];   // attn hi/lo (UNNORMALIZED)
__device__ __align__(128) __half g_wh[13 * Dd * Dd], g_wl[13 * Dd * Dd];
__device__ __align__(128) float g_x[XSZ];
__device__ __align__(128) float g_part[Bb * Nn * 4];     // row-sum partials (4 ctaY)

// ======================= MMA GEMM =======================
// BT=0: C = (Ah+Al)[M,K] @ (Bh[Ncols,K])^T       (both K-major)
// BT=1: C = (Ah+Al)[M,K] @ (Bh[K,Ncols])          (B row-major, trans-ldmatrix)
// EPI: 1=bias->hl | 2=sigmoid*adj->hl + rowsum partials | 4=relu(bias)->hl
//      5=relu(bias)+res->fp32+hl | 6=bias->fp32 | 7=rowscale(1/sum part)->hl
#define TM 128
#define TN 128
#define RS 80                           // padded smem row stride (A / non-trans B)
#define RSB 272                         // padded smem row stride (trans B: 256B rows)
#define MAT_BYTES (128 * RS)            // 10240
#define STAGE_BYTES (3 * MAT_BYTES)     // Ah, Al, B = 30720
#define GEMM_SMEM (2 * STAGE_BYTES)     // 61440 -> 2 CTAs/SM

template<int EPI, int BT>
__global__ void __launch_bounds__(256, 2)
mma_gemm(const __half* __restrict__ Ah, const __half* __restrict__ Al,
         const __half* __restrict__ Bh,
         int K, int ldb, long long sAz, long long sBz,
         float* __restrict__ Cf, __half* __restrict__ Ch, __half* __restrict__ Cl,
         long long sCz, int ldc,
         const float* __restrict__ bias, const float* __restrict__ res,
         const float* __restrict__ adj, float* __restrict__ part)
{
    extern __shared__ char smch[];
    const uint32_t sb = smem_u32(smch);
    const int tid = threadIdx.x;
    const int wid = tid >> 5;
    const int lane = tid & 31;
    const int z = blockIdx.z;
    const int bm = blockIdx.x * TM;
    const int bn = blockIdx.y * TN;

    Ah += (size_t)z * sAz + (size_t)bm * K;
    Al += (size_t)z * sAz + (size_t)bm * K;
    if (BT) Bh += (size_t)z * sBz + bn;
    else    Bh += (size_t)z * sBz + (size_t)bn * K;

    // A loader: each thread one 32B segment of one of 128 rows
    const int lr = tid >> 1;
    const int lc = (tid & 1) * 2;
    const uint32_t s_off = (uint32_t)lr * RS + (uint32_t)lc * 16;
    // trans-B loader: 32 rows x 256B; each thread one 32B segment
    const int lrB = tid >> 3;
    const int lsB = tid & 7;

    auto issue = [&](int kb, int buf) {
        const size_t go = (size_t)lr * K + (size_t)kb * 32 + (size_t)lc * 8;
        const uint32_t s0 = sb + buf * STAGE_BYTES + s_off;
        cp16(s0,                  Ah + go);
        cp16(s0 + 16,             Ah + go + 8);
        cp16(s0 + MAT_BYTES,      Al + go);
        cp16(s0 + MAT_BYTES + 16, Al + go + 8);
        if (BT) {
            const size_t gob = (size_t)(kb * 32 + lrB) * ldb + (size_t)lsB * 16;
            const uint32_t s0b = sb + buf * STAGE_BYTES + 2 * MAT_BYTES
                               + (uint32_t)lrB * RSB + (uint32_t)lsB * 32;
            cp16(s0b,      Bh + gob);
            cp16(s0b + 16, Bh + gob + 8);
        } else {
            const uint32_t s0b = sb + buf * STAGE_BYTES + 2 * MAT_BYTES + s_off;
            cp16(s0b,      Bh + go);
            cp16(s0b + 16, Bh + go + 8);
        }
    };

    const int KB = K / 32;
    issue(0, 0);
    asm volatile("cp.async.commit_group;" ::: "memory");
    issue(1, 1);
    asm volatile("cp.async.commit_group;" ::: "memory");

    const int wm = (wid & 1) * 64;
    const int wn = (wid >> 1) * 32;

    float acc[4][4][4];
    #pragma unroll
    for (int i = 0; i < 4; i++)
        #pragma unroll
        for (int j = 0; j < 4; j++)
            #pragma unroll
            for (int k = 0; k < 4; k++) acc[i][j][k] = 0.0f;

    const int rr = lane & 15;
    const int csel = lane >> 4;
    const int gB = lane >> 3;           // trans: matrix group 0..3
    const int rB = lane & 7;            // trans: row within matrix

    for (int kb = 0; kb < KB; kb++) {
        asm volatile("cp.async.wait_group 1;" ::: "memory");
        __syncthreads();
        const uint32_t bufb = sb + (kb & 1) * STAGE_BYTES;

        #pragma unroll
        for (int ks = 0; ks < 2; ks++) {
            const uint32_t coff = (uint32_t)(ks * 2 + csel) * 16;
            uint32_t ah[4][4], al[4][4], bh[4][2];
            const uint32_t abase = bufb + (uint32_t)(wm + rr) * RS + coff;
            #pragma unroll
            for (int mt = 0; mt < 4; mt++) {
                ldsm4(ah[mt], abase + mt * (16 * RS));
                ldsm4(al[mt], abase + mt * (16 * RS) + MAT_BYTES);
            }
            if (BT) {
                const uint32_t btb = bufb + 2 * MAT_BYTES
                    + (uint32_t)(ks * 16 + (gB & 1) * 8 + rB) * RSB
                    + (uint32_t)(wn + (gB >> 1) * 8) * 2;
                #pragma unroll
                for (int ntt = 0; ntt < 2; ntt++) {
                    uint32_t t4[4];
                    ldsm4t(t4, btb + ntt * 32);     // +16 n-cols = 32 bytes
                    bh[2 * ntt][0] = t4[0]; bh[2 * ntt][1] = t4[1];
                    bh[2 * ntt + 1][0] = t4[2]; bh[2 * ntt + 1][1] = t4[3];
                }
            } else {
                const uint32_t bbase = bufb + 2 * MAT_BYTES + (uint32_t)(wn + rr) * RS + coff;
                #pragma unroll
                for (int ntt = 0; ntt < 2; ntt++) {
                    uint32_t t4[4];
                    ldsm4(t4, bbase + ntt * (16 * RS));
                    bh[2 * ntt][0] = t4[0]; bh[2 * ntt][1] = t4[2];
                    bh[2 * ntt + 1][0] = t4[1]; bh[2 * ntt + 1][1] = t4[3];
                }
            }
            #pragma unroll
            for (int mt = 0; mt < 4; mt++)
                #pragma unroll
                for (int nt = 0; nt < 4; nt++) {
                    mma16816(acc[mt][nt], ah[mt], bh[nt]);
                    mma16816(acc[mt][nt], al[mt], bh[nt]);
                }
        }
        __syncthreads();
        if (kb + 2 < KB) issue(kb + 2, kb & 1);
        asm volatile("cp.async.commit_group;" ::: "memory");
    }

    // ======================= epilogue =======================
    const int qrow = lane >> 2;
    const int qcol = (lane & 3) * 2;
    float* redsm = (float*)smch;

    float rsum0[4], rsum1[4];

    #pragma unroll
    for (int mt = 0; mt < 4; mt++) {
        const int r0 = bm + wm + mt * 16 + qrow;
        const int r1 = r0 + 8;
        if (EPI == 2) { rsum0[mt] = 0.0f; rsum1[mt] = 0.0f; }
        #pragma unroll
        for (int nt = 0; nt < 4; nt++) {
            const int col = bn + wn + nt * 8 + qcol;
            float v00 = acc[mt][nt][0], v01 = acc[mt][nt][1];
            float v10 = acc[mt][nt][2], v11 = acc[mt][nt][3];

            if (EPI == 2) {
                const float* a0 = adj + ((size_t)z * Nn + r0) * Nn;
                const float* a1 = adj + ((size_t)z * Nn + r1) * Nn;
                float s00 = 1.0f / (1.0f + __expf(-v00));
                float s01 = 1.0f / (1.0f + __expf(-v01));
                float s10 = 1.0f / (1.0f + __expf(-v10));
                float s11 = 1.0f / (1.0f + __expf(-v11));
                v00 = (col == r0)     ? (s00 + 1e-5f) : s00 * __ldg(a0 + col);
                v01 = (col + 1 == r0) ? (s01 + 1e-5f) : s01 * __ldg(a0 + col + 1);
                v10 = (col == r1)     ? (s10 + 1e-5f) : s10 * __ldg(a1 + col);
                v11 = (col + 1 == r1) ? (s11 + 1e-5f) : s11 * __ldg(a1 + col + 1);
                rsum0[mt] += v00 + v01;
                rsum1[mt] += v10 + v11;
            } else if (EPI == 7) {
                const float4 p0 = *(const float4*)(part + ((size_t)z * Nn + r0) * 4);
                const float4 p1 = *(const float4*)(part + ((size_t)z * Nn + r1) * 4);
                const float inv0 = 1.0f / (p0.x + p0.y + p0.z + p0.w);
                const float inv1 = 1.0f / (p1.x + p1.y + p1.z + p1.w);
                v00 *= inv0; v01 *= inv0; v10 *= inv1; v11 *= inv1;
            } else if (EPI == 1) {
                const float b0v = __ldg(bias + col), b1v = __ldg(bias + col + 1);
                v00 += b0v; v01 += b1v; v10 += b0v; v11 += b1v;
            } else if (EPI == 4 || EPI == 5) {
                const float b0v = __ldg(bias + col), b1v = __ldg(bias + col + 1);
                v00 = fmaxf(v00 + b0v, 0.0f); v01 = fmaxf(v01 + b1v, 0.0f);
                v10 = fmaxf(v10 + b0v, 0.0f); v11 = fmaxf(v11 + b1v, 0.0f);
            }

            if (EPI == 6) {
                const float b0v = __ldg(bias + col), b1v = __ldg(bias + col + 1);
                float* cf0 = Cf + (size_t)z * sCz + (size_t)r0 * ldc;
                float* cf1 = Cf + (size_t)z * sCz + (size_t)r1 * ldc;
                float2 p0; p0.x = v00 + b0v; p0.y = v01 + b1v;
                float2 p1; p1.x = v10 + b0v; p1.y = v11 + b1v;
                *(float2*)(cf0 + col) = p0;
                *(float2*)(cf1 + col) = p1;
            } else {
                if (EPI == 5) {
                    const float* rp0 = res + (size_t)r0 * ldc;
                    const float* rp1 = res + (size_t)r1 * ldc;
                    v00 += rp0[col]; v01 += rp0[col + 1];
                    v10 += rp1[col]; v11 += rp1[col + 1];
                    float* cf0 = Cf + (size_t)r0 * ldc;
                    float* cf1 = Cf + (size_t)r1 * ldc;
                    float2 p0; p0.x = v00; p0.y = v01;
                    float2 p1; p1.x = v10; p1.y = v11;
                    *(float2*)(cf0 + col) = p0;
                    *(float2*)(cf1 + col) = p1;
                }
                __half* ch0 = Ch + (size_t)z * sCz + (size_t)r0 * ldc;
                __half* ch1 = Ch + (size_t)z * sCz + (size_t)r1 * ldc;
                __half* cl0 = Cl + (size_t)z * sCz + (size_t)r0 * ldc;
                __half* cl1 = Cl + (size_t)z * sCz + (size_t)r1 * ldc;
                const __half h00 = __float2half_rn(v00), h01 = __float2half_rn(v01);
                const __half h10 = __float2half_rn(v10), h11 = __float2half_rn(v11);
                __half2 hp0; hp0.x = h00; hp0.y = h01;
                __half2 hp1; hp1.x = h10; hp1.y = h11;
                *(__half2*)(ch0 + col) = hp0;
                *(__half2*)(ch1 + col) = hp1;
                __half2 lp0, lp1;
                lp0.x = __float2half_rn(v00 - __half2float(h00));
                lp0.y = __float2half_rn(v01 - __half2float(h01));
                lp1.x = __float2half_rn(v10 - __half2float(h10));
                lp1.y = __float2half_rn(v11 - __half2float(h11));
                *(__half2*)(cl0 + col) = lp0;
                *(__half2*)(cl1 + col) = lp1;
            }
        }
    }

    if (EPI == 2) {
        __syncthreads();
        const int nw = wid >> 1;
        #pragma unroll
        for (int mt = 0; mt < 4; mt++) {
            float s0 = rsum0[mt], s1 = rsum1[mt];
            s0 += __shfl_xor_sync(0xffffffffu, s0, 1);
            s0 += __shfl_xor_sync(0xffffffffu, s0, 2);
            s1 += __shfl_xor_sync(0xffffffffu, s1, 1);
            s1 += __shfl_xor_sync(0xffffffffu, s1, 2);
            if ((lane & 3) == 0) {
                const int rc = wm + mt * 16 + qrow;
                redsm[rc * 4 + nw]       = s0;
                redsm[(rc + 8) * 4 + nw] = s1;
            }
        }
        __syncthreads();
        if (tid < 128) {
            const float s = redsm[tid * 4] + redsm[tid * 4 + 1]
                          + redsm[tid * 4 + 2] + redsm[tid * 4 + 3];
            part[((size_t)z * Nn + bm + tid) * 4 + blockIdx.y] = s;
        }
    }
}

// ======================= small kernels =======================
__global__ void __launch_bounds__(256)
split_copy(const float4* __restrict__ src, float4* __restrict__ dst,
           __half* __restrict__ h, __half* __restrict__ l, int n4)
{
    const int i = blockIdx.x * blockDim.x + threadIdx.x;
    if (i >= n4) return;
    const float4 v = src[i];
    dst[i] = v;
    const float vv[4] = {v.x, v.y, v.z, v.w};
    __half hh[4], ll[4];
    #pragma unroll
    for (int k = 0; k < 4; k++) {
        hh[k] = __float2half_rn(vv[k]);
        ll[k] = __float2half_rn(vv[k] - __half2float(hh[k]));
    }
    __half2 a, b;
    a.x = hh[0]; a.y = hh[1]; b.x = hh[2]; b.y = hh[3];
    *(__half2*)(h + 4 * (size_t)i) = a;
    *(__half2*)(h + 4 * (size_t)i + 2) = b;
    a.x = ll[0]; a.y = ll[1]; b.x = ll[2]; b.y = ll[3];
    *(__half2*)(l + 4 * (size_t)i) = a;
    *(__half2*)(l + 4 * (size_t)i + 2) = b;
}

__global__ void __launch_bounds__(256)
wsplit(const float* __restrict__ src, __half* __restrict__ h,
       __half* __restrict__ l, int n)
{
    const int i = blockIdx.x * blockDim.x + threadIdx.x;
    if (i >= n) return;
    const float v = src[i];
    const __half hv = __float2half_rn(v);
    h[i] = hv;
    l[i] = __float2half_rn(v - __half2float(hv));
}

// write normalized fp32 attn from unnormalized hi/lo + rowsum partials
__global__ void __launch_bounds__(256)
normout(const __half* __restrict__ h, const __half* __restrict__ l,
        const float* __restrict__ part, float* __restrict__ out)
{
    const size_t row = blockIdx.x;
    const float4 p = *(const float4*)(part + row * 4);
    const float inv = 1.0f / (p.x + p.y + p.z + p.w);
    const int t = threadIdx.x;
    const __half2 hv = *(const __half2*)(h + row * Nn + t * 2);
    const __half2 lv = *(const __half2*)(l + row * Nn + t * 2);
    float2 o;
    o.x = (__half2float(hv.x) + __half2float(lv.x)) * inv;
    o.y = (__half2float(hv.y) + __half2float(lv.y)) * inv;
    *(float2*)(out + row * Nn + t * 2) = o;
}

// ======================= launch =======================
extern "C" void kernel_launch(void* const* d_in, const int* in_sizes, int n_in,
                              void* d_out, int out_size)
{
    const float* x_in  = (const float*)d_in[0];
    const float* adj   = (const float*)d_in[1];
    const float* wA_w  = (const float*)d_in[2];
    const float* wA_b  = (const float*)d_in[3];
    const float* l0_w  = (const float*)d_in[4];
    const float* l0_b  = (const float*)d_in[5];
    const float* l1_w  = (const float*)d_in[6];
    const float* l1_b  = (const float*)d_in[7];
    const float* fin_w = (const float*)d_in[8];
    const float* fin_b = (const float*)d_in[9];

    float* out_x = (float*)d_out;
    float* attls = out_x + (size_t)Bb * Nn * Dd;

    __half *xh, *xl, *th, *tl, *qh, *ql, *ah, *al, *wh, *wl;
    float *gx, *gp;
    cudaGetSymbolAddress((void**)&xh, g_xh); cudaGetSymbolAddress((void**)&xl, g_xl);
    cudaGetSymbolAddress((void**)&th, g_th); cudaGetSymbolAddress((void**)&tl, g_tl);
    cudaGetSymbolAddress((void**)&qh, g_qh); cudaGetSymbolAddress((void**)&ql, g_ql);
    cudaGetSymbolAddress((void**)&ah, g_ah); cudaGetSymbolAddress((void**)&al, g_al);
    cudaGetSymbolAddress((void**)&wh, g_wh); cudaGetSymbolAddress((void**)&wl, g_wl);
    cudaGetSymbolAddress((void**)&gx, g_x);  cudaGetSymbolAddress((void**)&gp, g_part);

    static cudaStream_t s2 = nullptr;
    static cudaEvent_t evRoot, evW, evF[Ll], evJ[Ll];
    if (s2 == nullptr) {
        cudaStreamCreateWithFlags(&s2, cudaStreamNonBlocking);
        cudaEventCreateWithFlags(&evRoot, cudaEventDisableTiming);
        cudaEventCreateWithFlags(&evW, cudaEventDisableTiming);
        for (int l = 0; l < Ll; l++) {
            cudaEventCreateWithFlags(&evF[l], cudaEventDisableTiming);
            cudaEventCreateWithFlags(&evJ[l], cudaEventDisableTiming);
        }
    }

    cudaFuncSetAttribute(mma_gemm<1,0>, cudaFuncAttributeMaxDynamicSharedMemorySize, GEMM_SMEM);
    cudaFuncSetAttribute(mma_gemm<2,0>, cudaFuncAttributeMaxDynamicSharedMemorySize, GEMM_SMEM);
    cudaFuncSetAttribute(mma_gemm<4,0>, cudaFuncAttributeMaxDynamicSharedMemorySize, GEMM_SMEM);
    cudaFuncSetAttribute(mma_gemm<5,0>, cudaFuncAttributeMaxDynamicSharedMemorySize, GEMM_SMEM);
    cudaFuncSetAttribute(mma_gemm<6,0>, cudaFuncAttributeMaxDynamicSharedMemorySize, GEMM_SMEM);
    cudaFuncSetAttribute(mma_gemm<7,1>, cudaFuncAttributeMaxDynamicSharedMemorySize, GEMM_SMEM);

    const int WSZ = Dd * Dd;
    const long long sX = (long long)Nn * Dd;
    const long long sA = (long long)Nn * Nn;

    // fork s2 at root: weight splits run concurrently with x split_copy
    cudaEventRecord(evRoot, 0);
    cudaStreamWaitEvent(s2, evRoot, 0);
    wsplit<<<(4 * WSZ + 255) / 256, 256, 0, s2>>>(wA_w,  wh,            wl,            4 * WSZ);
    wsplit<<<(4 * WSZ + 255) / 256, 256, 0, s2>>>(l0_w,  wh + 4 * WSZ,  wl + 4 * WSZ,  4 * WSZ);
    wsplit<<<(4 * WSZ + 255) / 256, 256, 0, s2>>>(l1_w,  wh + 8 * WSZ,  wl + 8 * WSZ,  4 * WSZ);
    wsplit<<<(WSZ + 255) / 256, 256, 0, s2>>>(fin_w, wh + 12 * WSZ, wl + 12 * WSZ, WSZ);
    cudaEventRecord(evW, s2);

    {
        const int n4 = XSZ / 4;
        split_copy<<<(n4 + 255) / 256, 256>>>((const float4*)x_in, (float4*)gx, xh, xl, n4);
    }
    cudaStreamWaitEvent(0, evW, 0);   // weights ready before first GEMM

    const int BIGM = Bb * Nn;
    for (int l = 0; l < Ll; l++) {
        const float* ba = wA_b + (size_t)l * Dd;
        const float* b0 = l0_b + (size_t)l * Dd;
        const float* b1 = l1_b + (size_t)l * Dd;
        const __half* Wah = wh + (size_t)l * WSZ;
        const __half* W0h = wh + (size_t)(4 + l) * WSZ;
        const __half* W1h = wh + (size_t)(8 + l) * WSZ;
        float* attl = attls + (size_t)l * Bb * Nn * Nn;

        // q = x @ Wa^T + ba  ->  qh/ql
        mma_gemm<1,0><<<dim3(BIGM / TM, Dd / TN, 1), 256, GEMM_SMEM>>>(
            xh, xl, Wah, Dd, 0, 0, 0,
            nullptr, qh, ql, 0, Dd, ba, nullptr, nullptr, nullptr);

        // previous layer's normout must be done before overwriting ah/al/gp
        if (l > 0) cudaStreamWaitEvent(0, evJ[l - 1], 0);

        // attn_unnorm = sig(q @ x^T)*adj (+diag) -> ah/al fp16 + rowsum partials
        mma_gemm<2,0><<<dim3(Nn / TM, Nn / TN, Bb), 256, GEMM_SMEM>>>(
            qh, ql, xh, Dd, 0, sX, sX,
            nullptr, ah, al, sA, Nn, nullptr, nullptr, adj, gp);

        // fork: normalized fp32 attn written on s2, overlapping the GEMMs below
        cudaEventRecord(evF[l], 0);
        cudaStreamWaitEvent(s2, evF[l], 0);
        normout<<<Bb * Nn, 256, 0, s2>>>(ah, al, gp, attl);
        cudaEventRecord(evJ[l], s2);

        // t1 = rowscale(attn_unnorm @ x)  (B = x row-major, trans-ldmatrix) -> qh/ql
        mma_gemm<7,1><<<dim3(Nn / TM, Dd / TN, Bb), 256, GEMM_SMEM>>>(
            ah, al, xh, Nn, Dd, sA, sX,
            nullptr, qh, ql, sX, Dd, nullptr, nullptr, nullptr, gp);

        // h = relu(t1 @ W0^T + b0) -> th/tl
        mma_gemm<4,0><<<dim3(BIGM / TM, Dd / TN, 1), 256, GEMM_SMEM>>>(
            qh, ql, W0h, Dd, 0, 0, 0,
            nullptr, th, tl, 0, Dd, b0, nullptr, nullptr, nullptr);

        // x = relu(h @ W1^T + b1) + x0 -> g_x (fp32) + xh/xl
        mma_gemm<5,0><<<dim3(BIGM / TM, Dd / TN, 1), 256, GEMM_SMEM>>>(
            th, tl, W1h, Dd, 0, 0, 0,
            gx, xh, xl, 0, Dd, b1, gx, nullptr, nullptr);
    }

    // join last normout before final GEMM closes the capture
    cudaStreamWaitEvent(0, evJ[Ll - 1], 0);

    // out = x @ final^T + b
    mma_gemm<6,0><<<dim3(BIGM / TM, Dd / TN, 1), 256, GEMM_SMEM>>>(
        xh, xl, wh + 12 * WSZ, Dd, 0, 0, 0,
        out_x, nullptr, nullptr, 0, Dd, fin_b, nullptr, nullptr, nullptr);
}

// round 9
// speedup vs baseline: 1.6644x; 1.0196x over previous
#include <cuda_runtime.h>
#include <cuda_fp16.h>
#include <cstdint>
#include <math.h>

#define Bb 64
#define Nn 512
#define Dd 256
#define Ll 4

// ======================= helpers =======================
__device__ __forceinline__ uint32_t smem_u32(const void* p) {
    uint32_t a;
    asm("{ .reg .u64 t; cvta.to.shared.u64 t, %1; cvt.u32.u64 %0, t; }" : "=r"(a) : "l"(p));
    return a;
}
__device__ __forceinline__ void cp16(uint32_t s, const void* g) {
    asm volatile("cp.async.cg.shared.global [%0], [%1], 16;" :: "r"(s), "l"(g));
}
__device__ __forceinline__ void ldsm4(uint32_t* r, uint32_t addr) {
    asm volatile("ldmatrix.sync.aligned.m8n8.x4.shared.b16 {%0,%1,%2,%3}, [%4];"
        : "=r"(r[0]), "=r"(r[1]), "=r"(r[2]), "=r"(r[3]) : "r"(addr));
}
__device__ __forceinline__ void ldsm4t(uint32_t* r, uint32_t addr) {
    asm volatile("ldmatrix.sync.aligned.m8n8.x4.trans.shared.b16 {%0,%1,%2,%3}, [%4];"
        : "=r"(r[0]), "=r"(r[1]), "=r"(r[2]), "=r"(r[3]) : "r"(addr));
}
__device__ __forceinline__ void mma16816(float* d, const uint32_t* a, const uint32_t* b) {
    asm volatile("mma.sync.aligned.m16n8k16.row.col.f32.f16.f16.f32 "
        "{%0,%1,%2,%3}, {%4,%5,%6,%7}, {%8,%9}, {%0,%1,%2,%3};"
        : "+f"(d[0]), "+f"(d[1]), "+f"(d[2]), "+f"(d[3])
        : "r"(a[0]), "r"(a[1]), "r"(a[2]), "r"(a[3]), "r"(b[0]), "r"(b[1]));
}

// ======================= device globals (scratch) =======================
#define XSZ (Bb * Nn * Dd)
#define ASZ (Bb * Nn * Nn)
__device__ __align__(128) __half g_xh[XSZ], g_xl[XSZ];
__device__ __align__(128) __half g_th[XSZ], g_tl[XSZ];   // lin0 output
__device__ __align__(128) __half g_qh[XSZ], g_ql[XSZ];   // q, then t1
__device__ __align__(128) __half g_ah[ASZ], g_al[ASZ];   // attn hi/lo (UNNORMALIZED)
__device__ __align__(128) __half g_wh[13 * Dd * Dd], g_wl[13 * Dd * Dd];
__device__ __align__(128) float g_x[XSZ];
__device__ __align__(128) float g_part[Bb * Nn * 4];     // row-sum partials (4 ctaY)

// ======================= MMA GEMM =======================
// BT=0: C = (Ah+Al)[M,K] @ (Bh[Ncols,K])^T       (both K-major)
// BT=1: C = (Ah+Al)[M,K] @ (Bh[K,Ncols])          (B row-major, trans-ldmatrix)
// EPI: 1=bias->hl | 2=sigmoid*adj->hl + rowsum partials | 4=relu(bias)->hl
//      5=relu(bias)+res->fp32+hl | 6=bias->fp32 | 7=rowscale(1/sum part)->hl
#define TM 128
#define TN 128
#define RS 80                           // padded smem row stride (A / non-trans B)
#define RSB 272                         // padded smem row stride (trans B: 256B rows)
#define MAT_BYTES (128 * RS)            // 10240
#define STAGE_BYTES (3 * MAT_BYTES)     // Ah, Al, B = 30720
#define NSTG 3
#define GEMM_SMEM (NSTG * STAGE_BYTES)  // 92160 -> 2 CTAs/SM

template<int EPI, int BT>
__global__ void __launch_bounds__(256, 2)
mma_gemm(const __half* __restrict__ Ah, const __half* __restrict__ Al,
         const __half* __restrict__ Bh,
         int K, int ldb, long long sAz, long long sBz,
         float* __restrict__ Cf, __half* __restrict__ Ch, __half* __restrict__ Cl,
         long long sCz, int ldc,
         const float* __restrict__ bias, const float* __restrict__ res,
         const float* __restrict__ adj, float* __restrict__ part)
{
    extern __shared__ char smch[];
    const uint32_t sb = smem_u32(smch);
    const int tid = threadIdx.x;
    const int wid = tid >> 5;
    const int lane = tid & 31;
    const int z = blockIdx.z;
    const int bm = blockIdx.x * TM;
    const int bn = blockIdx.y * TN;

    Ah += (size_t)z * sAz + (size_t)bm * K;
    Al += (size_t)z * sAz + (size_t)bm * K;
    if (BT) Bh += (size_t)z * sBz + bn;
    else    Bh += (size_t)z * sBz + (size_t)bn * K;

    // A loader: each thread one 32B segment of one of 128 rows
    const int lr = tid >> 1;
    const int lc = (tid & 1) * 2;
    const uint32_t s_off = (uint32_t)lr * RS + (uint32_t)lc * 16;
    // trans-B loader: 32 rows x 256B; each thread one 32B segment
    const int lrB = tid >> 3;
    const int lsB = tid & 7;

    auto issue = [&](int kb, int buf) {
        const size_t go = (size_t)lr * K + (size_t)kb * 32 + (size_t)lc * 8;
        const uint32_t s0 = sb + buf * STAGE_BYTES + s_off;
        cp16(s0,                  Ah + go);
        cp16(s0 + 16,             Ah + go + 8);
        cp16(s0 + MAT_BYTES,      Al + go);
        cp16(s0 + MAT_BYTES + 16, Al + go + 8);
        if (BT) {
            const size_t gob = (size_t)(kb * 32 + lrB) * ldb + (size_t)lsB * 16;
            const uint32_t s0b = sb + buf * STAGE_BYTES + 2 * MAT_BYTES
                               + (uint32_t)lrB * RSB + (uint32_t)lsB * 32;
            cp16(s0b,      Bh + gob);
            cp16(s0b + 16, Bh + gob + 8);
        } else {
            const uint32_t s0b = sb + buf * STAGE_BYTES + 2 * MAT_BYTES + s_off;
            cp16(s0b,      Bh + go);
            cp16(s0b + 16, Bh + go + 8);
        }
    };

    const int KB = K / 32;
    issue(0, 0);
    asm volatile("cp.async.commit_group;" ::: "memory");
    issue(1, 1);
    asm volatile("cp.async.commit_group;" ::: "memory");

    const int wm = (wid & 1) * 64;
    const int wn = (wid >> 1) * 32;

    float acc[4][4][4];
    #pragma unroll
    for (int i = 0; i < 4; i++)
        #pragma unroll
        for (int j = 0; j < 4; j++)
            #pragma unroll
            for (int k = 0; k < 4; k++) acc[i][j][k] = 0.0f;

    const int rr = lane & 15;
    const int csel = lane >> 4;
    const int gB = lane >> 3;           // trans: matrix group 0..3
    const int rB = lane & 7;            // trans: row within matrix

    int bufC = 0;                        // buffer being consumed (kb % 3)
    int bufW = 2;                        // buffer to write (kb+2) % 3
    for (int kb = 0; kb < KB; kb++) {
        asm volatile("cp.async.wait_group 1;" ::: "memory");
        __syncthreads();                 // ONLY barrier per iteration
        const uint32_t bufb = sb + bufC * STAGE_BYTES;

        // prefetch next-next stage into the buffer consumed at kb-1 (quiescent)
        if (kb + 2 < KB) issue(kb + 2, bufW);
        asm volatile("cp.async.commit_group;" ::: "memory");

        #pragma unroll
        for (int ks = 0; ks < 2; ks++) {
            const uint32_t coff = (uint32_t)(ks * 2 + csel) * 16;
            uint32_t ah[4][4], al[4][4], bh[4][2];
            const uint32_t abase = bufb + (uint32_t)(wm + rr) * RS + coff;
            #pragma unroll
            for (int mt = 0; mt < 4; mt++) {
                ldsm4(ah[mt], abase + mt * (16 * RS));
                ldsm4(al[mt], abase + mt * (16 * RS) + MAT_BYTES);
            }
            if (BT) {
                const uint32_t btb = bufb + 2 * MAT_BYTES
                    + (uint32_t)(ks * 16 + (gB & 1) * 8 + rB) * RSB
                    + (uint32_t)(wn + (gB >> 1) * 8) * 2;
                #pragma unroll
                for (int ntt = 0; ntt < 2; ntt++) {
                    uint32_t t4[4];
                    ldsm4t(t4, btb + ntt * 32);
                    bh[2 * ntt][0] = t4[0]; bh[2 * ntt][1] = t4[1];
                    bh[2 * ntt + 1][0] = t4[2]; bh[2 * ntt + 1][1] = t4[3];
                }
            } else {
                const uint32_t bbase = bufb + 2 * MAT_BYTES + (uint32_t)(wn + rr) * RS + coff;
                #pragma unroll
                for (int ntt = 0; ntt < 2; ntt++) {
                    uint32_t t4[4];
                    ldsm4(t4, bbase + ntt * (16 * RS));
                    bh[2 * ntt][0] = t4[0]; bh[2 * ntt][1] = t4[2];
                    bh[2 * ntt + 1][0] = t4[1]; bh[2 * ntt + 1][1] = t4[3];
                }
            }
            #pragma unroll
            for (int mt = 0; mt < 4; mt++)
                #pragma unroll
                for (int nt = 0; nt < 4; nt++) {
                    mma16816(acc[mt][nt], ah[mt], bh[nt]);
                    mma16816(acc[mt][nt], al[mt], bh[nt]);
                }
        }
        bufC = (bufC == NSTG - 1) ? 0 : bufC + 1;
        bufW = (bufW == NSTG - 1) ? 0 : bufW + 1;
    }

    // ======================= epilogue =======================
    const int qrow = lane >> 2;
    const int qcol = (lane & 3) * 2;
    float* redsm = (float*)smch;

    float rsum0[4], rsum1[4];

    #pragma unroll
    for (int mt = 0; mt < 4; mt++) {
        const int r0 = bm + wm + mt * 16 + qrow;
        const int r1 = r0 + 8;
        if (EPI == 2) { rsum0[mt] = 0.0f; rsum1[mt] = 0.0f; }
        #pragma unroll
        for (int nt = 0; nt < 4; nt++) {
            const int col = bn + wn + nt * 8 + qcol;
            float v00 = acc[mt][nt][0], v01 = acc[mt][nt][1];
            float v10 = acc[mt][nt][2], v11 = acc[mt][nt][3];

            if (EPI == 2) {
                const float* a0 = adj + ((size_t)z * Nn + r0) * Nn;
                const float* a1 = adj + ((size_t)z * Nn + r1) * Nn;
                float s00 = 1.0f / (1.0f + __expf(-v00));
                float s01 = 1.0f / (1.0f + __expf(-v01));
                float s10 = 1.0f / (1.0f + __expf(-v10));
                float s11 = 1.0f / (1.0f + __expf(-v11));
                v00 = (col == r0)     ? (s00 + 1e-5f) : s00 * __ldg(a0 + col);
                v01 = (col + 1 == r0) ? (s01 + 1e-5f) : s01 * __ldg(a0 + col + 1);
                v10 = (col == r1)     ? (s10 + 1e-5f) : s10 * __ldg(a1 + col);
                v11 = (col + 1 == r1) ? (s11 + 1e-5f) : s11 * __ldg(a1 + col + 1);
                rsum0[mt] += v00 + v01;
                rsum1[mt] += v10 + v11;
            } else if (EPI == 7) {
                const float4 p0 = *(const float4*)(part + ((size_t)z * Nn + r0) * 4);
                const float4 p1 = *(const float4*)(part + ((size_t)z * Nn + r1) * 4);
                const float inv0 = 1.0f / (p0.x + p0.y + p0.z + p0.w);
                const float inv1 = 1.0f / (p1.x + p1.y + p1.z + p1.w);
                v00 *= inv0; v01 *= inv0; v10 *= inv1; v11 *= inv1;
            } else if (EPI == 1) {
                const float b0v = __ldg(bias + col), b1v = __ldg(bias + col + 1);
                v00 += b0v; v01 += b1v; v10 += b0v; v11 += b1v;
            } else if (EPI == 4 || EPI == 5) {
                const float b0v = __ldg(bias + col), b1v = __ldg(bias + col + 1);
                v00 = fmaxf(v00 + b0v, 0.0f); v01 = fmaxf(v01 + b1v, 0.0f);
                v10 = fmaxf(v10 + b0v, 0.0f); v11 = fmaxf(v11 + b1v, 0.0f);
            }

            if (EPI == 6) {
                const float b0v = __ldg(bias + col), b1v = __ldg(bias + col + 1);
                float* cf0 = Cf + (size_t)z * sCz + (size_t)r0 * ldc;
                float* cf1 = Cf + (size_t)z * sCz + (size_t)r1 * ldc;
                float2 p0; p0.x = v00 + b0v; p0.y = v01 + b1v;
                float2 p1; p1.x = v10 + b0v; p1.y = v11 + b1v;
                *(float2*)(cf0 + col) = p0;
                *(float2*)(cf1 + col) = p1;
            } else {
                if (EPI == 5) {
                    const float* rp0 = res + (size_t)r0 * ldc;
                    const float* rp1 = res + (size_t)r1 * ldc;
                    v00 += rp0[col]; v01 += rp0[col + 1];
                    v10 += rp1[col]; v11 += rp1[col + 1];
                    float* cf0 = Cf + (size_t)r0 * ldc;
                    float* cf1 = Cf + (size_t)r1 * ldc;
                    float2 p0; p0.x = v00; p0.y = v01;
                    float2 p1; p1.x = v10; p1.y = v11;
                    *(float2*)(cf0 + col) = p0;
                    *(float2*)(cf1 + col) = p1;
                }
                __half* ch0 = Ch + (size_t)z * sCz + (size_t)r0 * ldc;
                __half* ch1 = Ch + (size_t)z * sCz + (size_t)r1 * ldc;
                __half* cl0 = Cl + (size_t)z * sCz + (size_t)r0 * ldc;
                __half* cl1 = Cl + (size_t)z * sCz + (size_t)r1 * ldc;
                const __half h00 = __float2half_rn(v00), h01 = __float2half_rn(v01);
                const __half h10 = __float2half_rn(v10), h11 = __float2half_rn(v11);
                __half2 hp0; hp0.x = h00; hp0.y = h01;
                __half2 hp1; hp1.x = h10; hp1.y = h11;
                *(__half2*)(ch0 + col) = hp0;
                *(__half2*)(ch1 + col) = hp1;
                __half2 lp0, lp1;
                lp0.x = __float2half_rn(v00 - __half2float(h00));
                lp0.y = __float2half_rn(v01 - __half2float(h01));
                lp1.x = __float2half_rn(v10 - __half2float(h10));
                lp1.y = __float2half_rn(v11 - __half2float(h11));
                *(__half2*)(cl0 + col) = lp0;
                *(__half2*)(cl1 + col) = lp1;
            }
        }
    }

    if (EPI == 2) {
        __syncthreads();
        const int nw = wid >> 1;
        #pragma unroll
        for (int mt = 0; mt < 4; mt++) {
            float s0 = rsum0[mt], s1 = rsum1[mt];
            s0 += __shfl_xor_sync(0xffffffffu, s0, 1);
            s0 += __shfl_xor_sync(0xffffffffu, s0, 2);
            s1 += __shfl_xor_sync(0xffffffffu, s1, 1);
            s1 += __shfl_xor_sync(0xffffffffu, s1, 2);
            if ((lane & 3) == 0) {
                const int rc = wm + mt * 16 + qrow;
                redsm[rc * 4 + nw]       = s0;
                redsm[(rc + 8) * 4 + nw] = s1;
            }
        }
        __syncthreads();
        if (tid < 128) {
            const float s = redsm[tid * 4] + redsm[tid * 4 + 1]
                          + redsm[tid * 4 + 2] + redsm[tid * 4 + 3];
            part[((size_t)z * Nn + bm + tid) * 4 + blockIdx.y] = s;
        }
    }
}

// ======================= small kernels =======================
__global__ void __launch_bounds__(256)
split_copy(const float4* __restrict__ src, float4* __restrict__ dst,
           __half* __restrict__ h, __half* __restrict__ l, int n4)
{
    const int i = blockIdx.x * blockDim.x + threadIdx.x;
    if (i >= n4) return;
    const float4 v = src[i];
    dst[i] = v;
    const float vv[4] = {v.x, v.y, v.z, v.w};
    __half hh[4], ll[4];
    #pragma unroll
    for (int k = 0; k < 4; k++) {
        hh[k] = __float2half_rn(vv[k]);
        ll[k] = __float2half_rn(vv[k] - __half2float(hh[k]));
    }
    __half2 a, b;
    a.x = hh[0]; a.y = hh[1]; b.x = hh[2]; b.y = hh[3];
    *(__half2*)(h + 4 * (size_t)i) = a;
    *(__half2*)(h + 4 * (size_t)i + 2) = b;
    a.x = ll[0]; a.y = ll[1]; b.x = ll[2]; b.y = ll[3];
    *(__half2*)(l + 4 * (size_t)i) = a;
    *(__half2*)(l + 4 * (size_t)i + 2) = b;
}

__global__ void __launch_bounds__(256)
wsplit(const float* __restrict__ src, __half* __restrict__ h,
       __half* __restrict__ l, int n)
{
    const int i = blockIdx.x * blockDim.x + threadIdx.x;
    if (i >= n) return;
    const float v = src[i];
    const __half hv = __float2half_rn(v);
    h[i] = hv;
    l[i] = __float2half_rn(v - __half2float(hv));
}

// write normalized fp32 attn from unnormalized hi/lo + rowsum partials
__global__ void __launch_bounds__(256)
normout(const __half* __restrict__ h, const __half* __restrict__ l,
        const float* __restrict__ part, float* __restrict__ out)
{
    const size_t row = blockIdx.x;
    const float4 p = *(const float4*)(part + row * 4);
    const float inv = 1.0f / (p.x + p.y + p.z + p.w);
    const int t = threadIdx.x;
    const __half2 hv = *(const __half2*)(h + row * Nn + t * 2);
    const __half2 lv = *(const __half2*)(l + row * Nn + t * 2);
    float2 o;
    o.x = (__half2float(hv.x) + __half2float(lv.x)) * inv;
    o.y = (__half2float(hv.y) + __half2float(lv.y)) * inv;
    *(float2*)(out + row * Nn + t * 2) = o;
}

// ======================= launch =======================
extern "C" void kernel_launch(void* const* d_in, const int* in_sizes, int n_in,
                              void* d_out, int out_size)
{
    const float* x_in  = (const float*)d_in[0];
    const float* adj   = (const float*)d_in[1];
    const float* wA_w  = (const float*)d_in[2];
    const float* wA_b  = (const float*)d_in[3];
    const float* l0_w  = (const float*)d_in[4];
    const float* l0_b  = (const float*)d_in[5];
    const float* l1_w  = (const float*)d_in[6];
    const float* l1_b  = (const float*)d_in[7];
    const float* fin_w = (const float*)d_in[8];
    const float* fin_b = (const float*)d_in[9];

    float* out_x = (float*)d_out;
    float* attls = out_x + (size_t)Bb * Nn * Dd;

    __half *xh, *xl, *th, *tl, *qh, *ql, *ah, *al, *wh, *wl;
    float *gx, *gp;
    cudaGetSymbolAddress((void**)&xh, g_xh); cudaGetSymbolAddress((void**)&xl, g_xl);
    cudaGetSymbolAddress((void**)&th, g_th); cudaGetSymbolAddress((void**)&tl, g_tl);
    cudaGetSymbolAddress((void**)&qh, g_qh); cudaGetSymbolAddress((void**)&ql, g_ql);
    cudaGetSymbolAddress((void**)&ah, g_ah); cudaGetSymbolAddress((void**)&al, g_al);
    cudaGetSymbolAddress((void**)&wh, g_wh); cudaGetSymbolAddress((void**)&wl, g_wl);
    cudaGetSymbolAddress((void**)&gx, g_x);  cudaGetSymbolAddress((void**)&gp, g_part);

    static cudaStream_t s2 = nullptr;
    static cudaEvent_t evRoot, evW, evF[Ll], evJ[Ll];
    if (s2 == nullptr) {
        cudaStreamCreateWithFlags(&s2, cudaStreamNonBlocking);
        cudaEventCreateWithFlags(&evRoot, cudaEventDisableTiming);
        cudaEventCreateWithFlags(&evW, cudaEventDisableTiming);
        for (int l = 0; l < Ll; l++) {
            cudaEventCreateWithFlags(&evF[l], cudaEventDisableTiming);
            cudaEventCreateWithFlags(&evJ[l], cudaEventDisableTiming);
        }
    }

    cudaFuncSetAttribute(mma_gemm<1,0>, cudaFuncAttributeMaxDynamicSharedMemorySize, GEMM_SMEM);
    cudaFuncSetAttribute(mma_gemm<2,0>, cudaFuncAttributeMaxDynamicSharedMemorySize, GEMM_SMEM);
    cudaFuncSetAttribute(mma_gemm<4,0>, cudaFuncAttributeMaxDynamicSharedMemorySize, GEMM_SMEM);
    cudaFuncSetAttribute(mma_gemm<5,0>, cudaFuncAttributeMaxDynamicSharedMemorySize, GEMM_SMEM);
    cudaFuncSetAttribute(mma_gemm<6,0>, cudaFuncAttributeMaxDynamicSharedMemorySize, GEMM_SMEM);
    cudaFuncSetAttribute(mma_gemm<7,1>, cudaFuncAttributeMaxDynamicSharedMemorySize, GEMM_SMEM);

    const int WSZ = Dd * Dd;
    const long long sX = (long long)Nn * Dd;
    const long long sA = (long long)Nn * Nn;

    // fork s2 at root: weight splits run concurrently with x split_copy
    cudaEventRecord(evRoot, 0);
    cudaStreamWaitEvent(s2, evRoot, 0);
    wsplit<<<(4 * WSZ + 255) / 256, 256, 0, s2>>>(wA_w,  wh,            wl,            4 * WSZ);
    wsplit<<<(4 * WSZ + 255) / 256, 256, 0, s2>>>(l0_w,  wh + 4 * WSZ,  wl + 4 * WSZ,  4 * WSZ);
    wsplit<<<(4 * WSZ + 255) / 256, 256, 0, s2>>>(l1_w,  wh + 8 * WSZ,  wl + 8 * WSZ,  4 * WSZ);
    wsplit<<<(WSZ + 255) / 256, 256, 0, s2>>>(fin_w, wh + 12 * WSZ, wl + 12 * WSZ, WSZ);
    cudaEventRecord(evW, s2);

    {
        const int n4 = XSZ / 4;
        split_copy<<<(n4 + 255) / 256, 256>>>((const float4*)x_in, (float4*)gx, xh, xl, n4);
    }
    cudaStreamWaitEvent(0, evW, 0);   // weights ready before first GEMM

    const int BIGM = Bb * Nn;
    for (int l = 0; l < Ll; l++) {
        const float* ba = wA_b + (size_t)l * Dd;
        const float* b0 = l0_b + (size_t)l * Dd;
        const float* b1 = l1_b + (size_t)l * Dd;
        const __half* Wah = wh + (size_t)l * WSZ;
        const __half* W0h = wh + (size_t)(4 + l) * WSZ;
        const __half* W1h = wh + (size_t)(8 + l) * WSZ;
        float* attl = attls + (size_t)l * Bb * Nn * Nn;

        // q = x @ Wa^T + ba  ->  qh/ql
        mma_gemm<1,0><<<dim3(BIGM / TM, Dd / TN, 1), 256, GEMM_SMEM>>>(
            xh, xl, Wah, Dd, 0, 0, 0,
            nullptr, qh, ql, 0, Dd, ba, nullptr, nullptr, nullptr);

        // previous layer's normout must be done before overwriting ah/al/gp
        if (l > 0) cudaStreamWaitEvent(0, evJ[l - 1], 0);

        // attn_unnorm = sig(q @ x^T)*adj (+diag) -> ah/al fp16 + rowsum partials
        mma_gemm<2,0><<<dim3(Nn / TM, Nn / TN, Bb), 256, GEMM_SMEM>>>(
            qh, ql, xh, Dd, 0, sX, sX,
            nullptr, ah, al, sA, Nn, nullptr, nullptr, adj, gp);

        // fork: normalized fp32 attn written on s2, overlapping the GEMMs below
        cudaEventRecord(evF[l], 0);
        cudaStreamWaitEvent(s2, evF[l], 0);
        normout<<<Bb * Nn, 256, 0, s2>>>(ah, al, gp, attl);
        cudaEventRecord(evJ[l], s2);

        // t1 = rowscale(attn_unnorm @ x)  (B = x row-major, trans-ldmatrix) -> qh/ql
        mma_gemm<7,1><<<dim3(Nn / TM, Dd / TN, Bb), 256, GEMM_SMEM>>>(
            ah, al, xh, Nn, Dd, sA, sX,
            nullptr, qh, ql, sX, Dd, nullptr, nullptr, nullptr, gp);

        // h = relu(t1 @ W0^T + b0) -> th/tl
        mma_gemm<4,0><<<dim3(BIGM / TM, Dd / TN, 1), 256, GEMM_SMEM>>>(
            qh, ql, W0h, Dd, 0, 0, 0,
            nullptr, th, tl, 0, Dd, b0, nullptr, nullptr, nullptr);

        // x = relu(h @ W1^T + b1) + x0 -> g_x (fp32) + xh/xl
        mma_gemm<5,0><<<dim3(BIGM / TM, Dd / TN, 1), 256, GEMM_SMEM>>>(
            th, tl, W1h, Dd, 0, 0, 0,
            gx, xh, xl, 0, Dd, b1, gx, nullptr, nullptr);
    }

    // join last normout before final GEMM closes the capture
    cudaStreamWaitEvent(0, evJ[Ll - 1], 0);

    // out = x @ final^T + b
    mma_gemm<6,0><<<dim3(BIGM / TM, Dd / TN, 1), 256, GEMM_SMEM>>>(
        xh, xl, wh + 12 * WSZ, Dd, 0, 0, 0,
        out_x, nullptr, nullptr, 0, Dd, fin_b, nullptr, nullptr, nullptr);
}

// round 10
// speedup vs baseline: 2.0313x; 1.2204x over previous
#include <cuda_runtime.h>
#include <cuda_fp16.h>
#include <cstdint>
#include <math.h>

#define Bb 64
#define Nn 512
#define Dd 256
#define Ll 4

// ======================= helpers =======================
__device__ __forceinline__ uint32_t smem_u32(const void* p) {
    uint32_t a;
    asm("{ .reg .u64 t; cvta.to.shared.u64 t, %1; cvt.u32.u64 %0, t; }" : "=r"(a) : "l"(p));
    return a;
}
__device__ __forceinline__ void cp16(uint32_t s, const void* g) {
    asm volatile("cp.async.cg.shared.global [%0], [%1], 16;" :: "r"(s), "l"(g));
}
__device__ __forceinline__ void ldsm4(uint32_t* r, uint32_t addr) {
    asm volatile("ldmatrix.sync.aligned.m8n8.x4.shared.b16 {%0,%1,%2,%3}, [%4];"
        : "=r"(r[0]), "=r"(r[1]), "=r"(r[2]), "=r"(r[3]) : "r"(addr));
}
__device__ __forceinline__ void ldsm4t(uint32_t* r, uint32_t addr) {
    asm volatile("ldmatrix.sync.aligned.m8n8.x4.trans.shared.b16 {%0,%1,%2,%3}, [%4];"
        : "=r"(r[0]), "=r"(r[1]), "=r"(r[2]), "=r"(r[3]) : "r"(addr));
}
__device__ __forceinline__ void mma16816(float* d, const uint32_t* a, const uint32_t* b) {
    asm volatile("mma.sync.aligned.m16n8k16.row.col.f32.f16.f16.f32 "
        "{%0,%1,%2,%3}, {%4,%5,%6,%7}, {%8,%9}, {%0,%1,%2,%3};"
        : "+f"(d[0]), "+f"(d[1]), "+f"(d[2]), "+f"(d[3])
        : "r"(a[0]), "r"(a[1]), "r"(a[2]), "r"(a[3]), "r"(b[0]), "r"(b[1]));
}

// ======================= device globals (scratch) =======================
#define XSZ (Bb * Nn * Dd)
#define ASZ (Bb * Nn * Nn)
__device__ __align__(128) __half g_xh[XSZ];
__device__ __align__(128) __half g_th[XSZ];              // lin0 output (single)
__device__ __align__(128) __half g_qh[XSZ], g_ql[XSZ];   // q hi/lo, then t1 (hi only)
__device__ __align__(128) __half g_ah[ASZ], g_al[ASZ];   // attn hi/lo (UNNORMALIZED)
__device__ __align__(128) __half g_wh[13 * Dd * Dd];
__device__ __align__(128) float g_x[XSZ];
__device__ __align__(128) float g_part[Bb * Nn * 4];     // row-sum partials (4 ctaY)

// ======================= MMA GEMM =======================
// BT=0: C = A[M,K] @ (Bh[Ncols,K])^T ; BT=1: C = A[M,K] @ (Bh[K,Ncols]) (trans-ldsm)
// PROD=2: A = Ah + Al (2 MMA products) ; PROD=1: A = Ah (single product)
// EPI: 1=bias->hl | 2=sigmoid*adj->hl + rowsum partials | 4=relu(bias)->h
//      5=relu(bias)+res->fp32+h | 6=bias->fp32 | 7=rowscale(1/sum part)->h
#define TM 128
#define TN 128
#define RS 80
#define RSB 272
#define MAT_BYTES (128 * RS)            // 10240
#define NSTG 3

template<int EPI, int BT, int PROD>
__global__ void __launch_bounds__(256, 2)
mma_gemm(const __half* __restrict__ Ah, const __half* __restrict__ Al,
         const __half* __restrict__ Bh,
         int K, int ldb, long long sAz, long long sBz,
         float* __restrict__ Cf, __half* __restrict__ Ch, __half* __restrict__ Cl,
         long long sCz, int ldc,
         const float* __restrict__ bias, const float* __restrict__ res,
         const float* __restrict__ adj, float* __restrict__ part)
{
    constexpr int STG = (PROD + 1) * MAT_BYTES;    // Ah [,Al], B
    constexpr uint32_t B_OFF = PROD * MAT_BYTES;
    constexpr bool WRITE_L = (EPI == 1 || EPI == 2);

    extern __shared__ char smch[];
    const uint32_t sb = smem_u32(smch);
    const int tid = threadIdx.x;
    const int wid = tid >> 5;
    const int lane = tid & 31;
    const int z = blockIdx.z;
    const int bm = blockIdx.x * TM;
    const int bn = blockIdx.y * TN;

    Ah += (size_t)z * sAz + (size_t)bm * K;
    if (PROD == 2) Al += (size_t)z * sAz + (size_t)bm * K;
    if (BT) Bh += (size_t)z * sBz + bn;
    else    Bh += (size_t)z * sBz + (size_t)bn * K;

    const int lr = tid >> 1;
    const int lc = (tid & 1) * 2;
    const uint32_t s_off = (uint32_t)lr * RS + (uint32_t)lc * 16;
    const int lrB = tid >> 3;
    const int lsB = tid & 7;

    auto issue = [&](int kb, int buf) {
        const size_t go = (size_t)lr * K + (size_t)kb * 32 + (size_t)lc * 8;
        const uint32_t s0 = sb + buf * STG + s_off;
        cp16(s0,      Ah + go);
        cp16(s0 + 16, Ah + go + 8);
        if (PROD == 2) {
            cp16(s0 + MAT_BYTES,      Al + go);
            cp16(s0 + MAT_BYTES + 16, Al + go + 8);
        }
        if (BT) {
            const size_t gob = (size_t)(kb * 32 + lrB) * ldb + (size_t)lsB * 16;
            const uint32_t s0b = sb + buf * STG + B_OFF
                               + (uint32_t)lrB * RSB + (uint32_t)lsB * 32;
            cp16(s0b,      Bh + gob);
            cp16(s0b + 16, Bh + gob + 8);
        } else {
            const uint32_t s0b = sb + buf * STG + B_OFF + s_off;
            cp16(s0b,      Bh + go);
            cp16(s0b + 16, Bh + go + 8);
        }
    };

    const int KB = K / 32;
    issue(0, 0);
    asm volatile("cp.async.commit_group;" ::: "memory");
    issue(1, 1);
    asm volatile("cp.async.commit_group;" ::: "memory");

    const int wm = (wid & 1) * 64;
    const int wn = (wid >> 1) * 32;

    float acc[4][4][4];
    #pragma unroll
    for (int i = 0; i < 4; i++)
        #pragma unroll
        for (int j = 0; j < 4; j++)
            #pragma unroll
            for (int k = 0; k < 4; k++) acc[i][j][k] = 0.0f;

    const int rr = lane & 15;
    const int csel = lane >> 4;
    const int gB = lane >> 3;
    const int rB = lane & 7;

    int bufC = 0, bufW = 2;
    for (int kb = 0; kb < KB; kb++) {
        asm volatile("cp.async.wait_group 1;" ::: "memory");
        __syncthreads();
        const uint32_t bufb = sb + bufC * STG;

        if (kb + 2 < KB) issue(kb + 2, bufW);
        asm volatile("cp.async.commit_group;" ::: "memory");

        #pragma unroll
        for (int ks = 0; ks < 2; ks++) {
            const uint32_t coff = (uint32_t)(ks * 2 + csel) * 16;
            uint32_t ah[4][4], al[4][4], bh[4][2];
            const uint32_t abase = bufb + (uint32_t)(wm + rr) * RS + coff;
            #pragma unroll
            for (int mt = 0; mt < 4; mt++) {
                ldsm4(ah[mt], abase + mt * (16 * RS));
                if (PROD == 2) ldsm4(al[mt], abase + mt * (16 * RS) + MAT_BYTES);
            }
            if (BT) {
                const uint32_t btb = bufb + B_OFF
                    + (uint32_t)(ks * 16 + (gB & 1) * 8 + rB) * RSB
                    + (uint32_t)(wn + (gB >> 1) * 8) * 2;
                #pragma unroll
                for (int ntt = 0; ntt < 2; ntt++) {
                    uint32_t t4[4];
                    ldsm4t(t4, btb + ntt * 32);
                    bh[2 * ntt][0] = t4[0]; bh[2 * ntt][1] = t4[1];
                    bh[2 * ntt + 1][0] = t4[2]; bh[2 * ntt + 1][1] = t4[3];
                }
            } else {
                const uint32_t bbase = bufb + B_OFF + (uint32_t)(wn + rr) * RS + coff;
                #pragma unroll
                for (int ntt = 0; ntt < 2; ntt++) {
                    uint32_t t4[4];
                    ldsm4(t4, bbase + ntt * (16 * RS));
                    bh[2 * ntt][0] = t4[0]; bh[2 * ntt][1] = t4[2];
                    bh[2 * ntt + 1][0] = t4[1]; bh[2 * ntt + 1][1] = t4[3];
                }
            }
            #pragma unroll
            for (int mt = 0; mt < 4; mt++)
                #pragma unroll
                for (int nt = 0; nt < 4; nt++) {
                    mma16816(acc[mt][nt], ah[mt], bh[nt]);
                    if (PROD == 2) mma16816(acc[mt][nt], al[mt], bh[nt]);
                }
        }
        bufC = (bufC == NSTG - 1) ? 0 : bufC + 1;
        bufW = (bufW == NSTG - 1) ? 0 : bufW + 1;
    }

    // ======================= epilogue =======================
    const int qrow = lane >> 2;
    const int qcol = (lane & 3) * 2;
    float* redsm = (float*)smch;

    float rsum0[4], rsum1[4];

    #pragma unroll
    for (int mt = 0; mt < 4; mt++) {
        const int r0 = bm + wm + mt * 16 + qrow;
        const int r1 = r0 + 8;
        if (EPI == 2) { rsum0[mt] = 0.0f; rsum1[mt] = 0.0f; }
        #pragma unroll
        for (int nt = 0; nt < 4; nt++) {
            const int col = bn + wn + nt * 8 + qcol;
            float v00 = acc[mt][nt][0], v01 = acc[mt][nt][1];
            float v10 = acc[mt][nt][2], v11 = acc[mt][nt][3];

            if (EPI == 2) {
                const float* a0 = adj + ((size_t)z * Nn + r0) * Nn;
                const float* a1 = adj + ((size_t)z * Nn + r1) * Nn;
                float s00 = 1.0f / (1.0f + __expf(-v00));
                float s01 = 1.0f / (1.0f + __expf(-v01));
                float s10 = 1.0f / (1.0f + __expf(-v10));
                float s11 = 1.0f / (1.0f + __expf(-v11));
                v00 = (col == r0)     ? (s00 + 1e-5f) : s00 * __ldg(a0 + col);
                v01 = (col + 1 == r0) ? (s01 + 1e-5f) : s01 * __ldg(a0 + col + 1);
                v10 = (col == r1)     ? (s10 + 1e-5f) : s10 * __ldg(a1 + col);
                v11 = (col + 1 == r1) ? (s11 + 1e-5f) : s11 * __ldg(a1 + col + 1);
                rsum0[mt] += v00 + v01;
                rsum1[mt] += v10 + v11;
            } else if (EPI == 7) {
                const float4 p0 = *(const float4*)(part + ((size_t)z * Nn + r0) * 4);
                const float4 p1 = *(const float4*)(part + ((size_t)z * Nn + r1) * 4);
                const float inv0 = 1.0f / (p0.x + p0.y + p0.z + p0.w);
                const float inv1 = 1.0f / (p1.x + p1.y + p1.z + p1.w);
                v00 *= inv0; v01 *= inv0; v10 *= inv1; v11 *= inv1;
            } else if (EPI == 1) {
                const float b0v = __ldg(bias + col), b1v = __ldg(bias + col + 1);
                v00 += b0v; v01 += b1v; v10 += b0v; v11 += b1v;
            } else if (EPI == 4 || EPI == 5) {
                const float b0v = __ldg(bias + col), b1v = __ldg(bias + col + 1);
                v00 = fmaxf(v00 + b0v, 0.0f); v01 = fmaxf(v01 + b1v, 0.0f);
                v10 = fmaxf(v10 + b0v, 0.0f); v11 = fmaxf(v11 + b1v, 0.0f);
            }

            if (EPI == 6) {
                const float b0v = __ldg(bias + col), b1v = __ldg(bias + col + 1);
                float* cf0 = Cf + (size_t)z * sCz + (size_t)r0 * ldc;
                float* cf1 = Cf + (size_t)z * sCz + (size_t)r1 * ldc;
                float2 p0; p0.x = v00 + b0v; p0.y = v01 + b1v;
                float2 p1; p1.x = v10 + b0v; p1.y = v11 + b1v;
                *(float2*)(cf0 + col) = p0;
                *(float2*)(cf1 + col) = p1;
            } else {
                if (EPI == 5) {
                    const float* rp0 = res + (size_t)r0 * ldc;
                    const float* rp1 = res + (size_t)r1 * ldc;
                    v00 += rp0[col]; v01 += rp0[col + 1];
                    v10 += rp1[col]; v11 += rp1[col + 1];
                    float* cf0 = Cf + (size_t)r0 * ldc;
                    float* cf1 = Cf + (size_t)r1 * ldc;
                    float2 p0; p0.x = v00; p0.y = v01;
                    float2 p1; p1.x = v10; p1.y = v11;
                    *(float2*)(cf0 + col) = p0;
                    *(float2*)(cf1 + col) = p1;
                }
                __half* ch0 = Ch + (size_t)z * sCz + (size_t)r0 * ldc;
                __half* ch1 = Ch + (size_t)z * sCz + (size_t)r1 * ldc;
                const __half h00 = __float2half_rn(v00), h01 = __float2half_rn(v01);
                const __half h10 = __float2half_rn(v10), h11 = __float2half_rn(v11);
                __half2 hp0; hp0.x = h00; hp0.y = h01;
                __half2 hp1; hp1.x = h10; hp1.y = h11;
                *(__half2*)(ch0 + col) = hp0;
                *(__half2*)(ch1 + col) = hp1;
                if (WRITE_L) {
                    __half* cl0 = Cl + (size_t)z * sCz + (size_t)r0 * ldc;
                    __half* cl1 = Cl + (size_t)z * sCz + (size_t)r1 * ldc;
                    __half2 lp0, lp1;
                    lp0.x = __float2half_rn(v00 - __half2float(h00));
                    lp0.y = __float2half_rn(v01 - __half2float(h01));
                    lp1.x = __float2half_rn(v10 - __half2float(h10));
                    lp1.y = __float2half_rn(v11 - __half2float(h11));
                    *(__half2*)(cl0 + col) = lp0;
                    *(__half2*)(cl1 + col) = lp1;
                }
            }
        }
    }

    if (EPI == 2) {
        __syncthreads();
        const int nw = wid >> 1;
        #pragma unroll
        for (int mt = 0; mt < 4; mt++) {
            float s0 = rsum0[mt], s1 = rsum1[mt];
            s0 += __shfl_xor_sync(0xffffffffu, s0, 1);
            s0 += __shfl_xor_sync(0xffffffffu, s0, 2);
            s1 += __shfl_xor_sync(0xffffffffu, s1, 1);
            s1 += __shfl_xor_sync(0xffffffffu, s1, 2);
            if ((lane & 3) == 0) {
                const int rc = wm + mt * 16 + qrow;
                redsm[rc * 4 + nw]       = s0;
                redsm[(rc + 8) * 4 + nw] = s1;
            }
        }
        __syncthreads();
        if (tid < 128) {
            const float s = redsm[tid * 4] + redsm[tid * 4 + 1]
                          + redsm[tid * 4 + 2] + redsm[tid * 4 + 3];
            part[((size_t)z * Nn + bm + tid) * 4 + blockIdx.y] = s;
        }
    }
}

// ======================= small kernels =======================
__global__ void __launch_bounds__(256)
split_copy(const float4* __restrict__ src, float4* __restrict__ dst,
           __half* __restrict__ h, int n4)
{
    const int i = blockIdx.x * blockDim.x + threadIdx.x;
    if (i >= n4) return;
    const float4 v = src[i];
    dst[i] = v;
    __half2 a, b;
    a.x = __float2half_rn(v.x); a.y = __float2half_rn(v.y);
    b.x = __float2half_rn(v.z); b.y = __float2half_rn(v.w);
    *(__half2*)(h + 4 * (size_t)i) = a;
    *(__half2*)(h + 4 * (size_t)i + 2) = b;
}

__global__ void __launch_bounds__(256)
wconv(const float* __restrict__ src, __half* __restrict__ h, int n)
{
    const int i = blockIdx.x * blockDim.x + threadIdx.x;
    if (i < n) h[i] = __float2half_rn(src[i]);
}

// write normalized fp32 attn from unnormalized hi/lo + rowsum partials
__global__ void __launch_bounds__(256)
normout(const __half* __restrict__ h, const __half* __restrict__ l,
        const float* __restrict__ part, float* __restrict__ out)
{
    const size_t row = blockIdx.x;
    const float4 p = *(const float4*)(part + row * 4);
    const float inv = 1.0f / (p.x + p.y + p.z + p.w);
    const int t = threadIdx.x;
    const __half2 hv = *(const __half2*)(h + row * Nn + t * 2);
    const __half2 lv = *(const __half2*)(l + row * Nn + t * 2);
    float2 o;
    o.x = (__half2float(hv.x) + __half2float(lv.x)) * inv;
    o.y = (__half2float(hv.y) + __half2float(lv.y)) * inv;
    *(float2*)(out + row * Nn + t * 2) = o;
}

// ======================= launch =======================
#define SMEM_P2 (NSTG * 3 * MAT_BYTES)   // 92160
#define SMEM_P1 (NSTG * 2 * MAT_BYTES)   // 61440

extern "C" void kernel_launch(void* const* d_in, const int* in_sizes, int n_in,
                              void* d_out, int out_size)
{
    const float* x_in  = (const float*)d_in[0];
    const float* adj   = (const float*)d_in[1];
    const float* wA_w  = (const float*)d_in[2];
    const float* wA_b  = (const float*)d_in[3];
    const float* l0_w  = (const float*)d_in[4];
    const float* l0_b  = (const float*)d_in[5];
    const float* l1_w  = (const float*)d_in[6];
    const float* l1_b  = (const float*)d_in[7];
    const float* fin_w = (const float*)d_in[8];
    const float* fin_b = (const float*)d_in[9];

    float* out_x = (float*)d_out;
    float* attls = out_x + (size_t)Bb * Nn * Dd;

    __half *xh, *th, *qh, *ql, *ah, *al, *wh;
    float *gx, *gp;
    cudaGetSymbolAddress((void**)&xh, g_xh);
    cudaGetSymbolAddress((void**)&th, g_th);
    cudaGetSymbolAddress((void**)&qh, g_qh); cudaGetSymbolAddress((void**)&ql, g_ql);
    cudaGetSymbolAddress((void**)&ah, g_ah); cudaGetSymbolAddress((void**)&al, g_al);
    cudaGetSymbolAddress((void**)&wh, g_wh);
    cudaGetSymbolAddress((void**)&gx, g_x);  cudaGetSymbolAddress((void**)&gp, g_part);

    static cudaStream_t s2 = nullptr;
    static cudaEvent_t evRoot, evW, evF[Ll], evJ[Ll];
    if (s2 == nullptr) {
        cudaStreamCreateWithFlags(&s2, cudaStreamNonBlocking);
        cudaEventCreateWithFlags(&evRoot, cudaEventDisableTiming);
        cudaEventCreateWithFlags(&evW, cudaEventDisableTiming);
        for (int l = 0; l < Ll; l++) {
            cudaEventCreateWithFlags(&evF[l], cudaEventDisableTiming);
            cudaEventCreateWithFlags(&evJ[l], cudaEventDisableTiming);
        }
    }

    cudaFuncSetAttribute(mma_gemm<1,0,1>, cudaFuncAttributeMaxDynamicSharedMemorySize, SMEM_P1);
    cudaFuncSetAttribute(mma_gemm<2,0,2>, cudaFuncAttributeMaxDynamicSharedMemorySize, SMEM_P2);
    cudaFuncSetAttribute(mma_gemm<4,0,1>, cudaFuncAttributeMaxDynamicSharedMemorySize, SMEM_P1);
    cudaFuncSetAttribute(mma_gemm<5,0,1>, cudaFuncAttributeMaxDynamicSharedMemorySize, SMEM_P1);
    cudaFuncSetAttribute(mma_gemm<6,0,1>, cudaFuncAttributeMaxDynamicSharedMemorySize, SMEM_P1);
    cudaFuncSetAttribute(mma_gemm<7,1,2>, cudaFuncAttributeMaxDynamicSharedMemorySize, SMEM_P2);

    const int WSZ = Dd * Dd;
    const long long sX = (long long)Nn * Dd;
    const long long sA = (long long)Nn * Nn;

    // fork s2 at root: weight converts run concurrently with x split_copy
    cudaEventRecord(evRoot, 0);
    cudaStreamWaitEvent(s2, evRoot, 0);
    wconv<<<(4 * WSZ + 255) / 256, 256, 0, s2>>>(wA_w,  wh,            4 * WSZ);
    wconv<<<(4 * WSZ + 255) / 256, 256, 0, s2>>>(l0_w,  wh + 4 * WSZ,  4 * WSZ);
    wconv<<<(4 * WSZ + 255) / 256, 256, 0, s2>>>(l1_w,  wh + 8 * WSZ,  4 * WSZ);
    wconv<<<(WSZ + 255) / 256, 256, 0, s2>>>(fin_w, wh + 12 * WSZ, WSZ);
    cudaEventRecord(evW, s2);

    {
        const int n4 = XSZ / 4;
        split_copy<<<(n4 + 255) / 256, 256>>>((const float4*)x_in, (float4*)gx, xh, n4);
    }
    cudaStreamWaitEvent(0, evW, 0);

    const int BIGM = Bb * Nn;
    for (int l = 0; l < Ll; l++) {
        const float* ba = wA_b + (size_t)l * Dd;
        const float* b0 = l0_b + (size_t)l * Dd;
        const float* b1 = l1_b + (size_t)l * Dd;
        const __half* Wah = wh + (size_t)l * WSZ;
        const __half* W0h = wh + (size_t)(4 + l) * WSZ;
        const __half* W1h = wh + (size_t)(8 + l) * WSZ;
        float* attl = attls + (size_t)l * Bb * Nn * Nn;

        // q = x @ Wa^T + ba  (A = xh single)  ->  qh/ql (hi/lo kept for EPI2)
        mma_gemm<1,0,1><<<dim3(BIGM / TM, Dd / TN, 1), 256, SMEM_P1>>>(
            xh, nullptr, Wah, Dd, 0, 0, 0,
            nullptr, qh, ql, 0, Dd, ba, nullptr, nullptr, nullptr);

        if (l > 0) cudaStreamWaitEvent(0, evJ[l - 1], 0);

        // attn_unnorm = sig(q @ x^T)*adj (+diag)  (A = q hi/lo) -> ah/al + partials
        mma_gemm<2,0,2><<<dim3(Nn / TM, Nn / TN, Bb), 256, SMEM_P2>>>(
            qh, ql, xh, Dd, 0, sX, sX,
            nullptr, ah, al, sA, Nn, nullptr, nullptr, adj, gp);

        cudaEventRecord(evF[l], 0);
        cudaStreamWaitEvent(s2, evF[l], 0);
        normout<<<Bb * Nn, 256, 0, s2>>>(ah, al, gp, attl);
        cudaEventRecord(evJ[l], s2);

        // t1 = rowscale(attn_unnorm @ x)  (A = attn hi/lo, B trans) -> qh (hi only)
        mma_gemm<7,1,2><<<dim3(Nn / TM, Dd / TN, Bb), 256, SMEM_P2>>>(
            ah, al, xh, Nn, Dd, sA, sX,
            nullptr, qh, nullptr, sX, Dd, nullptr, nullptr, nullptr, gp);

        // h = relu(t1 @ W0^T + b0)  (A = t1 single) -> th
        mma_gemm<4,0,1><<<dim3(BIGM / TM, Dd / TN, 1), 256, SMEM_P1>>>(
            qh, nullptr, W0h, Dd, 0, 0, 0,
            nullptr, th, nullptr, 0, Dd, b0, nullptr, nullptr, nullptr);

        // x = relu(h @ W1^T + b1) + x0  (A = h single) -> g_x fp32 + xh
        mma_gemm<5,0,1><<<dim3(BIGM / TM, Dd / TN, 1), 256, SMEM_P1>>>(
            th, nullptr, W1h, Dd, 0, 0, 0,
            gx, xh, nullptr, 0, Dd, b1, gx, nullptr, nullptr);
    }

    cudaStreamWaitEvent(0, evJ[Ll - 1], 0);

    // out = x @ final^T + b  (A = xh single)
    mma_gemm<6,0,1><<<dim3(BIGM / TM, Dd / TN, 1), 256, SMEM_P1>>>(
        xh, nullptr, wh + 12 * WSZ, Dd, 0, 0, 0,
        out_x, nullptr, nullptr, 0, Dd, fin_b, nullptr, nullptr, nullptr);
}

// round 11
// speedup vs baseline: 2.1913x; 1.0788x over previous
#include <cuda_runtime.h>
#include <cuda_fp16.h>
#include <cstdint>
#include <math.h>

#define Bb 64
#define Nn 512
#define Dd 256
#define Ll 4

// ======================= helpers =======================
__device__ __forceinline__ uint32_t smem_u32(const void* p) {
    uint32_t a;
    asm("{ .reg .u64 t; cvta.to.shared.u64 t, %1; cvt.u32.u64 %0, t; }" : "=r"(a) : "l"(p));
    return a;
}
__device__ __forceinline__ void cp16(uint32_t s, const void* g) {
    asm volatile("cp.async.cg.shared.global [%0], [%1], 16;" :: "r"(s), "l"(g));
}
__device__ __forceinline__ void ldsm4(uint32_t* r, uint32_t addr) {
    asm volatile("ldmatrix.sync.aligned.m8n8.x4.shared.b16 {%0,%1,%2,%3}, [%4];"
        : "=r"(r[0]), "=r"(r[1]), "=r"(r[2]), "=r"(r[3]) : "r"(addr));
}
__device__ __forceinline__ void ldsm4t(uint32_t* r, uint32_t addr) {
    asm volatile("ldmatrix.sync.aligned.m8n8.x4.trans.shared.b16 {%0,%1,%2,%3}, [%4];"
        : "=r"(r[0]), "=r"(r[1]), "=r"(r[2]), "=r"(r[3]) : "r"(addr));
}
__device__ __forceinline__ void mma16816(float* d, const uint32_t* a, const uint32_t* b) {
    asm volatile("mma.sync.aligned.m16n8k16.row.col.f32.f16.f16.f32 "
        "{%0,%1,%2,%3}, {%4,%5,%6,%7}, {%8,%9}, {%0,%1,%2,%3};"
        : "+f"(d[0]), "+f"(d[1]), "+f"(d[2]), "+f"(d[3])
        : "r"(a[0]), "r"(a[1]), "r"(a[2]), "r"(a[3]), "r"(b[0]), "r"(b[1]));
}

// ======================= device globals (scratch) =======================
#define XSZ (Bb * Nn * Dd)
#define ASZ (Bb * Nn * Nn)
__device__ __align__(128) __half g_xh[XSZ];
__device__ __align__(128) __half g_th[XSZ];              // lin0 output (single)
__device__ __align__(128) __half g_qh[XSZ], g_ql[XSZ];   // q hi/lo, then t1 (hi only)
__device__ __align__(128) __half g_ah[ASZ], g_al[ASZ];   // attn hi/lo (UNNORMALIZED)
__device__ __align__(128) __half g_wh[13 * Dd * Dd];
__device__ __align__(128) float g_x[XSZ];
__device__ __align__(128) float g_part[Bb * Nn * 4];     // row-sum partials (4 ctaY)

// ======================= MMA GEMM =======================
// BT=0: C = A[M,K] @ (Bh[Ncols,K])^T ; BT=1: C = A[M,K] @ (Bh[K,Ncols]) (trans-ldsm)
// PROD=2: A = Ah + Al (2 MMA products) ; PROD=1: A = Ah (single product)
// EPI: 1=bias->hl | 2=sigmoid*adj->hl + rowsum partials | 4=relu(bias)->h
//      5=relu(bias)+res->fp32+h | 6=bias->fp32 | 7=rowscale(1/sum part)->h
#define TM 128
#define TN 128
#define RS 80
#define RSB 272
#define MAT_BYTES (128 * RS)            // 10240
#define NSTG 3

template<int EPI, int BT, int PROD>
__global__ void __launch_bounds__(256, 2)
mma_gemm(const __half* __restrict__ Ah, const __half* __restrict__ Al,
         const __half* __restrict__ Bh,
         int K, int ldb, long long sAz, long long sBz,
         float* __restrict__ Cf, __half* __restrict__ Ch, __half* __restrict__ Cl,
         long long sCz, int ldc,
         const float* __restrict__ bias, const float* __restrict__ res,
         const float* __restrict__ adj, float* __restrict__ part)
{
    constexpr int STG = (PROD + 1) * MAT_BYTES;    // Ah [,Al], B
    constexpr uint32_t B_OFF = PROD * MAT_BYTES;
    constexpr bool WRITE_L = (EPI == 1 || EPI == 2);

    extern __shared__ char smch[];
    const uint32_t sb = smem_u32(smch);
    const int tid = threadIdx.x;
    const int wid = tid >> 5;
    const int lane = tid & 31;
    const int z = blockIdx.z;
    const int bm = blockIdx.x * TM;
    const int bn = blockIdx.y * TN;

    Ah += (size_t)z * sAz + (size_t)bm * K;
    if (PROD == 2) Al += (size_t)z * sAz + (size_t)bm * K;
    if (BT) Bh += (size_t)z * sBz + bn;
    else    Bh += (size_t)z * sBz + (size_t)bn * K;

    const int lr = tid >> 1;
    const int lc = (tid & 1) * 2;
    const uint32_t s_off = (uint32_t)lr * RS + (uint32_t)lc * 16;
    const int lrB = tid >> 3;
    const int lsB = tid & 7;

    auto issue = [&](int kb, int buf) {
        const size_t go = (size_t)lr * K + (size_t)kb * 32 + (size_t)lc * 8;
        const uint32_t s0 = sb + buf * STG + s_off;
        cp16(s0,      Ah + go);
        cp16(s0 + 16, Ah + go + 8);
        if (PROD == 2) {
            cp16(s0 + MAT_BYTES,      Al + go);
            cp16(s0 + MAT_BYTES + 16, Al + go + 8);
        }
        if (BT) {
            const size_t gob = (size_t)(kb * 32 + lrB) * ldb + (size_t)lsB * 16;
            const uint32_t s0b = sb + buf * STG + B_OFF
                               + (uint32_t)lrB * RSB + (uint32_t)lsB * 32;
            cp16(s0b,      Bh + gob);
            cp16(s0b + 16, Bh + gob + 8);
        } else {
            const uint32_t s0b = sb + buf * STG + B_OFF + s_off;
            cp16(s0b,      Bh + go);
            cp16(s0b + 16, Bh + go + 8);
        }
    };

    const int KB = K / 32;
    issue(0, 0);
    asm volatile("cp.async.commit_group;" ::: "memory");
    issue(1, 1);
    asm volatile("cp.async.commit_group;" ::: "memory");

    const int wm = (wid & 1) * 64;
    const int wn = (wid >> 1) * 32;

    float acc[4][4][4];
    #pragma unroll
    for (int i = 0; i < 4; i++)
        #pragma unroll
        for (int j = 0; j < 4; j++)
            #pragma unroll
            for (int k = 0; k < 4; k++) acc[i][j][k] = 0.0f;

    const int rr = lane & 15;
    const int csel = lane >> 4;
    const int gB = lane >> 3;
    const int rB = lane & 7;

    int bufC = 0, bufW = 2;
    for (int kb = 0; kb < KB; kb++) {
        asm volatile("cp.async.wait_group 1;" ::: "memory");
        __syncthreads();
        const uint32_t bufb = sb + bufC * STG;

        if (kb + 2 < KB) issue(kb + 2, bufW);
        asm volatile("cp.async.commit_group;" ::: "memory");

        #pragma unroll
        for (int ks = 0; ks < 2; ks++) {
            const uint32_t coff = (uint32_t)(ks * 2 + csel) * 16;
            uint32_t ah[4][4], al[4][4], bh[4][2];
            const uint32_t abase = bufb + (uint32_t)(wm + rr) * RS + coff;
            #pragma unroll
            for (int mt = 0; mt < 4; mt++) {
                ldsm4(ah[mt], abase + mt * (16 * RS));
                if (PROD == 2) ldsm4(al[mt], abase + mt * (16 * RS) + MAT_BYTES);
            }
            if (BT) {
                const uint32_t btb = bufb + B_OFF
                    + (uint32_t)(ks * 16 + (gB & 1) * 8 + rB) * RSB
                    + (uint32_t)(wn + (gB >> 1) * 8) * 2;
                #pragma unroll
                for (int ntt = 0; ntt < 2; ntt++) {
                    uint32_t t4[4];
                    ldsm4t(t4, btb + ntt * 32);
                    bh[2 * ntt][0] = t4[0]; bh[2 * ntt][1] = t4[1];
                    bh[2 * ntt + 1][0] = t4[2]; bh[2 * ntt + 1][1] = t4[3];
                }
            } else {
                const uint32_t bbase = bufb + B_OFF + (uint32_t)(wn + rr) * RS + coff;
                #pragma unroll
                for (int ntt = 0; ntt < 2; ntt++) {
                    uint32_t t4[4];
                    ldsm4(t4, bbase + ntt * (16 * RS));
                    bh[2 * ntt][0] = t4[0]; bh[2 * ntt][1] = t4[2];
                    bh[2 * ntt + 1][0] = t4[1]; bh[2 * ntt + 1][1] = t4[3];
                }
            }
            #pragma unroll
            for (int mt = 0; mt < 4; mt++)
                #pragma unroll
                for (int nt = 0; nt < 4; nt++) {
                    mma16816(acc[mt][nt], ah[mt], bh[nt]);
                    if (PROD == 2) mma16816(acc[mt][nt], al[mt], bh[nt]);
                }
        }
        bufC = (bufC == NSTG - 1) ? 0 : bufC + 1;
        bufW = (bufW == NSTG - 1) ? 0 : bufW + 1;
    }

    // ======================= epilogue =======================
    const int qrow = lane >> 2;
    const int qcol = (lane & 3) * 2;
    float* redsm = (float*)smch;

    float rsum0[4], rsum1[4];

    #pragma unroll
    for (int mt = 0; mt < 4; mt++) {
        const int r0 = bm + wm + mt * 16 + qrow;
        const int r1 = r0 + 8;
        if (EPI == 2) { rsum0[mt] = 0.0f; rsum1[mt] = 0.0f; }
        #pragma unroll
        for (int nt = 0; nt < 4; nt++) {
            const int col = bn + wn + nt * 8 + qcol;
            float v00 = acc[mt][nt][0], v01 = acc[mt][nt][1];
            float v10 = acc[mt][nt][2], v11 = acc[mt][nt][3];

            if (EPI == 2) {
                const float* a0 = adj + ((size_t)z * Nn + r0) * Nn;
                const float* a1 = adj + ((size_t)z * Nn + r1) * Nn;
                float s00 = 1.0f / (1.0f + __expf(-v00));
                float s01 = 1.0f / (1.0f + __expf(-v01));
                float s10 = 1.0f / (1.0f + __expf(-v10));
                float s11 = 1.0f / (1.0f + __expf(-v11));
                v00 = (col == r0)     ? (s00 + 1e-5f) : s00 * __ldg(a0 + col);
                v01 = (col + 1 == r0) ? (s01 + 1e-5f) : s01 * __ldg(a0 + col + 1);
                v10 = (col == r1)     ? (s10 + 1e-5f) : s10 * __ldg(a1 + col);
                v11 = (col + 1 == r1) ? (s11 + 1e-5f) : s11 * __ldg(a1 + col + 1);
                rsum0[mt] += v00 + v01;
                rsum1[mt] += v10 + v11;
            } else if (EPI == 7) {
                const float4 p0 = *(const float4*)(part + ((size_t)z * Nn + r0) * 4);
                const float4 p1 = *(const float4*)(part + ((size_t)z * Nn + r1) * 4);
                const float inv0 = 1.0f / (p0.x + p0.y + p0.z + p0.w);
                const float inv1 = 1.0f / (p1.x + p1.y + p1.z + p1.w);
                v00 *= inv0; v01 *= inv0; v10 *= inv1; v11 *= inv1;
            } else if (EPI == 1) {
                const float b0v = __ldg(bias + col), b1v = __ldg(bias + col + 1);
                v00 += b0v; v01 += b1v; v10 += b0v; v11 += b1v;
            } else if (EPI == 4 || EPI == 5) {
                const float b0v = __ldg(bias + col), b1v = __ldg(bias + col + 1);
                v00 = fmaxf(v00 + b0v, 0.0f); v01 = fmaxf(v01 + b1v, 0.0f);
                v10 = fmaxf(v10 + b0v, 0.0f); v11 = fmaxf(v11 + b1v, 0.0f);
            }

            if (EPI == 6) {
                const float b0v = __ldg(bias + col), b1v = __ldg(bias + col + 1);
                float* cf0 = Cf + (size_t)z * sCz + (size_t)r0 * ldc;
                float* cf1 = Cf + (size_t)z * sCz + (size_t)r1 * ldc;
                float2 p0; p0.x = v00 + b0v; p0.y = v01 + b1v;
                float2 p1; p1.x = v10 + b0v; p1.y = v11 + b1v;
                *(float2*)(cf0 + col) = p0;
                *(float2*)(cf1 + col) = p1;
            } else {
                if (EPI == 5) {
                    const float* rp0 = res + (size_t)r0 * ldc;
                    const float* rp1 = res + (size_t)r1 * ldc;
                    v00 += rp0[col]; v01 += rp0[col + 1];
                    v10 += rp1[col]; v11 += rp1[col + 1];
                    float* cf0 = Cf + (size_t)r0 * ldc;
                    float* cf1 = Cf + (size_t)r1 * ldc;
                    float2 p0; p0.x = v00; p0.y = v01;
                    float2 p1; p1.x = v10; p1.y = v11;
                    *(float2*)(cf0 + col) = p0;
                    *(float2*)(cf1 + col) = p1;
                }
                __half* ch0 = Ch + (size_t)z * sCz + (size_t)r0 * ldc;
                __half* ch1 = Ch + (size_t)z * sCz + (size_t)r1 * ldc;
                const __half h00 = __float2half_rn(v00), h01 = __float2half_rn(v01);
                const __half h10 = __float2half_rn(v10), h11 = __float2half_rn(v11);
                __half2 hp0; hp0.x = h00; hp0.y = h01;
                __half2 hp1; hp1.x = h10; hp1.y = h11;
                *(__half2*)(ch0 + col) = hp0;
                *(__half2*)(ch1 + col) = hp1;
                if (WRITE_L) {
                    __half* cl0 = Cl + (size_t)z * sCz + (size_t)r0 * ldc;
                    __half* cl1 = Cl + (size_t)z * sCz + (size_t)r1 * ldc;
                    __half2 lp0, lp1;
                    lp0.x = __float2half_rn(v00 - __half2float(h00));
                    lp0.y = __float2half_rn(v01 - __half2float(h01));
                    lp1.x = __float2half_rn(v10 - __half2float(h10));
                    lp1.y = __float2half_rn(v11 - __half2float(h11));
                    *(__half2*)(cl0 + col) = lp0;
                    *(__half2*)(cl1 + col) = lp1;
                }
            }
        }
    }

    if (EPI == 2) {
        __syncthreads();
        const int nw = wid >> 1;
        #pragma unroll
        for (int mt = 0; mt < 4; mt++) {
            float s0 = rsum0[mt], s1 = rsum1[mt];
            s0 += __shfl_xor_sync(0xffffffffu, s0, 1);
            s0 += __shfl_xor_sync(0xffffffffu, s0, 2);
            s1 += __shfl_xor_sync(0xffffffffu, s1, 1);
            s1 += __shfl_xor_sync(0xffffffffu, s1, 2);
            if ((lane & 3) == 0) {
                const int rc = wm + mt * 16 + qrow;
                redsm[rc * 4 + nw]       = s0;
                redsm[(rc + 8) * 4 + nw] = s1;
            }
        }
        __syncthreads();
        if (tid < 128) {
            const float s = redsm[tid * 4] + redsm[tid * 4 + 1]
                          + redsm[tid * 4 + 2] + redsm[tid * 4 + 3];
            part[((size_t)z * Nn + bm + tid) * 4 + blockIdx.y] = s;
        }
    }
}

// ======================= small kernels =======================
__global__ void __launch_bounds__(256)
split_copy(const float4* __restrict__ src, float4* __restrict__ dst,
           __half* __restrict__ h, int n4)
{
    const int i = blockIdx.x * blockDim.x + threadIdx.x;
    if (i >= n4) return;
    const float4 v = src[i];
    dst[i] = v;
    __half2 a, b;
    a.x = __float2half_rn(v.x); a.y = __float2half_rn(v.y);
    b.x = __float2half_rn(v.z); b.y = __float2half_rn(v.w);
    *(__half2*)(h + 4 * (size_t)i) = a;
    *(__half2*)(h + 4 * (size_t)i + 2) = b;
}

__global__ void __launch_bounds__(256)
wconv(const float* __restrict__ src, __half* __restrict__ h, int n)
{
    const int i = blockIdx.x * blockDim.x + threadIdx.x;
    if (i < n) h[i] = __float2half_rn(src[i]);
}

// write normalized fp32 attn from unnormalized hi/lo + rowsum partials
__global__ void __launch_bounds__(256)
normout(const __half* __restrict__ h, const __half* __restrict__ l,
        const float* __restrict__ part, float* __restrict__ out)
{
    const size_t row = blockIdx.x;
    const float4 p = *(const float4*)(part + row * 4);
    const float inv = 1.0f / (p.x + p.y + p.z + p.w);
    const int t = threadIdx.x;
    const __half2 hv = *(const __half2*)(h + row * Nn + t * 2);
    const __half2 lv = *(const __half2*)(l + row * Nn + t * 2);
    float2 o;
    o.x = (__half2float(hv.x) + __half2float(lv.x)) * inv;
    o.y = (__half2float(hv.y) + __half2float(lv.y)) * inv;
    *(float2*)(out + row * Nn + t * 2) = o;
}

// ======================= launch =======================
#define SMEM_P2 (NSTG * 3 * MAT_BYTES)   // 92160
#define SMEM_P1 (NSTG * 2 * MAT_BYTES)   // 61440

extern "C" void kernel_launch(void* const* d_in, const int* in_sizes, int n_in,
                              void* d_out, int out_size)
{
    const float* x_in  = (const float*)d_in[0];
    const float* adj   = (const float*)d_in[1];
    const float* wA_w  = (const float*)d_in[2];
    const float* wA_b  = (const float*)d_in[3];
    const float* l0_w  = (const float*)d_in[4];
    const float* l0_b  = (const float*)d_in[5];
    const float* l1_w  = (const float*)d_in[6];
    const float* l1_b  = (const float*)d_in[7];
    const float* fin_w = (const float*)d_in[8];
    const float* fin_b = (const float*)d_in[9];

    float* out_x = (float*)d_out;
    float* attls = out_x + (size_t)Bb * Nn * Dd;

    __half *xh, *th, *qh, *ql, *ah, *al, *wh;
    float *gx, *gp;
    cudaGetSymbolAddress((void**)&xh, g_xh);
    cudaGetSymbolAddress((void**)&th, g_th);
    cudaGetSymbolAddress((void**)&qh, g_qh); cudaGetSymbolAddress((void**)&ql, g_ql);
    cudaGetSymbolAddress((void**)&ah, g_ah); cudaGetSymbolAddress((void**)&al, g_al);
    cudaGetSymbolAddress((void**)&wh, g_wh);
    cudaGetSymbolAddress((void**)&gx, g_x);  cudaGetSymbolAddress((void**)&gp, g_part);

    static cudaStream_t s2 = nullptr;
    static cudaEvent_t evRoot, evW, evF[Ll], evJ[Ll];
    if (s2 == nullptr) {
        cudaStreamCreateWithFlags(&s2, cudaStreamNonBlocking);
        cudaEventCreateWithFlags(&evRoot, cudaEventDisableTiming);
        cudaEventCreateWithFlags(&evW, cudaEventDisableTiming);
        for (int l = 0; l < Ll; l++) {
            cudaEventCreateWithFlags(&evF[l], cudaEventDisableTiming);
            cudaEventCreateWithFlags(&evJ[l], cudaEventDisableTiming);
        }
    }

    cudaFuncSetAttribute(mma_gemm<1,0,1>, cudaFuncAttributeMaxDynamicSharedMemorySize, SMEM_P1);
    cudaFuncSetAttribute(mma_gemm<2,0,2>, cudaFuncAttributeMaxDynamicSharedMemorySize, SMEM_P2);
    cudaFuncSetAttribute(mma_gemm<4,0,1>, cudaFuncAttributeMaxDynamicSharedMemorySize, SMEM_P1);
    cudaFuncSetAttribute(mma_gemm<5,0,1>, cudaFuncAttributeMaxDynamicSharedMemorySize, SMEM_P1);
    cudaFuncSetAttribute(mma_gemm<6,0,1>, cudaFuncAttributeMaxDynamicSharedMemorySize, SMEM_P1);
    cudaFuncSetAttribute(mma_gemm<7,1,1>, cudaFuncAttributeMaxDynamicSharedMemorySize, SMEM_P1);

    const int WSZ = Dd * Dd;
    const long long sX = (long long)Nn * Dd;
    const long long sA = (long long)Nn * Nn;

    // fork s2 at root: weight converts run concurrently with x split_copy
    cudaEventRecord(evRoot, 0);
    cudaStreamWaitEvent(s2, evRoot, 0);
    wconv<<<(4 * WSZ + 255) / 256, 256, 0, s2>>>(wA_w,  wh,            4 * WSZ);
    wconv<<<(4 * WSZ + 255) / 256, 256, 0, s2>>>(l0_w,  wh + 4 * WSZ,  4 * WSZ);
    wconv<<<(4 * WSZ + 255) / 256, 256, 0, s2>>>(l1_w,  wh + 8 * WSZ,  4 * WSZ);
    wconv<<<(WSZ + 255) / 256, 256, 0, s2>>>(fin_w, wh + 12 * WSZ, WSZ);
    cudaEventRecord(evW, s2);

    {
        const int n4 = XSZ / 4;
        split_copy<<<(n4 + 255) / 256, 256>>>((const float4*)x_in, (float4*)gx, xh, n4);
    }
    cudaStreamWaitEvent(0, evW, 0);

    const int BIGM = Bb * Nn;
    for (int l = 0; l < Ll; l++) {
        const float* ba = wA_b + (size_t)l * Dd;
        const float* b0 = l0_b + (size_t)l * Dd;
        const float* b1 = l1_b + (size_t)l * Dd;
        const __half* Wah = wh + (size_t)l * WSZ;
        const __half* W0h = wh + (size_t)(4 + l) * WSZ;
        const __half* W1h = wh + (size_t)(8 + l) * WSZ;
        float* attl = attls + (size_t)l * Bb * Nn * Nn;

        // q = x @ Wa^T + ba  (A = xh single)  ->  qh/ql (hi/lo kept for EPI2)
        mma_gemm<1,0,1><<<dim3(BIGM / TM, Dd / TN, 1), 256, SMEM_P1>>>(
            xh, nullptr, Wah, Dd, 0, 0, 0,
            nullptr, qh, ql, 0, Dd, ba, nullptr, nullptr, nullptr);

        if (l > 0) cudaStreamWaitEvent(0, evJ[l - 1], 0);

        // attn_unnorm = sig(q @ x^T)*adj (+diag)  (A = q hi/lo) -> ah/al + partials
        mma_gemm<2,0,2><<<dim3(Nn / TM, Nn / TN, Bb), 256, SMEM_P2>>>(
            qh, ql, xh, Dd, 0, sX, sX,
            nullptr, ah, al, sA, Nn, nullptr, nullptr, adj, gp);

        cudaEventRecord(evF[l], 0);
        cudaStreamWaitEvent(s2, evF[l], 0);
        normout<<<Bb * Nn, 256, 0, s2>>>(ah, al, gp, attl);
        cudaEventRecord(evJ[l], s2);

        // t1 = rowscale(attn_unnorm @ x)  (A = attn HI only, B trans) -> qh (hi only)
        mma_gemm<7,1,1><<<dim3(Nn / TM, Dd / TN, Bb), 256, SMEM_P1>>>(
            ah, nullptr, xh, Nn, Dd, sA, sX,
            nullptr, qh, nullptr, sX, Dd, nullptr, nullptr, nullptr, gp);

        // h = relu(t1 @ W0^T + b0)  (A = t1 single) -> th
        mma_gemm<4,0,1><<<dim3(BIGM / TM, Dd / TN, 1), 256, SMEM_P1>>>(
            qh, nullptr, W0h, Dd, 0, 0, 0,
            nullptr, th, nullptr, 0, Dd, b0, nullptr, nullptr, nullptr);

        // x = relu(h @ W1^T + b1) + x0  (A = h single) -> g_x fp32 + xh
        mma_gemm<5,0,1><<<dim3(BIGM / TM, Dd / TN, 1), 256, SMEM_P1>>>(
            th, nullptr, W1h, Dd, 0, 0, 0,
            gx, xh, nullptr, 0, Dd, b1, gx, nullptr, nullptr);
    }

    cudaStreamWaitEvent(0, evJ[Ll - 1], 0);

    // out = x @ final^T + b  (A = xh single)
    mma_gemm<6,0,1><<<dim3(BIGM / TM, Dd / TN, 1), 256, SMEM_P1>>>(
        xh, nullptr, wh + 12 * WSZ, Dd, 0, 0, 0,
        out_x, nullptr, nullptr, 0, Dd, fin_b, nullptr, nullptr, nullptr);
}

// round 12
// speedup vs baseline: 2.4299x; 1.1089x over previous
#include <cuda_runtime.h>
#include <cuda_fp16.h>
#include <cstdint>
#include <math.h>

#define Bb 64
#define Nn 512
#define Dd 256
#define Ll 4

// ======================= helpers =======================
__device__ __forceinline__ uint32_t smem_u32(const void* p) {
    uint32_t a;
    asm("{ .reg .u64 t; cvta.to.shared.u64 t, %1; cvt.u32.u64 %0, t; }" : "=r"(a) : "l"(p));
    return a;
}
__device__ __forceinline__ void cp16(uint32_t s, const void* g) {
    asm volatile("cp.async.cg.shared.global [%0], [%1], 16;" :: "r"(s), "l"(g));
}
__device__ __forceinline__ void ldsm4(uint32_t* r, uint32_t addr) {
    asm volatile("ldmatrix.sync.aligned.m8n8.x4.shared.b16 {%0,%1,%2,%3}, [%4];"
        : "=r"(r[0]), "=r"(r[1]), "=r"(r[2]), "=r"(r[3]) : "r"(addr));
}
__device__ __forceinline__ void ldsm4t(uint32_t* r, uint32_t addr) {
    asm volatile("ldmatrix.sync.aligned.m8n8.x4.trans.shared.b16 {%0,%1,%2,%3}, [%4];"
        : "=r"(r[0]), "=r"(r[1]), "=r"(r[2]), "=r"(r[3]) : "r"(addr));
}
__device__ __forceinline__ void mma16816(float* d, const uint32_t* a, const uint32_t* b) {
    asm volatile("mma.sync.aligned.m16n8k16.row.col.f32.f16.f16.f32 "
        "{%0,%1,%2,%3}, {%4,%5,%6,%7}, {%8,%9}, {%0,%1,%2,%3};"
        : "+f"(d[0]), "+f"(d[1]), "+f"(d[2]), "+f"(d[3])
        : "r"(a[0]), "r"(a[1]), "r"(a[2]), "r"(a[3]), "r"(b[0]), "r"(b[1]));
}

// ======================= device globals (scratch) =======================
#define XSZ (Bb * Nn * Dd)
#define ASZ (Bb * Nn * Nn)
__device__ __align__(128) __half g_xh[XSZ];
__device__ __align__(128) __half g_th[XSZ];              // lin0 output
__device__ __align__(128) __half g_qh[XSZ];              // q, then t1
__device__ __align__(128) __half g_ah[ASZ], g_al[ASZ];   // attn hi/lo (UNNORMALIZED)
__device__ __align__(128) __half g_wh[13 * Dd * Dd];
__device__ __align__(128) float g_x[XSZ];
__device__ __align__(128) float g_part[Bb * Nn * 4];     // row-sum partials (4 ctaY)

// ======================= MMA GEMM =======================
// BT=0: C = A[M,K] @ (Bh[Ncols,K])^T ; BT=1: C = A[M,K] @ (Bh[K,Ncols]) (trans-ldsm)
// PROD=2: A = Ah + Al (2 MMA products) ; PROD=1: A = Ah (single product)
// EPI: 1=bias->h | 2=sigmoid*adj->hl + rowsum partials | 4=relu(bias)->h
//      5=relu(bias)+res->fp32+h | 6=bias->fp32 | 7=rowscale(1/sum part)->h
#define TM 128
#define TN 128
#define RS 80
#define RSB 272
#define MAT_BYTES (128 * RS)            // 10240
#define NSTG 3

template<int EPI, int BT, int PROD>
__global__ void __launch_bounds__(256, 2)
mma_gemm(const __half* __restrict__ Ah, const __half* __restrict__ Al,
         const __half* __restrict__ Bh,
         int K, int ldb, long long sAz, long long sBz,
         float* __restrict__ Cf, __half* __restrict__ Ch, __half* __restrict__ Cl,
         long long sCz, int ldc,
         const float* __restrict__ bias, const float* __restrict__ res,
         const float* __restrict__ adj, float* __restrict__ part)
{
    constexpr int STG = (PROD + 1) * MAT_BYTES;    // Ah [,Al], B
    constexpr uint32_t B_OFF = PROD * MAT_BYTES;
    constexpr bool WRITE_L = (EPI == 2);

    extern __shared__ char smch[];
    const uint32_t sb = smem_u32(smch);
    const int tid = threadIdx.x;
    const int wid = tid >> 5;
    const int lane = tid & 31;
    const int z = blockIdx.z;
    const int bm = blockIdx.x * TM;
    const int bn = blockIdx.y * TN;

    Ah += (size_t)z * sAz + (size_t)bm * K;
    if (PROD == 2) Al += (size_t)z * sAz + (size_t)bm * K;
    if (BT) Bh += (size_t)z * sBz + bn;
    else    Bh += (size_t)z * sBz + (size_t)bn * K;

    const int lr = tid >> 1;
    const int lc = (tid & 1) * 2;
    const uint32_t s_off = (uint32_t)lr * RS + (uint32_t)lc * 16;
    const int lrB = tid >> 3;
    const int lsB = tid & 7;

    auto issue = [&](int kb, int buf) {
        const size_t go = (size_t)lr * K + (size_t)kb * 32 + (size_t)lc * 8;
        const uint32_t s0 = sb + buf * STG + s_off;
        cp16(s0,      Ah + go);
        cp16(s0 + 16, Ah + go + 8);
        if (PROD == 2) {
            cp16(s0 + MAT_BYTES,      Al + go);
            cp16(s0 + MAT_BYTES + 16, Al + go + 8);
        }
        if (BT) {
            const size_t gob = (size_t)(kb * 32 + lrB) * ldb + (size_t)lsB * 16;
            const uint32_t s0b = sb + buf * STG + B_OFF
                               + (uint32_t)lrB * RSB + (uint32_t)lsB * 32;
            cp16(s0b,      Bh + gob);
            cp16(s0b + 16, Bh + gob + 8);
        } else {
            const uint32_t s0b = sb + buf * STG + B_OFF + s_off;
            cp16(s0b,      Bh + go);
            cp16(s0b + 16, Bh + go + 8);
        }
    };

    const int KB = K / 32;
    issue(0, 0);
    asm volatile("cp.async.commit_group;" ::: "memory");
    issue(1, 1);
    asm volatile("cp.async.commit_group;" ::: "memory");

    const int wm = (wid & 1) * 64;
    const int wn = (wid >> 1) * 32;

    float acc[4][4][4];
    #pragma unroll
    for (int i = 0; i < 4; i++)
        #pragma unroll
        for (int j = 0; j < 4; j++)
            #pragma unroll
            for (int k = 0; k < 4; k++) acc[i][j][k] = 0.0f;

    const int rr = lane & 15;
    const int csel = lane >> 4;
    const int gB = lane >> 3;
    const int rB = lane & 7;

    int bufC = 0, bufW = 2;
    for (int kb = 0; kb < KB; kb++) {
        asm volatile("cp.async.wait_group 1;" ::: "memory");
        __syncthreads();
        const uint32_t bufb = sb + bufC * STG;

        if (kb + 2 < KB) issue(kb + 2, bufW);
        asm volatile("cp.async.commit_group;" ::: "memory");

        #pragma unroll
        for (int ks = 0; ks < 2; ks++) {
            const uint32_t coff = (uint32_t)(ks * 2 + csel) * 16;
            uint32_t ah[4][4], al[4][4], bh[4][2];
            const uint32_t abase = bufb + (uint32_t)(wm + rr) * RS + coff;
            #pragma unroll
            for (int mt = 0; mt < 4; mt++) {
                ldsm4(ah[mt], abase + mt * (16 * RS));
                if (PROD == 2) ldsm4(al[mt], abase + mt * (16 * RS) + MAT_BYTES);
            }
            if (BT) {
                const uint32_t btb = bufb + B_OFF
                    + (uint32_t)(ks * 16 + (gB & 1) * 8 + rB) * RSB
                    + (uint32_t)(wn + (gB >> 1) * 8) * 2;
                #pragma unroll
                for (int ntt = 0; ntt < 2; ntt++) {
                    uint32_t t4[4];
                    ldsm4t(t4, btb + ntt * 32);
                    bh[2 * ntt][0] = t4[0]; bh[2 * ntt][1] = t4[1];
                    bh[2 * ntt + 1][0] = t4[2]; bh[2 * ntt + 1][1] = t4[3];
                }
            } else {
                const uint32_t bbase = bufb + B_OFF + (uint32_t)(wn + rr) * RS + coff;
                #pragma unroll
                for (int ntt = 0; ntt < 2; ntt++) {
                    uint32_t t4[4];
                    ldsm4(t4, bbase + ntt * (16 * RS));
                    bh[2 * ntt][0] = t4[0]; bh[2 * ntt][1] = t4[2];
                    bh[2 * ntt + 1][0] = t4[1]; bh[2 * ntt + 1][1] = t4[3];
                }
            }
            #pragma unroll
            for (int mt = 0; mt < 4; mt++)
                #pragma unroll
                for (int nt = 0; nt < 4; nt++) {
                    mma16816(acc[mt][nt], ah[mt], bh[nt]);
                    if (PROD == 2) mma16816(acc[mt][nt], al[mt], bh[nt]);
                }
        }
        bufC = (bufC == NSTG - 1) ? 0 : bufC + 1;
        bufW = (bufW == NSTG - 1) ? 0 : bufW + 1;
    }

    // ======================= epilogue =======================
    const int qrow = lane >> 2;
    const int qcol = (lane & 3) * 2;
    float* redsm = (float*)smch;

    float rsum0[4], rsum1[4];

    #pragma unroll
    for (int mt = 0; mt < 4; mt++) {
        const int r0 = bm + wm + mt * 16 + qrow;
        const int r1 = r0 + 8;
        if (EPI == 2) { rsum0[mt] = 0.0f; rsum1[mt] = 0.0f; }
        #pragma unroll
        for (int nt = 0; nt < 4; nt++) {
            const int col = bn + wn + nt * 8 + qcol;
            float v00 = acc[mt][nt][0], v01 = acc[mt][nt][1];
            float v10 = acc[mt][nt][2], v11 = acc[mt][nt][3];

            if (EPI == 2) {
                const float* a0 = adj + ((size_t)z * Nn + r0) * Nn;
                const float* a1 = adj + ((size_t)z * Nn + r1) * Nn;
                float s00 = 1.0f / (1.0f + __expf(-v00));
                float s01 = 1.0f / (1.0f + __expf(-v01));
                float s10 = 1.0f / (1.0f + __expf(-v10));
                float s11 = 1.0f / (1.0f + __expf(-v11));
                v00 = (col == r0)     ? (s00 + 1e-5f) : s00 * __ldg(a0 + col);
                v01 = (col + 1 == r0) ? (s01 + 1e-5f) : s01 * __ldg(a0 + col + 1);
                v10 = (col == r1)     ? (s10 + 1e-5f) : s10 * __ldg(a1 + col);
                v11 = (col + 1 == r1) ? (s11 + 1e-5f) : s11 * __ldg(a1 + col + 1);
                rsum0[mt] += v00 + v01;
                rsum1[mt] += v10 + v11;
            } else if (EPI == 7) {
                const float4 p0 = *(const float4*)(part + ((size_t)z * Nn + r0) * 4);
                const float4 p1 = *(const float4*)(part + ((size_t)z * Nn + r1) * 4);
                const float inv0 = 1.0f / (p0.x + p0.y + p0.z + p0.w);
                const float inv1 = 1.0f / (p1.x + p1.y + p1.z + p1.w);
                v00 *= inv0; v01 *= inv0; v10 *= inv1; v11 *= inv1;
            } else if (EPI == 1) {
                const float b0v = __ldg(bias + col), b1v = __ldg(bias + col + 1);
                v00 += b0v; v01 += b1v; v10 += b0v; v11 += b1v;
            } else if (EPI == 4 || EPI == 5) {
                const float b0v = __ldg(bias + col), b1v = __ldg(bias + col + 1);
                v00 = fmaxf(v00 + b0v, 0.0f); v01 = fmaxf(v01 + b1v, 0.0f);
                v10 = fmaxf(v10 + b0v, 0.0f); v11 = fmaxf(v11 + b1v, 0.0f);
            }

            if (EPI == 6) {
                const float b0v = __ldg(bias + col), b1v = __ldg(bias + col + 1);
                float* cf0 = Cf + (size_t)z * sCz + (size_t)r0 * ldc;
                float* cf1 = Cf + (size_t)z * sCz + (size_t)r1 * ldc;
                float2 p0; p0.x = v00 + b0v; p0.y = v01 + b1v;
                float2 p1; p1.x = v10 + b0v; p1.y = v11 + b1v;
                *(float2*)(cf0 + col) = p0;
                *(float2*)(cf1 + col) = p1;
            } else {
                if (EPI == 5) {
                    const float* rp0 = res + (size_t)r0 * ldc;
                    const float* rp1 = res + (size_t)r1 * ldc;
                    v00 += rp0[col]; v01 += rp0[col + 1];
                    v10 += rp1[col]; v11 += rp1[col + 1];
                    float* cf0 = Cf + (size_t)r0 * ldc;
                    float* cf1 = Cf + (size_t)r1 * ldc;
                    float2 p0; p0.x = v00; p0.y = v01;
                    float2 p1; p1.x = v10; p1.y = v11;
                    *(float2*)(cf0 + col) = p0;
                    *(float2*)(cf1 + col) = p1;
                }
                __half* ch0 = Ch + (size_t)z * sCz + (size_t)r0 * ldc;
                __half* ch1 = Ch + (size_t)z * sCz + (size_t)r1 * ldc;
                const __half h00 = __float2half_rn(v00), h01 = __float2half_rn(v01);
                const __half h10 = __float2half_rn(v10), h11 = __float2half_rn(v11);
                __half2 hp0; hp0.x = h00; hp0.y = h01;
                __half2 hp1; hp1.x = h10; hp1.y = h11;
                *(__half2*)(ch0 + col) = hp0;
                *(__half2*)(ch1 + col) = hp1;
                if (WRITE_L) {
                    __half* cl0 = Cl + (size_t)z * sCz + (size_t)r0 * ldc;
                    __half* cl1 = Cl + (size_t)z * sCz + (size_t)r1 * ldc;
                    __half2 lp0, lp1;
                    lp0.x = __float2half_rn(v00 - __half2float(h00));
                    lp0.y = __float2half_rn(v01 - __half2float(h01));
                    lp1.x = __float2half_rn(v10 - __half2float(h10));
                    lp1.y = __float2half_rn(v11 - __half2float(h11));
                    *(__half2*)(cl0 + col) = lp0;
                    *(__half2*)(cl1 + col) = lp1;
                }
            }
        }
    }

    if (EPI == 2) {
        __syncthreads();
        const int nw = wid >> 1;
        #pragma unroll
        for (int mt = 0; mt < 4; mt++) {
            float s0 = rsum0[mt], s1 = rsum1[mt];
            s0 += __shfl_xor_sync(0xffffffffu, s0, 1);
            s0 += __shfl_xor_sync(0xffffffffu, s0, 2);
            s1 += __shfl_xor_sync(0xffffffffu, s1, 1);
            s1 += __shfl_xor_sync(0xffffffffu, s1, 2);
            if ((lane & 3) == 0) {
                const int rc = wm + mt * 16 + qrow;
                redsm[rc * 4 + nw]       = s0;
                redsm[(rc + 8) * 4 + nw] = s1;
            }
        }
        __syncthreads();
        if (tid < 128) {
            const float s = redsm[tid * 4] + redsm[tid * 4 + 1]
                          + redsm[tid * 4 + 2] + redsm[tid * 4 + 3];
            part[((size_t)z * Nn + bm + tid) * 4 + blockIdx.y] = s;
        }
    }
}

// ======================= small kernels =======================
__global__ void __launch_bounds__(256)
split_copy(const float4* __restrict__ src, float4* __restrict__ dst,
           __half* __restrict__ h, int n4)
{
    const int i = blockIdx.x * blockDim.x + threadIdx.x;
    if (i >= n4) return;
    const float4 v = src[i];
    dst[i] = v;
    __half2 a, b;
    a.x = __float2half_rn(v.x); a.y = __float2half_rn(v.y);
    b.x = __float2half_rn(v.z); b.y = __float2half_rn(v.w);
    *(__half2*)(h + 4 * (size_t)i) = a;
    *(__half2*)(h + 4 * (size_t)i + 2) = b;
}

__global__ void __launch_bounds__(256)
wconv(const float* __restrict__ src, __half* __restrict__ h, int n)
{
    const int i = blockIdx.x * blockDim.x + threadIdx.x;
    if (i < n) h[i] = __float2half_rn(src[i]);
}

// write normalized fp32 attn from unnormalized hi/lo + rowsum partials
__global__ void __launch_bounds__(256)
normout(const __half* __restrict__ h, const __half* __restrict__ l,
        const float* __restrict__ part, float* __restrict__ out)
{
    const size_t row = blockIdx.x;
    const float4 p = *(const float4*)(part + row * 4);
    const float inv = 1.0f / (p.x + p.y + p.z + p.w);
    const int t = threadIdx.x;
    const __half2 hv = *(const __half2*)(h + row * Nn + t * 2);
    const __half2 lv = *(const __half2*)(l + row * Nn + t * 2);
    float2 o;
    o.x = (__half2float(hv.x) + __half2float(lv.x)) * inv;
    o.y = (__half2float(hv.y) + __half2float(lv.y)) * inv;
    *(float2*)(out + row * Nn + t * 2) = o;
}

// ======================= launch =======================
#define SMEM_P2 (NSTG * 3 * MAT_BYTES)   // 92160
#define SMEM_P1 (NSTG * 2 * MAT_BYTES)   // 61440

extern "C" void kernel_launch(void* const* d_in, const int* in_sizes, int n_in,
                              void* d_out, int out_size)
{
    const float* x_in  = (const float*)d_in[0];
    const float* adj   = (const float*)d_in[1];
    const float* wA_w  = (const float*)d_in[2];
    const float* wA_b  = (const float*)d_in[3];
    const float* l0_w  = (const float*)d_in[4];
    const float* l0_b  = (const float*)d_in[5];
    const float* l1_w  = (const float*)d_in[6];
    const float* l1_b  = (const float*)d_in[7];
    const float* fin_w = (const float*)d_in[8];
    const float* fin_b = (const float*)d_in[9];

    float* out_x = (float*)d_out;
    float* attls = out_x + (size_t)Bb * Nn * Dd;

    __half *xh, *th, *qh, *ah, *al, *wh;
    float *gx, *gp;
    cudaGetSymbolAddress((void**)&xh, g_xh);
    cudaGetSymbolAddress((void**)&th, g_th);
    cudaGetSymbolAddress((void**)&qh, g_qh);
    cudaGetSymbolAddress((void**)&ah, g_ah); cudaGetSymbolAddress((void**)&al, g_al);
    cudaGetSymbolAddress((void**)&wh, g_wh);
    cudaGetSymbolAddress((void**)&gx, g_x);  cudaGetSymbolAddress((void**)&gp, g_part);

    static cudaStream_t s2 = nullptr;
    static cudaEvent_t evRoot, evW, evF[Ll], evJ[Ll];
    if (s2 == nullptr) {
        cudaStreamCreateWithFlags(&s2, cudaStreamNonBlocking);
        cudaEventCreateWithFlags(&evRoot, cudaEventDisableTiming);
        cudaEventCreateWithFlags(&evW, cudaEventDisableTiming);
        for (int l = 0; l < Ll; l++) {
            cudaEventCreateWithFlags(&evF[l], cudaEventDisableTiming);
            cudaEventCreateWithFlags(&evJ[l], cudaEventDisableTiming);
        }
    }

    cudaFuncSetAttribute(mma_gemm<1,0,1>, cudaFuncAttributeMaxDynamicSharedMemorySize, SMEM_P1);
    cudaFuncSetAttribute(mma_gemm<2,0,1>, cudaFuncAttributeMaxDynamicSharedMemorySize, SMEM_P1);
    cudaFuncSetAttribute(mma_gemm<4,0,1>, cudaFuncAttributeMaxDynamicSharedMemorySize, SMEM_P1);
    cudaFuncSetAttribute(mma_gemm<5,0,1>, cudaFuncAttributeMaxDynamicSharedMemorySize, SMEM_P1);
    cudaFuncSetAttribute(mma_gemm<6,0,1>, cudaFuncAttributeMaxDynamicSharedMemorySize, SMEM_P1);
    cudaFuncSetAttribute(mma_gemm<7,1,1>, cudaFuncAttributeMaxDynamicSharedMemorySize, SMEM_P1);

    const int WSZ = Dd * Dd;
    const long long sX = (long long)Nn * Dd;
    const long long sA = (long long)Nn * Nn;

    // fork s2 at root: weight converts run concurrently with x split_copy
    cudaEventRecord(evRoot, 0);
    cudaStreamWaitEvent(s2, evRoot, 0);
    wconv<<<(4 * WSZ + 255) / 256, 256, 0, s2>>>(wA_w,  wh,            4 * WSZ);
    wconv<<<(4 * WSZ + 255) / 256, 256, 0, s2>>>(l0_w,  wh + 4 * WSZ,  4 * WSZ);
    wconv<<<(4 * WSZ + 255) / 256, 256, 0, s2>>>(l1_w,  wh + 8 * WSZ,  4 * WSZ);
    wconv<<<(WSZ + 255) / 256, 256, 0, s2>>>(fin_w, wh + 12 * WSZ, WSZ);
    cudaEventRecord(evW, s2);

    {
        const int n4 = XSZ / 4;
        split_copy<<<(n4 + 255) / 256, 256>>>((const float4*)x_in, (float4*)gx, xh, n4);
    }
    cudaStreamWaitEvent(0, evW, 0);

    const int BIGM = Bb * Nn;
    for (int l = 0; l < Ll; l++) {
        const float* ba = wA_b + (size_t)l * Dd;
        const float* b0 = l0_b + (size_t)l * Dd;
        const float* b1 = l1_b + (size_t)l * Dd;
        const __half* Wah = wh + (size_t)l * WSZ;
        const __half* W0h = wh + (size_t)(4 + l) * WSZ;
        const __half* W1h = wh + (size_t)(8 + l) * WSZ;
        float* attl = attls + (size_t)l * Bb * Nn * Nn;

        // q = x @ Wa^T + ba  (A = xh single)  ->  qh (hi only)
        mma_gemm<1,0,1><<<dim3(BIGM / TM, Dd / TN, 1), 256, SMEM_P1>>>(
            xh, nullptr, Wah, Dd, 0, 0, 0,
            nullptr, qh, nullptr, 0, Dd, ba, nullptr, nullptr, nullptr);

        if (l > 0) cudaStreamWaitEvent(0, evJ[l - 1], 0);

        // attn_unnorm = sig(q @ x^T)*adj (+diag)  (A = qh single) -> ah/al + partials
        mma_gemm<2,0,1><<<dim3(Nn / TM, Nn / TN, Bb), 256, SMEM_P1>>>(
            qh, nullptr, xh, Dd, 0, sX, sX,
            nullptr, ah, al, sA, Nn, nullptr, nullptr, adj, gp);

        cudaEventRecord(evF[l], 0);
        cudaStreamWaitEvent(s2, evF[l], 0);
        normout<<<Bb * Nn, 256, 0, s2>>>(ah, al, gp, attl);
        cudaEventRecord(evJ[l], s2);

        // t1 = rowscale(attn_unnorm @ x)  (A = attn hi, B trans) -> qh
        mma_gemm<7,1,1><<<dim3(Nn / TM, Dd / TN, Bb), 256, SMEM_P1>>>(
            ah, nullptr, xh, Nn, Dd, sA, sX,
            nullptr, qh, nullptr, sX, Dd, nullptr, nullptr, nullptr, gp);

        // h = relu(t1 @ W0^T + b0)  (A = t1 single) -> th
        mma_gemm<4,0,1><<<dim3(BIGM / TM, Dd / TN, 1), 256, SMEM_P1>>>(
            qh, nullptr, W0h, Dd, 0, 0, 0,
            nullptr, th, nullptr, 0, Dd, b0, nullptr, nullptr, nullptr);

        // x = relu(h @ W1^T + b1) + x0  (A = h single) -> g_x fp32 + xh
        mma_gemm<5,0,1><<<dim3(BIGM / TM, Dd / TN, 1), 256, SMEM_P1>>>(
            th, nullptr, W1h, Dd, 0, 0, 0,
            gx, xh, nullptr, 0, Dd, b1, gx, nullptr, nullptr);
    }

    cudaStreamWaitEvent(0, evJ[Ll - 1], 0);

    // out = x @ final^T + b  (A = xh single)
    mma_gemm<6,0,1><<<dim3(BIGM / TM, Dd / TN, 1), 256, SMEM_P1>>>(
        xh, nullptr, wh + 12 * WSZ, Dd, 0, 0, 0,
        out_x, nullptr, nullptr, 0, Dd, fin_b, nullptr, nullptr, nullptr);
}